// round 4
// baseline (speedup 1.0000x reference)
#include <cuda_runtime.h>
#include <math.h>
#include <stdint.h>

// ---------------- problem constants ----------------
constexpr int NN   = 50000;
constexpr int EE   = 800000;
constexpr int DIM  = 128;
constexpr int NH   = 8;
constexpr int HID  = 512;
constexpr int KEU  = 320;

// ---------------- scratch ----------------
__device__ float g_xin  [(size_t)NN*DIM];
__device__ float g_h    [(size_t)NN*DIM];
__device__ float g_qkvs [(size_t)NN*4*DIM];   // q[0:128) k[128:256) v[256:384) skip[384:512)
__device__ float g_eproj[(size_t)EE*DIM];
__device__ float g_alpha[(size_t)EE*NH];
__device__ float g_amax [(size_t)NN*NH];
__device__ float g_denom[(size_t)NN*NH];
__device__ float g_agg  [(size_t)NN*DIM];
__device__ float g_xattn[(size_t)NN*DIM];
__device__ float g_h2   [(size_t)NN*DIM];
__device__ float g_ffn1 [(size_t)NN*HID];
__device__ float g_xn   [(size_t)NN*DIM];
__device__ float g_W4   [(size_t)DIM*512];
__device__ float g_b4   [512];
__device__ int   g_deg  [NN];

// ---------------- helpers ----------------
__device__ __forceinline__ float warp_sum(float v) {
#pragma unroll
    for (int o = 16; o > 0; o >>= 1) v += __shfl_xor_sync(0xffffffffu, v, o);
    return v;
}
__device__ __forceinline__ void atomicMaxF(float* addr, float v) {
    if (v >= 0.0f) atomicMax((int*)addr, __float_as_int(v));
    else           atomicMin((unsigned int*)addr, __float_as_uint(v));
}

// packed f32x2 FMA: d = a*b + d (elementwise on 2 floats) — FFMA2, 2x fp32 rate
__device__ __forceinline__ void ffma2(uint64_t& d, uint64_t a, uint64_t b) {
    asm volatile("fma.rn.f32x2 %0, %1, %2, %0;" : "+l"(d) : "l"(a), "l"(b));
}
__device__ __forceinline__ void lds_2x64(uint64_t& x, uint64_t& y, uint32_t saddr) {
    asm volatile("ld.shared.v2.b64 {%0,%1}, [%2];" : "=l"(x), "=l"(y) : "r"(saddr));
}
__device__ __forceinline__ float lo32(uint64_t v) { return __uint_as_float((uint32_t)v); }
__device__ __forceinline__ float hi32(uint64_t v) { return __uint_as_float((uint32_t)(v >> 32)); }

// ---------------- init / degree ----------------
__global__ void k_init() {
    int i  = blockIdx.x * blockDim.x + threadIdx.x;
    int st = gridDim.x * blockDim.x;
    for (int j = i; j < NN*DIM; j += st) g_agg[j] = 0.0f;
    for (int j = i; j < NN*NH;  j += st) { g_denom[j] = 0.0f; g_amax[j] = -INFINITY; }
    for (int j = i; j < NN;     j += st) g_deg[j] = 0;
}
__global__ void k_deg(const int* __restrict__ src) {
    int i = blockIdx.x * blockDim.x + threadIdx.x;
    if (i < EE) atomicAdd(&g_deg[src[i]], 1);
}
__global__ void k_pack(const float* __restrict__ Wq, const float* __restrict__ Wk,
                       const float* __restrict__ Wv, const float* __restrict__ Ws,
                       const float* __restrict__ bq, const float* __restrict__ bk,
                       const float* __restrict__ bv, const float* __restrict__ bs) {
    int i = blockIdx.x * blockDim.x + threadIdx.x;
    if (i < DIM*DIM) {
        int r = i >> 7, c = i & 127;
        g_W4[(size_t)r*512 +       c] = Wq[i];
        g_W4[(size_t)r*512 + 128 + c] = Wk[i];
        g_W4[(size_t)r*512 + 256 + c] = Wv[i];
        g_W4[(size_t)r*512 + 384 + c] = Ws[i];
    }
    if (i < 128) {
        g_b4[i] = bq[i]; g_b4[128+i] = bk[i]; g_b4[256+i] = bv[i]; g_b4[384+i] = bs[i];
    }
}

// ---------------- fused LN kernels ----------------
__global__ void k_node_prep(const float* __restrict__ x, const float* __restrict__ demb,
                            const float* __restrict__ g, const float* __restrict__ b) {
    int row = blockIdx.x * 8 + (threadIdx.x >> 5);
    if (row >= NN) return;
    int lane = threadIdx.x & 31;
    int d = g_deg[row]; if (d > 255) d = 255;
    float4 xv = *(const float4*)(x + (size_t)row*DIM + lane*4);
    float4 dv = *(const float4*)(demb + (size_t)d*DIM + lane*4);
    float4 xi = make_float4(xv.x+dv.x, xv.y+dv.y, xv.z+dv.z, xv.w+dv.w);
    *(float4*)(g_xin + (size_t)row*DIM + lane*4) = xi;
    float m = warp_sum(xi.x+xi.y+xi.z+xi.w) * (1.0f/128.0f);
    float4 dd = make_float4(xi.x-m, xi.y-m, xi.z-m, xi.w-m);
    float var = warp_sum(dd.x*dd.x+dd.y*dd.y+dd.z*dd.z+dd.w*dd.w) * (1.0f/128.0f);
    float inv = rsqrtf(var + 1e-5f);
    float4 gv = *(const float4*)(g + lane*4);
    float4 bv = *(const float4*)(b + lane*4);
    *(float4*)(g_h + (size_t)row*DIM + lane*4) =
        make_float4(dd.x*inv*gv.x+bv.x, dd.y*inv*gv.y+bv.y, dd.z*inv*gv.z+bv.z, dd.w*inv*gv.w+bv.w);
}

__global__ void k_node_post(const float* __restrict__ g, const float* __restrict__ b) {
    int row = blockIdx.x * 8 + (threadIdx.x >> 5);
    if (row >= NN) return;
    int lane = threadIdx.x & 31;
    float4 xi = *(const float4*)(g_xin + (size_t)row*DIM + lane*4);
    float4 ag = *(const float4*)(g_agg + (size_t)row*DIM + lane*4);
    float4 sk = *(const float4*)(g_qkvs + (size_t)row*512 + 384 + lane*4);
    float4 xa = make_float4(xi.x+ag.x+sk.x, xi.y+ag.y+sk.y, xi.z+ag.z+sk.z, xi.w+ag.w+sk.w);
    *(float4*)(g_xattn + (size_t)row*DIM + lane*4) = xa;
    float m = warp_sum(xa.x+xa.y+xa.z+xa.w) * (1.0f/128.0f);
    float4 dd = make_float4(xa.x-m, xa.y-m, xa.z-m, xa.w-m);
    float var = warp_sum(dd.x*dd.x+dd.y*dd.y+dd.z*dd.z+dd.w*dd.w) * (1.0f/128.0f);
    float inv = rsqrtf(var + 1e-5f);
    float4 gv = *(const float4*)(g + lane*4);
    float4 bv = *(const float4*)(b + lane*4);
    *(float4*)(g_h2 + (size_t)row*DIM + lane*4) =
        make_float4(dd.x*inv*gv.x+bv.x, dd.y*inv*gv.y+bv.y, dd.z*inv*gv.z+bv.z, dd.w*inv*gv.w+bv.w);
}

__global__ void k_xn(const float* __restrict__ xnew,
                     const float* __restrict__ g, const float* __restrict__ b) {
    int row = blockIdx.x * 8 + (threadIdx.x >> 5);
    if (row >= NN) return;
    int lane = threadIdx.x & 31;
    float4 xv = *(const float4*)(xnew + (size_t)row*DIM + lane*4);
    float m = warp_sum(xv.x+xv.y+xv.z+xv.w) * (1.0f/128.0f);
    float4 dd = make_float4(xv.x-m, xv.y-m, xv.z-m, xv.w-m);
    float var = warp_sum(dd.x*dd.x+dd.y*dd.y+dd.z*dd.z+dd.w*dd.w) * (1.0f/128.0f);
    float inv = rsqrtf(var + 1e-5f);
    float4 gv = *(const float4*)(g + lane*4);
    float4 bv = *(const float4*)(b + lane*4);
    *(float4*)(g_xn + (size_t)row*DIM + lane*4) =
        make_float4(dd.x*inv*gv.x+bv.x, dd.y*inv*gv.y+bv.y, dd.z*inv*gv.z+bv.z, dd.w*inv*gv.w+bv.w);
}

// ---------------- 128x128-tile GEMM with FFMA2 inner loop ----------------
// A tile stored as duplicated float2 pairs (a,a); B read as natural (b0,b1) pairs.
// MODE 0: +bias. MODE 1: +bias, exact GELU. MODE 2: +bias +res.
template<int MODE>
__global__ void __launch_bounds__(256, 2)
k_gemm128(const float* __restrict__ A, int lda,
          const float* __restrict__ B, int ldb,
          const float* __restrict__ bias,
          float* __restrict__ Co, int ldc,
          const float* __restrict__ res, int ldr,
          int M, int K) {
    __shared__ float2 Ash2[16][132];
    __shared__ float  Bsh [16][132];
    const int m0 = blockIdx.y * 128, n0 = blockIdx.x * 128;
    const int tid = threadIdx.x;
    const int tx = tid & 15, ty = tid >> 4;
    const int lr = tid >> 1, lh = (tid & 1) * 8;     // A loader
    const int br = tid >> 4, bc = (tid & 15) * 8;    // B loader
    const uint32_t aAddr0 = (uint32_t)__cvta_generic_to_shared(&Ash2[0][0]) + ty*64;
    const uint32_t bAddr0 = (uint32_t)__cvta_generic_to_shared(&Bsh[0][0])  + tx*32;
    uint64_t acc2[8][4] = {};

    for (int k0 = 0; k0 < K; k0 += 16) {
        float4 a0, a1;
        if (m0 + lr < M) {
            const float* ap = A + (size_t)(m0 + lr)*lda + k0 + lh;
            a0 = *(const float4*)ap; a1 = *(const float4*)(ap + 4);
        } else { a0 = make_float4(0,0,0,0); a1 = a0; }
        Ash2[lh+0][lr] = make_float2(a0.x, a0.x);
        Ash2[lh+1][lr] = make_float2(a0.y, a0.y);
        Ash2[lh+2][lr] = make_float2(a0.z, a0.z);
        Ash2[lh+3][lr] = make_float2(a0.w, a0.w);
        Ash2[lh+4][lr] = make_float2(a1.x, a1.x);
        Ash2[lh+5][lr] = make_float2(a1.y, a1.y);
        Ash2[lh+6][lr] = make_float2(a1.z, a1.z);
        Ash2[lh+7][lr] = make_float2(a1.w, a1.w);
        const float* bp = B + (size_t)(k0 + br)*ldb + n0 + bc;
        *(float4*)&Bsh[br][bc]   = *(const float4*)bp;
        *(float4*)&Bsh[br][bc+4] = *(const float4*)(bp + 4);
        __syncthreads();
#pragma unroll
        for (int kk = 0; kk < 16; kk++) {
            uint64_t a2[8], b2[4];
            uint32_t aA = aAddr0 + kk*(132*8);
            uint32_t bA = bAddr0 + kk*(132*4);
            lds_2x64(a2[0], a2[1], aA);
            lds_2x64(a2[2], a2[3], aA + 16);
            lds_2x64(a2[4], a2[5], aA + 32);
            lds_2x64(a2[6], a2[7], aA + 48);
            lds_2x64(b2[0], b2[1], bA);
            lds_2x64(b2[2], b2[3], bA + 16);
#pragma unroll
            for (int i = 0; i < 8; i++)
#pragma unroll
                for (int j = 0; j < 4; j++) ffma2(acc2[i][j], a2[i], b2[j]);
        }
        __syncthreads();
    }
#pragma unroll
    for (int i = 0; i < 8; i++) {
        int m = m0 + ty*8 + i;
        if (m >= M) continue;
#pragma unroll
        for (int jp = 0; jp < 4; jp += 2) {
            int n = n0 + tx*8 + jp*2;
            float4 bb = *(const float4*)(bias + n);
            float4 c = make_float4(lo32(acc2[i][jp])   + bb.x, hi32(acc2[i][jp])   + bb.y,
                                   lo32(acc2[i][jp+1]) + bb.z, hi32(acc2[i][jp+1]) + bb.w);
            if (MODE == 1) {
                c.x = 0.5f*c.x*(1.0f+erff(c.x*0.70710678118654752f));
                c.y = 0.5f*c.y*(1.0f+erff(c.y*0.70710678118654752f));
                c.z = 0.5f*c.z*(1.0f+erff(c.z*0.70710678118654752f));
                c.w = 0.5f*c.w*(1.0f+erff(c.w*0.70710678118654752f));
            }
            if (MODE == 2) {
                float4 rr = *(const float4*)(res + (size_t)m*ldr + n);
                c.x += rr.x; c.y += rr.y; c.z += rr.z; c.w += rr.w;
            }
            *(float4*)(Co + (size_t)m*ldc + n) = c;
        }
    }
}

// no-bias variant for eproj
__global__ void __launch_bounds__(256, 2)
k_gemm128_nb(const float* __restrict__ A, int lda,
             const float* __restrict__ B, int ldb,
             float* __restrict__ Co, int ldc, int M, int K) {
    __shared__ float2 Ash2[16][132];
    __shared__ float  Bsh [16][132];
    const int m0 = blockIdx.y * 128, n0 = blockIdx.x * 128;
    const int tid = threadIdx.x;
    const int tx = tid & 15, ty = tid >> 4;
    const int lr = tid >> 1, lh = (tid & 1) * 8;
    const int br = tid >> 4, bc = (tid & 15) * 8;
    const uint32_t aAddr0 = (uint32_t)__cvta_generic_to_shared(&Ash2[0][0]) + ty*64;
    const uint32_t bAddr0 = (uint32_t)__cvta_generic_to_shared(&Bsh[0][0])  + tx*32;
    uint64_t acc2[8][4] = {};
    for (int k0 = 0; k0 < K; k0 += 16) {
        const float* ap = A + (size_t)(m0 + lr)*lda + k0 + lh;
        float4 a0 = *(const float4*)ap, a1 = *(const float4*)(ap + 4);
        Ash2[lh+0][lr] = make_float2(a0.x, a0.x);
        Ash2[lh+1][lr] = make_float2(a0.y, a0.y);
        Ash2[lh+2][lr] = make_float2(a0.z, a0.z);
        Ash2[lh+3][lr] = make_float2(a0.w, a0.w);
        Ash2[lh+4][lr] = make_float2(a1.x, a1.x);
        Ash2[lh+5][lr] = make_float2(a1.y, a1.y);
        Ash2[lh+6][lr] = make_float2(a1.z, a1.z);
        Ash2[lh+7][lr] = make_float2(a1.w, a1.w);
        const float* bp = B + (size_t)(k0 + br)*ldb + n0 + bc;
        *(float4*)&Bsh[br][bc]   = *(const float4*)bp;
        *(float4*)&Bsh[br][bc+4] = *(const float4*)(bp + 4);
        __syncthreads();
#pragma unroll
        for (int kk = 0; kk < 16; kk++) {
            uint64_t a2[8], b2[4];
            uint32_t aA = aAddr0 + kk*(132*8);
            uint32_t bA = bAddr0 + kk*(132*4);
            lds_2x64(a2[0], a2[1], aA);
            lds_2x64(a2[2], a2[3], aA + 16);
            lds_2x64(a2[4], a2[5], aA + 32);
            lds_2x64(a2[6], a2[7], aA + 48);
            lds_2x64(b2[0], b2[1], bA);
            lds_2x64(b2[2], b2[3], bA + 16);
#pragma unroll
            for (int i = 0; i < 8; i++)
#pragma unroll
                for (int j = 0; j < 4; j++) ffma2(acc2[i][j], a2[i], b2[j]);
        }
        __syncthreads();
    }
#pragma unroll
    for (int i = 0; i < 8; i++) {
        int m = m0 + ty*8 + i;
#pragma unroll
        for (int jp = 0; jp < 4; jp += 2) {
            int n = n0 + tx*8 + jp*2;
            *(float4*)(Co + (size_t)m*ldc + n) =
                make_float4(lo32(acc2[i][jp]), hi32(acc2[i][jp]),
                            lo32(acc2[i][jp+1]), hi32(acc2[i][jp+1]));
        }
    }
}

// ---------------- attention ----------------
__global__ void k_alpha(const int* __restrict__ src, const int* __restrict__ dst) {
    int idx = blockIdx.x * blockDim.x + threadIdx.x;   // EE*NH
    int e = idx >> 3, hh = idx & 7;
    int s = src[e], d = dst[e];
    const float4* qp = (const float4*)(g_qkvs + (size_t)d*512 + hh*16);
    const float4* kp = (const float4*)(g_qkvs + (size_t)s*512 + 128 + hh*16);
    const float4* ep = (const float4*)(g_eproj + (size_t)e*128 + hh*16);
    float sum = 0.0f;
#pragma unroll
    for (int i = 0; i < 4; i++) {
        float4 q = qp[i], k = kp[i], ev = ep[i];
        sum += q.x*(k.x+ev.x) + q.y*(k.y+ev.y) + q.z*(k.z+ev.z) + q.w*(k.w+ev.w);
    }
    float a = sum * 0.25f;
    g_alpha[idx] = a;
    atomicMaxF(&g_amax[(size_t)d*NH + hh], a);
}

__global__ void k_pe(const int* __restrict__ dst) {
    int idx = blockIdx.x * blockDim.x + threadIdx.x;   // EE*NH
    int e = idx >> 3, hh = idx & 7;
    int d = dst[e];
    float p = expf(g_alpha[idx] - g_amax[(size_t)d*NH + hh]);
    g_alpha[idx] = p;
    atomicAdd(&g_denom[(size_t)d*NH + hh], p);
}

__global__ void k_agg(const int* __restrict__ src, const int* __restrict__ dst) {
    int idx = blockIdx.x * blockDim.x + threadIdx.x;   // EE*32
    int e = idx >> 5, t = idx & 31;
    int s = src[e], d = dst[e];
    int hh = t >> 2;
    float attn = g_alpha[(size_t)e*NH + hh] / g_denom[(size_t)d*NH + hh];
    float4 v = *(const float4*)(g_qkvs + (size_t)s*512 + 256 + t*4);
    float4 ev = *(const float4*)(g_eproj + (size_t)e*128 + t*4);
    float* o = g_agg + (size_t)d*128 + t*4;
    float m0 = attn*(v.x+ev.x), m1 = attn*(v.y+ev.y);
    float m2 = attn*(v.z+ev.z), m3 = attn*(v.w+ev.w);
    asm volatile("red.global.add.v4.f32 [%0], {%1,%2,%3,%4};"
                 :: "l"(o), "f"(m0), "f"(m1), "f"(m2), "f"(m3) : "memory");
}

// ---------------- edge update: gather-GEMM 128e x 320 @ 320 x 128, FFMA2, fused gate+LN ----------------
__global__ void __launch_bounds__(256, 2)
k_edge128(const int* __restrict__ src, const int* __restrict__ dst,
          const float* __restrict__ ea,
          const float* __restrict__ W, const float* __restrict__ bvec,
          const float* __restrict__ eg, const float* __restrict__ ebias,
          float* __restrict__ out) {
    extern __shared__ float sm[];
    float2 (*Ash2)[132] = (float2(*)[132])sm;              // 16 x 132 float2 (16896 B)
    float  (*Bsh)[132]  = (float(*)[132])(sm + 4224);      // 16 x 132 float  (8448 B)
    float  (*raw)[132]  = (float(*)[132])sm;               // 128 x 132 overlay after mainloop
    __shared__ int sidx[128], didx[128];

    const int tid = threadIdx.x;
    const int e0 = blockIdx.x * 128;
    if (tid < 128) { sidx[tid] = src[e0+tid]; didx[tid] = dst[e0+tid]; }
    __syncthreads();

    const int tx = tid & 15, ty = tid >> 4;
    const int lr = tid >> 1, lh = (tid & 1) * 8;
    const int br = tid >> 4, bc = (tid & 15) * 8;
    const uint32_t aAddr0 = (uint32_t)__cvta_generic_to_shared(&Ash2[0][0]) + ty*64;
    const uint32_t bAddr0 = (uint32_t)__cvta_generic_to_shared(&Bsh[0][0])  + tx*32;
    uint64_t acc2[8][4] = {};

    for (int k0 = 0; k0 < KEU; k0 += 16) {
        const float* base; int col;
        if (k0 < 128)      { base = g_xn + (size_t)sidx[lr]*128; col = k0 + lh; }
        else if (k0 < 256) { base = g_xn + (size_t)didx[lr]*128; col = k0 - 128 + lh; }
        else               { base = ea + (size_t)(e0+lr)*64;     col = k0 - 256 + lh; }
        float4 a0 = *(const float4*)(base + col);
        float4 a1 = *(const float4*)(base + col + 4);
        Ash2[lh+0][lr] = make_float2(a0.x, a0.x);
        Ash2[lh+1][lr] = make_float2(a0.y, a0.y);
        Ash2[lh+2][lr] = make_float2(a0.z, a0.z);
        Ash2[lh+3][lr] = make_float2(a0.w, a0.w);
        Ash2[lh+4][lr] = make_float2(a1.x, a1.x);
        Ash2[lh+5][lr] = make_float2(a1.y, a1.y);
        Ash2[lh+6][lr] = make_float2(a1.z, a1.z);
        Ash2[lh+7][lr] = make_float2(a1.w, a1.w);
        const float* bp = W + (size_t)(k0 + br)*128 + bc;
        *(float4*)&Bsh[br][bc]   = *(const float4*)bp;
        *(float4*)&Bsh[br][bc+4] = *(const float4*)(bp + 4);
        __syncthreads();
#pragma unroll
        for (int kk = 0; kk < 16; kk++) {
            uint64_t a2[8], b2[4];
            uint32_t aA = aAddr0 + kk*(132*8);
            uint32_t bA = bAddr0 + kk*(132*4);
            lds_2x64(a2[0], a2[1], aA);
            lds_2x64(a2[2], a2[3], aA + 16);
            lds_2x64(a2[4], a2[5], aA + 32);
            lds_2x64(a2[6], a2[7], aA + 48);
            lds_2x64(b2[0], b2[1], bA);
            lds_2x64(b2[2], b2[3], bA + 16);
#pragma unroll
            for (int i = 0; i < 8; i++)
#pragma unroll
                for (int j = 0; j < 4; j++) ffma2(acc2[i][j], a2[i], b2[j]);
        }
        __syncthreads();
    }

    // bias + relu -> raw smem (overlays dead A/B tiles)
#pragma unroll
    for (int i = 0; i < 8; i++) {
#pragma unroll
        for (int jp = 0; jp < 4; jp += 2) {
            int n = tx*8 + jp*2;
            float4 bb = *(const float4*)(bvec + n);
            *(float4*)&raw[ty*8+i][n] =
                make_float4(fmaxf(lo32(acc2[i][jp])  +bb.x, 0.0f),
                            fmaxf(hi32(acc2[i][jp])  +bb.y, 0.0f),
                            fmaxf(lo32(acc2[i][jp+1])+bb.z, 0.0f),
                            fmaxf(hi32(acc2[i][jp+1])+bb.w, 0.0f));
        }
    }
    __syncthreads();

    // t = edge_attr + sigmoid(gate)*delta; LN over 64.
#pragma unroll
    for (int half = 0; half < 2; half++) {
        int r = (tid >> 2) + half * 64;
        int q = tid & 3;
        float t[16]; float s = 0.0f;
#pragma unroll
        for (int i4 = 0; i4 < 16; i4 += 4) {
            int c = q*16 + i4;
            float4 e4 = *(const float4*)(ea + (size_t)(e0+r)*64 + c);
            t[i4+0] = e4.x + raw[r][c+0] / (1.0f + expf(-raw[r][64+c+0]));
            t[i4+1] = e4.y + raw[r][c+1] / (1.0f + expf(-raw[r][64+c+1]));
            t[i4+2] = e4.z + raw[r][c+2] / (1.0f + expf(-raw[r][64+c+2]));
            t[i4+3] = e4.w + raw[r][c+3] / (1.0f + expf(-raw[r][64+c+3]));
            s += t[i4+0] + t[i4+1] + t[i4+2] + t[i4+3];
        }
        s += __shfl_xor_sync(0xffffffffu, s, 1);
        s += __shfl_xor_sync(0xffffffffu, s, 2);
        float m = s * (1.0f/64.0f);
        float vs = 0.0f;
#pragma unroll
        for (int i = 0; i < 16; i++) { float dd = t[i] - m; vs += dd*dd; }
        vs += __shfl_xor_sync(0xffffffffu, vs, 1);
        vs += __shfl_xor_sync(0xffffffffu, vs, 2);
        float inv = rsqrtf(vs * (1.0f/64.0f) + 1e-5f);
#pragma unroll
        for (int i4 = 0; i4 < 16; i4 += 4) {
            int c = q*16 + i4;
            float4 gv = *(const float4*)(eg + c);
            float4 bb = *(const float4*)(ebias + c);
            *(float4*)(out + (size_t)(e0+r)*64 + c) =
                make_float4((t[i4+0]-m)*inv*gv.x+bb.x, (t[i4+1]-m)*inv*gv.y+bb.y,
                            (t[i4+2]-m)*inv*gv.z+bb.z, (t[i4+3]-m)*inv*gv.w+bb.w);
        }
    }
}

// ---------------- launcher ----------------
extern "C" void kernel_launch(void* const* d_in, const int* in_sizes, int n_in,
                              void* d_out, int out_size) {
    const float* x     = (const float*)d_in[0];
    const int*   ei    = (const int*)  d_in[1];
    const float* ea    = (const float*)d_in[2];
    const float* demb  = (const float*)d_in[3];
    const float* ng    = (const float*)d_in[4];
    const float* nbv   = (const float*)d_in[5];
    const float* Wq    = (const float*)d_in[6];
    const float* bq    = (const float*)d_in[7];
    const float* Wk    = (const float*)d_in[8];
    const float* bk    = (const float*)d_in[9];
    const float* Wv    = (const float*)d_in[10];
    const float* bv    = (const float*)d_in[11];
    const float* We    = (const float*)d_in[12];
    const float* Wskip = (const float*)d_in[13];
    const float* bskip = (const float*)d_in[14];
    const float* W1    = (const float*)d_in[15];
    const float* b1    = (const float*)d_in[16];
    const float* W2    = (const float*)d_in[17];
    const float* b2    = (const float*)d_in[18];
    const float* eung  = (const float*)d_in[19];
    const float* eunb  = (const float*)d_in[20];
    const float* euW   = (const float*)d_in[21];
    const float* eub   = (const float*)d_in[22];
    const float* eueg  = (const float*)d_in[23];
    const float* eueb  = (const float*)d_in[24];
    float* out = (float*)d_out;

    const int* src = ei;
    const int* dst = ei + EE;

    static float *p_h = nullptr, *p_qkvs = nullptr, *p_eproj = nullptr,
                 *p_h2 = nullptr, *p_ffn1 = nullptr, *p_xattn = nullptr,
                 *p_W4 = nullptr, *p_b4 = nullptr;
    static bool inited = false;
    if (!inited) {
        cudaGetSymbolAddress((void**)&p_h,     g_h);
        cudaGetSymbolAddress((void**)&p_qkvs,  g_qkvs);
        cudaGetSymbolAddress((void**)&p_eproj, g_eproj);
        cudaGetSymbolAddress((void**)&p_h2,    g_h2);
        cudaGetSymbolAddress((void**)&p_ffn1,  g_ffn1);
        cudaGetSymbolAddress((void**)&p_xattn, g_xattn);
        cudaGetSymbolAddress((void**)&p_W4,    g_W4);
        cudaGetSymbolAddress((void**)&p_b4,    g_b4);
        cudaFuncSetAttribute(k_edge128, cudaFuncAttributeMaxDynamicSharedMemorySize, 128*132*4);
        inited = true;
    }

    k_init<<<2048, 256>>>();
    k_deg<<<(EE + 255)/256, 256>>>(src);
    k_pack<<<64, 256>>>(Wq, Wk, Wv, Wskip, bq, bk, bv, bskip);
    k_node_prep<<<(NN + 7)/8, 256>>>(x, demb, ng, nbv);

    // fused QKV+skip: [50000x128] @ [128x512]
    k_gemm128<0><<<dim3(4, (NN+127)/128), 256>>>(p_h, 128, p_W4, 512, p_b4, p_qkvs, 512,
                                                 nullptr, 0, NN, 128);
    // edge proj: [800000x64] @ [64x128]
    k_gemm128_nb<<<dim3(1, EE/128), 256>>>(ea, 64, We, 128, p_eproj, 128, EE, 64);

    k_alpha<<<(EE*NH)/256, 256>>>(src, dst);
    k_pe   <<<(EE*NH)/256, 256>>>(dst);
    k_agg  <<<(EE*32)/256, 256>>>(src, dst);

    k_node_post<<<(NN + 7)/8, 256>>>(ng, nbv);

    // FFN
    k_gemm128<1><<<dim3(4, (NN+127)/128), 256>>>(p_h2, 128, W1, 512, b1, p_ffn1, 512,
                                                 nullptr, 0, NN, 128);
    k_gemm128<2><<<dim3(1, (NN+127)/128), 256>>>(p_ffn1, 512, W2, 128, b2, out, 128,
                                                 p_xattn, 128, NN, 512);

    k_xn<<<(NN + 7)/8, 256>>>(out, eung, eunb);
    k_edge128<<<EE/128, 256, 128*132*4>>>(src, dst, ea, euW, eub, eueg, eueb,
                                          out + (size_t)NN*DIM);
}

// round 5
// speedup vs baseline: 1.0013x; 1.0013x over previous
#include <cuda_runtime.h>
#include <math.h>
#include <stdint.h>

// ---------------- problem constants ----------------
constexpr int NN   = 50000;
constexpr int EE   = 800000;
constexpr int DIM  = 128;
constexpr int NH   = 8;
constexpr int HID  = 512;
constexpr int KEU  = 320;

// ---------------- scratch ----------------
__device__ float g_xin  [(size_t)NN*DIM];
__device__ float g_h    [(size_t)NN*DIM];
__device__ float g_qkvs [(size_t)NN*4*DIM];   // q[0:128) k[128:256) v[256:384) skip[384:512)
__device__ float g_eproj[(size_t)EE*DIM];
__device__ float g_alpha[(size_t)EE*NH];
__device__ float g_amax [(size_t)NN*NH];
__device__ float g_denom[(size_t)NN*NH];
__device__ float g_agg  [(size_t)NN*DIM];
__device__ float g_xattn[(size_t)NN*DIM];
__device__ float g_h2   [(size_t)NN*DIM];
__device__ float g_ffn1 [(size_t)NN*HID];
__device__ float g_xn   [(size_t)NN*DIM];
__device__ float g_W4   [(size_t)DIM*512];
__device__ float g_b4   [512];
__device__ int   g_deg  [NN];

// ---------------- helpers ----------------
__device__ __forceinline__ float warp_sum(float v) {
#pragma unroll
    for (int o = 16; o > 0; o >>= 1) v += __shfl_xor_sync(0xffffffffu, v, o);
    return v;
}
__device__ __forceinline__ void atomicMaxF(float* addr, float v) {
    if (v >= 0.0f) atomicMax((int*)addr, __float_as_int(v));
    else           atomicMin((unsigned int*)addr, __float_as_uint(v));
}

// packed f32x2 FMA: d = a*b + d (elementwise on 2 floats) — FFMA2, 2x fp32 rate
__device__ __forceinline__ void ffma2(uint64_t& d, uint64_t a, uint64_t b) {
    asm volatile("fma.rn.f32x2 %0, %1, %2, %0;" : "+l"(d) : "l"(a), "l"(b));
}
__device__ __forceinline__ void lds_2x64(uint64_t& x, uint64_t& y, uint32_t saddr) {
    asm volatile("ld.shared.v2.b64 {%0,%1}, [%2];" : "=l"(x), "=l"(y) : "r"(saddr));
}
__device__ __forceinline__ float lo32(uint64_t v) { return __uint_as_float((uint32_t)v); }
__device__ __forceinline__ float hi32(uint64_t v) { return __uint_as_float((uint32_t)(v >> 32)); }

// ---------------- init / degree ----------------
__global__ void k_init() {
    int i  = blockIdx.x * blockDim.x + threadIdx.x;
    int st = gridDim.x * blockDim.x;
    for (int j = i; j < NN*DIM; j += st) g_agg[j] = 0.0f;
    for (int j = i; j < NN*NH;  j += st) { g_denom[j] = 0.0f; g_amax[j] = -INFINITY; }
    for (int j = i; j < NN;     j += st) g_deg[j] = 0;
}
__global__ void k_deg(const int* __restrict__ src) {
    int i = blockIdx.x * blockDim.x + threadIdx.x;
    if (i < EE) atomicAdd(&g_deg[src[i]], 1);
}
__global__ void k_pack(const float* __restrict__ Wq, const float* __restrict__ Wk,
                       const float* __restrict__ Wv, const float* __restrict__ Ws,
                       const float* __restrict__ bq, const float* __restrict__ bk,
                       const float* __restrict__ bv, const float* __restrict__ bs) {
    int i = blockIdx.x * blockDim.x + threadIdx.x;
    if (i < DIM*DIM) {
        int r = i >> 7, c = i & 127;
        g_W4[(size_t)r*512 +       c] = Wq[i];
        g_W4[(size_t)r*512 + 128 + c] = Wk[i];
        g_W4[(size_t)r*512 + 256 + c] = Wv[i];
        g_W4[(size_t)r*512 + 384 + c] = Ws[i];
    }
    if (i < 128) {
        g_b4[i] = bq[i]; g_b4[128+i] = bk[i]; g_b4[256+i] = bv[i]; g_b4[384+i] = bs[i];
    }
}

// ---------------- fused LN kernels ----------------
__global__ void k_node_prep(const float* __restrict__ x, const float* __restrict__ demb,
                            const float* __restrict__ g, const float* __restrict__ b) {
    int row = blockIdx.x * 8 + (threadIdx.x >> 5);
    if (row >= NN) return;
    int lane = threadIdx.x & 31;
    int d = g_deg[row]; if (d > 255) d = 255;
    float4 xv = *(const float4*)(x + (size_t)row*DIM + lane*4);
    float4 dv = *(const float4*)(demb + (size_t)d*DIM + lane*4);
    float4 xi = make_float4(xv.x+dv.x, xv.y+dv.y, xv.z+dv.z, xv.w+dv.w);
    *(float4*)(g_xin + (size_t)row*DIM + lane*4) = xi;
    float m = warp_sum(xi.x+xi.y+xi.z+xi.w) * (1.0f/128.0f);
    float4 dd = make_float4(xi.x-m, xi.y-m, xi.z-m, xi.w-m);
    float var = warp_sum(dd.x*dd.x+dd.y*dd.y+dd.z*dd.z+dd.w*dd.w) * (1.0f/128.0f);
    float inv = rsqrtf(var + 1e-5f);
    float4 gv = *(const float4*)(g + lane*4);
    float4 bv = *(const float4*)(b + lane*4);
    *(float4*)(g_h + (size_t)row*DIM + lane*4) =
        make_float4(dd.x*inv*gv.x+bv.x, dd.y*inv*gv.y+bv.y, dd.z*inv*gv.z+bv.z, dd.w*inv*gv.w+bv.w);
}

__global__ void k_node_post(const float* __restrict__ g, const float* __restrict__ b) {
    int row = blockIdx.x * 8 + (threadIdx.x >> 5);
    if (row >= NN) return;
    int lane = threadIdx.x & 31;
    float4 xi = *(const float4*)(g_xin + (size_t)row*DIM + lane*4);
    float4 ag = *(const float4*)(g_agg + (size_t)row*DIM + lane*4);
    float4 sk = *(const float4*)(g_qkvs + (size_t)row*512 + 384 + lane*4);
    float4 xa = make_float4(xi.x+ag.x+sk.x, xi.y+ag.y+sk.y, xi.z+ag.z+sk.z, xi.w+ag.w+sk.w);
    *(float4*)(g_xattn + (size_t)row*DIM + lane*4) = xa;
    float m = warp_sum(xa.x+xa.y+xa.z+xa.w) * (1.0f/128.0f);
    float4 dd = make_float4(xa.x-m, xa.y-m, xa.z-m, xa.w-m);
    float var = warp_sum(dd.x*dd.x+dd.y*dd.y+dd.z*dd.z+dd.w*dd.w) * (1.0f/128.0f);
    float inv = rsqrtf(var + 1e-5f);
    float4 gv = *(const float4*)(g + lane*4);
    float4 bv = *(const float4*)(b + lane*4);
    *(float4*)(g_h2 + (size_t)row*DIM + lane*4) =
        make_float4(dd.x*inv*gv.x+bv.x, dd.y*inv*gv.y+bv.y, dd.z*inv*gv.z+bv.z, dd.w*inv*gv.w+bv.w);
}

__global__ void k_xn(const float* __restrict__ xnew,
                     const float* __restrict__ g, const float* __restrict__ b) {
    int row = blockIdx.x * 8 + (threadIdx.x >> 5);
    if (row >= NN) return;
    int lane = threadIdx.x & 31;
    float4 xv = *(const float4*)(xnew + (size_t)row*DIM + lane*4);
    float m = warp_sum(xv.x+xv.y+xv.z+xv.w) * (1.0f/128.0f);
    float4 dd = make_float4(xv.x-m, xv.y-m, xv.z-m, xv.w-m);
    float var = warp_sum(dd.x*dd.x+dd.y*dd.y+dd.z*dd.z+dd.w*dd.w) * (1.0f/128.0f);
    float inv = rsqrtf(var + 1e-5f);
    float4 gv = *(const float4*)(g + lane*4);
    float4 bv = *(const float4*)(b + lane*4);
    *(float4*)(g_xn + (size_t)row*DIM + lane*4) =
        make_float4(dd.x*inv*gv.x+bv.x, dd.y*inv*gv.y+bv.y, dd.z*inv*gv.z+bv.z, dd.w*inv*gv.w+bv.w);
}

// ---------------- 128x128-tile GEMM with FFMA2 inner loop ----------------
// A tile stored as duplicated float2 pairs (a,a); B read as natural (b0,b1) pairs.
// MODE 0: +bias. MODE 1: +bias, exact GELU. MODE 2: +bias +res.
template<int MODE>
__global__ void __launch_bounds__(256, 2)
k_gemm128(const float* __restrict__ A, int lda,
          const float* __restrict__ B, int ldb,
          const float* __restrict__ bias,
          float* __restrict__ Co, int ldc,
          const float* __restrict__ res, int ldr,
          int M, int K) {
    __shared__ float2 Ash2[16][132];
    __shared__ float  Bsh [16][132];
    const int m0 = blockIdx.y * 128, n0 = blockIdx.x * 128;
    const int tid = threadIdx.x;
    const int tx = tid & 15, ty = tid >> 4;
    const int lr = tid >> 1, lh = (tid & 1) * 8;     // A loader
    const int br = tid >> 4, bc = (tid & 15) * 8;    // B loader
    const uint32_t aAddr0 = (uint32_t)__cvta_generic_to_shared(&Ash2[0][0]) + ty*64;
    const uint32_t bAddr0 = (uint32_t)__cvta_generic_to_shared(&Bsh[0][0])  + tx*32;
    uint64_t acc2[8][4] = {};

    for (int k0 = 0; k0 < K; k0 += 16) {
        float4 a0, a1;
        if (m0 + lr < M) {
            const float* ap = A + (size_t)(m0 + lr)*lda + k0 + lh;
            a0 = *(const float4*)ap; a1 = *(const float4*)(ap + 4);
        } else { a0 = make_float4(0,0,0,0); a1 = a0; }
        Ash2[lh+0][lr] = make_float2(a0.x, a0.x);
        Ash2[lh+1][lr] = make_float2(a0.y, a0.y);
        Ash2[lh+2][lr] = make_float2(a0.z, a0.z);
        Ash2[lh+3][lr] = make_float2(a0.w, a0.w);
        Ash2[lh+4][lr] = make_float2(a1.x, a1.x);
        Ash2[lh+5][lr] = make_float2(a1.y, a1.y);
        Ash2[lh+6][lr] = make_float2(a1.z, a1.z);
        Ash2[lh+7][lr] = make_float2(a1.w, a1.w);
        const float* bp = B + (size_t)(k0 + br)*ldb + n0 + bc;
        *(float4*)&Bsh[br][bc]   = *(const float4*)bp;
        *(float4*)&Bsh[br][bc+4] = *(const float4*)(bp + 4);
        __syncthreads();
#pragma unroll
        for (int kk = 0; kk < 16; kk++) {
            uint64_t a2[8], b2[4];
            uint32_t aA = aAddr0 + kk*(132*8);
            uint32_t bA = bAddr0 + kk*(132*4);
            lds_2x64(a2[0], a2[1], aA);
            lds_2x64(a2[2], a2[3], aA + 16);
            lds_2x64(a2[4], a2[5], aA + 32);
            lds_2x64(a2[6], a2[7], aA + 48);
            lds_2x64(b2[0], b2[1], bA);
            lds_2x64(b2[2], b2[3], bA + 16);
#pragma unroll
            for (int i = 0; i < 8; i++)
#pragma unroll
                for (int j = 0; j < 4; j++) ffma2(acc2[i][j], a2[i], b2[j]);
        }
        __syncthreads();
    }
#pragma unroll
    for (int i = 0; i < 8; i++) {
        int m = m0 + ty*8 + i;
        if (m >= M) continue;
#pragma unroll
        for (int jp = 0; jp < 4; jp += 2) {
            int n = n0 + tx*8 + jp*2;
            float4 bb = *(const float4*)(bias + n);
            float4 c = make_float4(lo32(acc2[i][jp])   + bb.x, hi32(acc2[i][jp])   + bb.y,
                                   lo32(acc2[i][jp+1]) + bb.z, hi32(acc2[i][jp+1]) + bb.w);
            if (MODE == 1) {
                c.x = 0.5f*c.x*(1.0f+erff(c.x*0.70710678118654752f));
                c.y = 0.5f*c.y*(1.0f+erff(c.y*0.70710678118654752f));
                c.z = 0.5f*c.z*(1.0f+erff(c.z*0.70710678118654752f));
                c.w = 0.5f*c.w*(1.0f+erff(c.w*0.70710678118654752f));
            }
            if (MODE == 2) {
                float4 rr = *(const float4*)(res + (size_t)m*ldr + n);
                c.x += rr.x; c.y += rr.y; c.z += rr.z; c.w += rr.w;
            }
            *(float4*)(Co + (size_t)m*ldc + n) = c;
        }
    }
}

// no-bias variant for eproj
__global__ void __launch_bounds__(256, 2)
k_gemm128_nb(const float* __restrict__ A, int lda,
             const float* __restrict__ B, int ldb,
             float* __restrict__ Co, int ldc, int M, int K) {
    __shared__ float2 Ash2[16][132];
    __shared__ float  Bsh [16][132];
    const int m0 = blockIdx.y * 128, n0 = blockIdx.x * 128;
    const int tid = threadIdx.x;
    const int tx = tid & 15, ty = tid >> 4;
    const int lr = tid >> 1, lh = (tid & 1) * 8;
    const int br = tid >> 4, bc = (tid & 15) * 8;
    const uint32_t aAddr0 = (uint32_t)__cvta_generic_to_shared(&Ash2[0][0]) + ty*64;
    const uint32_t bAddr0 = (uint32_t)__cvta_generic_to_shared(&Bsh[0][0])  + tx*32;
    uint64_t acc2[8][4] = {};
    for (int k0 = 0; k0 < K; k0 += 16) {
        const float* ap = A + (size_t)(m0 + lr)*lda + k0 + lh;
        float4 a0 = *(const float4*)ap, a1 = *(const float4*)(ap + 4);
        Ash2[lh+0][lr] = make_float2(a0.x, a0.x);
        Ash2[lh+1][lr] = make_float2(a0.y, a0.y);
        Ash2[lh+2][lr] = make_float2(a0.z, a0.z);
        Ash2[lh+3][lr] = make_float2(a0.w, a0.w);
        Ash2[lh+4][lr] = make_float2(a1.x, a1.x);
        Ash2[lh+5][lr] = make_float2(a1.y, a1.y);
        Ash2[lh+6][lr] = make_float2(a1.z, a1.z);
        Ash2[lh+7][lr] = make_float2(a1.w, a1.w);
        const float* bp = B + (size_t)(k0 + br)*ldb + n0 + bc;
        *(float4*)&Bsh[br][bc]   = *(const float4*)bp;
        *(float4*)&Bsh[br][bc+4] = *(const float4*)(bp + 4);
        __syncthreads();
#pragma unroll
        for (int kk = 0; kk < 16; kk++) {
            uint64_t a2[8], b2[4];
            uint32_t aA = aAddr0 + kk*(132*8);
            uint32_t bA = bAddr0 + kk*(132*4);
            lds_2x64(a2[0], a2[1], aA);
            lds_2x64(a2[2], a2[3], aA + 16);
            lds_2x64(a2[4], a2[5], aA + 32);
            lds_2x64(a2[6], a2[7], aA + 48);
            lds_2x64(b2[0], b2[1], bA);
            lds_2x64(b2[2], b2[3], bA + 16);
#pragma unroll
            for (int i = 0; i < 8; i++)
#pragma unroll
                for (int j = 0; j < 4; j++) ffma2(acc2[i][j], a2[i], b2[j]);
        }
        __syncthreads();
    }
#pragma unroll
    for (int i = 0; i < 8; i++) {
        int m = m0 + ty*8 + i;
#pragma unroll
        for (int jp = 0; jp < 4; jp += 2) {
            int n = n0 + tx*8 + jp*2;
            *(float4*)(Co + (size_t)m*ldc + n) =
                make_float4(lo32(acc2[i][jp]), hi32(acc2[i][jp]),
                            lo32(acc2[i][jp+1]), hi32(acc2[i][jp+1]));
        }
    }
}

// ---------------- attention ----------------
__global__ void k_alpha(const int* __restrict__ src, const int* __restrict__ dst) {
    int idx = blockIdx.x * blockDim.x + threadIdx.x;   // EE*NH
    int e = idx >> 3, hh = idx & 7;
    int s = src[e], d = dst[e];
    const float4* qp = (const float4*)(g_qkvs + (size_t)d*512 + hh*16);
    const float4* kp = (const float4*)(g_qkvs + (size_t)s*512 + 128 + hh*16);
    const float4* ep = (const float4*)(g_eproj + (size_t)e*128 + hh*16);
    float sum = 0.0f;
#pragma unroll
    for (int i = 0; i < 4; i++) {
        float4 q = qp[i], k = kp[i], ev = ep[i];
        sum += q.x*(k.x+ev.x) + q.y*(k.y+ev.y) + q.z*(k.z+ev.z) + q.w*(k.w+ev.w);
    }
    float a = sum * 0.25f;
    g_alpha[idx] = a;
    atomicMaxF(&g_amax[(size_t)d*NH + hh], a);
}

__global__ void k_pe(const int* __restrict__ dst) {
    int idx = blockIdx.x * blockDim.x + threadIdx.x;   // EE*NH
    int e = idx >> 3, hh = idx & 7;
    int d = dst[e];
    float p = expf(g_alpha[idx] - g_amax[(size_t)d*NH + hh]);
    g_alpha[idx] = p;
    atomicAdd(&g_denom[(size_t)d*NH + hh], p);
}

__global__ void k_agg(const int* __restrict__ src, const int* __restrict__ dst) {
    int idx = blockIdx.x * blockDim.x + threadIdx.x;   // EE*32
    int e = idx >> 5, t = idx & 31;
    int s = src[e], d = dst[e];
    int hh = t >> 2;
    float attn = g_alpha[(size_t)e*NH + hh] / g_denom[(size_t)d*NH + hh];
    float4 v = *(const float4*)(g_qkvs + (size_t)s*512 + 256 + t*4);
    float4 ev = *(const float4*)(g_eproj + (size_t)e*128 + t*4);
    float* o = g_agg + (size_t)d*128 + t*4;
    float m0 = attn*(v.x+ev.x), m1 = attn*(v.y+ev.y);
    float m2 = attn*(v.z+ev.z), m3 = attn*(v.w+ev.w);
    asm volatile("red.global.add.v4.f32 [%0], {%1,%2,%3,%4};"
                 :: "l"(o), "f"(m0), "f"(m1), "f"(m2), "f"(m3) : "memory");
}

// ---------------- edge update: gather-GEMM 128e x 320 @ 320 x 128, FFMA2, fused gate+LN ----------------
__global__ void __launch_bounds__(256, 2)
k_edge128(const int* __restrict__ src, const int* __restrict__ dst,
          const float* __restrict__ ea,
          const float* __restrict__ W, const float* __restrict__ bvec,
          const float* __restrict__ eg, const float* __restrict__ ebias,
          float* __restrict__ out) {
    extern __shared__ float sm[];
    float2 (*Ash2)[132] = (float2(*)[132])sm;              // 16 x 132 float2 (16896 B)
    float  (*Bsh)[132]  = (float(*)[132])(sm + 4224);      // 16 x 132 float  (8448 B)
    float  (*raw)[132]  = (float(*)[132])sm;               // 128 x 132 overlay after mainloop
    __shared__ int sidx[128], didx[128];

    const int tid = threadIdx.x;
    const int e0 = blockIdx.x * 128;
    if (tid < 128) { sidx[tid] = src[e0+tid]; didx[tid] = dst[e0+tid]; }
    __syncthreads();

    const int tx = tid & 15, ty = tid >> 4;
    const int lr = tid >> 1, lh = (tid & 1) * 8;
    const int br = tid >> 4, bc = (tid & 15) * 8;
    const uint32_t aAddr0 = (uint32_t)__cvta_generic_to_shared(&Ash2[0][0]) + ty*64;
    const uint32_t bAddr0 = (uint32_t)__cvta_generic_to_shared(&Bsh[0][0])  + tx*32;
    uint64_t acc2[8][4] = {};

    for (int k0 = 0; k0 < KEU; k0 += 16) {
        const float* base; int col;
        if (k0 < 128)      { base = g_xn + (size_t)sidx[lr]*128; col = k0 + lh; }
        else if (k0 < 256) { base = g_xn + (size_t)didx[lr]*128; col = k0 - 128 + lh; }
        else               { base = ea + (size_t)(e0+lr)*64;     col = k0 - 256 + lh; }
        float4 a0 = *(const float4*)(base + col);
        float4 a1 = *(const float4*)(base + col + 4);
        Ash2[lh+0][lr] = make_float2(a0.x, a0.x);
        Ash2[lh+1][lr] = make_float2(a0.y, a0.y);
        Ash2[lh+2][lr] = make_float2(a0.z, a0.z);
        Ash2[lh+3][lr] = make_float2(a0.w, a0.w);
        Ash2[lh+4][lr] = make_float2(a1.x, a1.x);
        Ash2[lh+5][lr] = make_float2(a1.y, a1.y);
        Ash2[lh+6][lr] = make_float2(a1.z, a1.z);
        Ash2[lh+7][lr] = make_float2(a1.w, a1.w);
        const float* bp = W + (size_t)(k0 + br)*128 + bc;
        *(float4*)&Bsh[br][bc]   = *(const float4*)bp;
        *(float4*)&Bsh[br][bc+4] = *(const float4*)(bp + 4);
        __syncthreads();
#pragma unroll
        for (int kk = 0; kk < 16; kk++) {
            uint64_t a2[8], b2[4];
            uint32_t aA = aAddr0 + kk*(132*8);
            uint32_t bA = bAddr0 + kk*(132*4);
            lds_2x64(a2[0], a2[1], aA);
            lds_2x64(a2[2], a2[3], aA + 16);
            lds_2x64(a2[4], a2[5], aA + 32);
            lds_2x64(a2[6], a2[7], aA + 48);
            lds_2x64(b2[0], b2[1], bA);
            lds_2x64(b2[2], b2[3], bA + 16);
#pragma unroll
            for (int i = 0; i < 8; i++)
#pragma unroll
                for (int j = 0; j < 4; j++) ffma2(acc2[i][j], a2[i], b2[j]);
        }
        __syncthreads();
    }

    // bias + relu -> raw smem (overlays dead A/B tiles)
#pragma unroll
    for (int i = 0; i < 8; i++) {
#pragma unroll
        for (int jp = 0; jp < 4; jp += 2) {
            int n = tx*8 + jp*2;
            float4 bb = *(const float4*)(bvec + n);
            *(float4*)&raw[ty*8+i][n] =
                make_float4(fmaxf(lo32(acc2[i][jp])  +bb.x, 0.0f),
                            fmaxf(hi32(acc2[i][jp])  +bb.y, 0.0f),
                            fmaxf(lo32(acc2[i][jp+1])+bb.z, 0.0f),
                            fmaxf(hi32(acc2[i][jp+1])+bb.w, 0.0f));
        }
    }
    __syncthreads();

    // t = edge_attr + sigmoid(gate)*delta; LN over 64.
#pragma unroll
    for (int half = 0; half < 2; half++) {
        int r = (tid >> 2) + half * 64;
        int q = tid & 3;
        float t[16]; float s = 0.0f;
#pragma unroll
        for (int i4 = 0; i4 < 16; i4 += 4) {
            int c = q*16 + i4;
            float4 e4 = *(const float4*)(ea + (size_t)(e0+r)*64 + c);
            t[i4+0] = e4.x + raw[r][c+0] / (1.0f + expf(-raw[r][64+c+0]));
            t[i4+1] = e4.y + raw[r][c+1] / (1.0f + expf(-raw[r][64+c+1]));
            t[i4+2] = e4.z + raw[r][c+2] / (1.0f + expf(-raw[r][64+c+2]));
            t[i4+3] = e4.w + raw[r][c+3] / (1.0f + expf(-raw[r][64+c+3]));
            s += t[i4+0] + t[i4+1] + t[i4+2] + t[i4+3];
        }
        s += __shfl_xor_sync(0xffffffffu, s, 1);
        s += __shfl_xor_sync(0xffffffffu, s, 2);
        float m = s * (1.0f/64.0f);
        float vs = 0.0f;
#pragma unroll
        for (int i = 0; i < 16; i++) { float dd = t[i] - m; vs += dd*dd; }
        vs += __shfl_xor_sync(0xffffffffu, vs, 1);
        vs += __shfl_xor_sync(0xffffffffu, vs, 2);
        float inv = rsqrtf(vs * (1.0f/64.0f) + 1e-5f);
#pragma unroll
        for (int i4 = 0; i4 < 16; i4 += 4) {
            int c = q*16 + i4;
            float4 gv = *(const float4*)(eg + c);
            float4 bb = *(const float4*)(ebias + c);
            *(float4*)(out + (size_t)(e0+r)*64 + c) =
                make_float4((t[i4+0]-m)*inv*gv.x+bb.x, (t[i4+1]-m)*inv*gv.y+bb.y,
                            (t[i4+2]-m)*inv*gv.z+bb.z, (t[i4+3]-m)*inv*gv.w+bb.w);
        }
    }
}

// ---------------- launcher ----------------
extern "C" void kernel_launch(void* const* d_in, const int* in_sizes, int n_in,
                              void* d_out, int out_size) {
    const float* x     = (const float*)d_in[0];
    const int*   ei    = (const int*)  d_in[1];
    const float* ea    = (const float*)d_in[2];
    const float* demb  = (const float*)d_in[3];
    const float* ng    = (const float*)d_in[4];
    const float* nbv   = (const float*)d_in[5];
    const float* Wq    = (const float*)d_in[6];
    const float* bq    = (const float*)d_in[7];
    const float* Wk    = (const float*)d_in[8];
    const float* bk    = (const float*)d_in[9];
    const float* Wv    = (const float*)d_in[10];
    const float* bv    = (const float*)d_in[11];
    const float* We    = (const float*)d_in[12];
    const float* Wskip = (const float*)d_in[13];
    const float* bskip = (const float*)d_in[14];
    const float* W1    = (const float*)d_in[15];
    const float* b1    = (const float*)d_in[16];
    const float* W2    = (const float*)d_in[17];
    const float* b2    = (const float*)d_in[18];
    const float* eung  = (const float*)d_in[19];
    const float* eunb  = (const float*)d_in[20];
    const float* euW   = (const float*)d_in[21];
    const float* eub   = (const float*)d_in[22];
    const float* eueg  = (const float*)d_in[23];
    const float* eueb  = (const float*)d_in[24];
    float* out = (float*)d_out;

    const int* src = ei;
    const int* dst = ei + EE;

    static float *p_h = nullptr, *p_qkvs = nullptr, *p_eproj = nullptr,
                 *p_h2 = nullptr, *p_ffn1 = nullptr, *p_xattn = nullptr,
                 *p_W4 = nullptr, *p_b4 = nullptr;
    static bool inited = false;
    if (!inited) {
        cudaGetSymbolAddress((void**)&p_h,     g_h);
        cudaGetSymbolAddress((void**)&p_qkvs,  g_qkvs);
        cudaGetSymbolAddress((void**)&p_eproj, g_eproj);
        cudaGetSymbolAddress((void**)&p_h2,    g_h2);
        cudaGetSymbolAddress((void**)&p_ffn1,  g_ffn1);
        cudaGetSymbolAddress((void**)&p_xattn, g_xattn);
        cudaGetSymbolAddress((void**)&p_W4,    g_W4);
        cudaGetSymbolAddress((void**)&p_b4,    g_b4);
        cudaFuncSetAttribute(k_edge128, cudaFuncAttributeMaxDynamicSharedMemorySize, 128*132*4);
        inited = true;
    }

    k_init<<<2048, 256>>>();
    k_deg<<<(EE + 255)/256, 256>>>(src);
    k_pack<<<64, 256>>>(Wq, Wk, Wv, Wskip, bq, bk, bv, bskip);
    k_node_prep<<<(NN + 7)/8, 256>>>(x, demb, ng, nbv);

    // fused QKV+skip: [50000x128] @ [128x512]
    k_gemm128<0><<<dim3(4, (NN+127)/128), 256>>>(p_h, 128, p_W4, 512, p_b4, p_qkvs, 512,
                                                 nullptr, 0, NN, 128);
    // edge proj: [800000x64] @ [64x128]
    k_gemm128_nb<<<dim3(1, EE/128), 256>>>(ea, 64, We, 128, p_eproj, 128, EE, 64);

    k_alpha<<<(EE*NH)/256, 256>>>(src, dst);
    k_pe   <<<(EE*NH)/256, 256>>>(dst);
    k_agg  <<<(EE*32)/256, 256>>>(src, dst);

    k_node_post<<<(NN + 7)/8, 256>>>(ng, nbv);

    // FFN
    k_gemm128<1><<<dim3(4, (NN+127)/128), 256>>>(p_h2, 128, W1, 512, b1, p_ffn1, 512,
                                                 nullptr, 0, NN, 128);
    k_gemm128<2><<<dim3(1, (NN+127)/128), 256>>>(p_ffn1, 512, W2, 128, b2, out, 128,
                                                 p_xattn, 128, NN, 512);

    k_xn<<<(NN + 7)/8, 256>>>(out, eung, eunb);
    k_edge128<<<EE/128, 256, 128*132*4>>>(src, dst, ea, euW, eub, eueg, eueb,
                                          out + (size_t)NN*DIM);
}

// round 6
// speedup vs baseline: 1.5396x; 1.5377x over previous
#include <cuda_runtime.h>
#include <math.h>
#include <stdint.h>

// ---------------- problem constants ----------------
constexpr int NN   = 50000;
constexpr int EE   = 800000;
constexpr int DIM  = 128;
constexpr int NH   = 8;
constexpr int HID  = 512;
constexpr int KEU  = 320;

// ---------------- scratch ----------------
__device__ float g_xin  [(size_t)NN*DIM];
__device__ float g_h    [(size_t)NN*DIM];
__device__ float g_qkvs [(size_t)NN*4*DIM];   // q[0:128) k[128:256) v[256:384) skip[384:512)
__device__ float g_eproj[(size_t)EE*DIM];
__device__ float g_alpha[(size_t)EE*NH];
__device__ float g_amax [(size_t)NN*NH];
__device__ float g_denom[(size_t)NN*NH];
__device__ float g_agg  [(size_t)NN*DIM];
__device__ float g_xattn[(size_t)NN*DIM];
__device__ float g_h2   [(size_t)NN*DIM];
__device__ float g_ffn1 [(size_t)NN*HID];
__device__ float g_xn   [(size_t)NN*DIM];
__device__ float g_W4   [(size_t)DIM*512];
__device__ float g_b4   [512];
__device__ int   g_deg  [NN];

// ---------------- helpers ----------------
__device__ __forceinline__ float warp_sum(float v) {
#pragma unroll
    for (int o = 16; o > 0; o >>= 1) v += __shfl_xor_sync(0xffffffffu, v, o);
    return v;
}
__device__ __forceinline__ void atomicMaxF(float* addr, float v) {
    if (v >= 0.0f) atomicMax((int*)addr, __float_as_int(v));
    else           atomicMin((unsigned int*)addr, __float_as_uint(v));
}
__device__ __forceinline__ uint32_t f2tf32(float f) {
    uint32_t r;
    asm("cvt.rna.tf32.f32 %0, %1;" : "=r"(r) : "f"(f));
    return r;
}
__device__ __forceinline__ void mma_tf32(float* c,
                                         uint32_t a0, uint32_t a1, uint32_t a2, uint32_t a3,
                                         uint32_t b0, uint32_t b1) {
    asm volatile("mma.sync.aligned.m16n8k8.row.col.f32.tf32.tf32.f32 "
                 "{%0,%1,%2,%3}, {%4,%5,%6,%7}, {%8,%9}, {%0,%1,%2,%3};"
                 : "+f"(c[0]), "+f"(c[1]), "+f"(c[2]), "+f"(c[3])
                 : "r"(a0), "r"(a1), "r"(a2), "r"(a3), "r"(b0), "r"(b1));
}

// ---------------- init / degree ----------------
__global__ void k_init() {
    int i  = blockIdx.x * blockDim.x + threadIdx.x;
    int st = gridDim.x * blockDim.x;
    for (int j = i; j < NN*DIM; j += st) g_agg[j] = 0.0f;
    for (int j = i; j < NN*NH;  j += st) { g_denom[j] = 0.0f; g_amax[j] = -INFINITY; }
    for (int j = i; j < NN;     j += st) g_deg[j] = 0;
}
__global__ void k_deg(const int* __restrict__ src) {
    int i = blockIdx.x * blockDim.x + threadIdx.x;
    if (i < EE) atomicAdd(&g_deg[src[i]], 1);
}
__global__ void k_pack(const float* __restrict__ Wq, const float* __restrict__ Wk,
                       const float* __restrict__ Wv, const float* __restrict__ Ws,
                       const float* __restrict__ bq, const float* __restrict__ bk,
                       const float* __restrict__ bv, const float* __restrict__ bs) {
    int i = blockIdx.x * blockDim.x + threadIdx.x;
    if (i < DIM*DIM) {
        int r = i >> 7, c = i & 127;
        g_W4[(size_t)r*512 +       c] = Wq[i];
        g_W4[(size_t)r*512 + 128 + c] = Wk[i];
        g_W4[(size_t)r*512 + 256 + c] = Wv[i];
        g_W4[(size_t)r*512 + 384 + c] = Ws[i];
    }
    if (i < 128) {
        g_b4[i] = bq[i]; g_b4[128+i] = bk[i]; g_b4[256+i] = bv[i]; g_b4[384+i] = bs[i];
    }
}

// ---------------- fused LN kernels ----------------
__global__ void k_node_prep(const float* __restrict__ x, const float* __restrict__ demb,
                            const float* __restrict__ g, const float* __restrict__ b) {
    int row = blockIdx.x * 8 + (threadIdx.x >> 5);
    if (row >= NN) return;
    int lane = threadIdx.x & 31;
    int d = g_deg[row]; if (d > 255) d = 255;
    float4 xv = *(const float4*)(x + (size_t)row*DIM + lane*4);
    float4 dv = *(const float4*)(demb + (size_t)d*DIM + lane*4);
    float4 xi = make_float4(xv.x+dv.x, xv.y+dv.y, xv.z+dv.z, xv.w+dv.w);
    *(float4*)(g_xin + (size_t)row*DIM + lane*4) = xi;
    float m = warp_sum(xi.x+xi.y+xi.z+xi.w) * (1.0f/128.0f);
    float4 dd = make_float4(xi.x-m, xi.y-m, xi.z-m, xi.w-m);
    float var = warp_sum(dd.x*dd.x+dd.y*dd.y+dd.z*dd.z+dd.w*dd.w) * (1.0f/128.0f);
    float inv = rsqrtf(var + 1e-5f);
    float4 gv = *(const float4*)(g + lane*4);
    float4 bv = *(const float4*)(b + lane*4);
    *(float4*)(g_h + (size_t)row*DIM + lane*4) =
        make_float4(dd.x*inv*gv.x+bv.x, dd.y*inv*gv.y+bv.y, dd.z*inv*gv.z+bv.z, dd.w*inv*gv.w+bv.w);
}

__global__ void k_node_post(const float* __restrict__ g, const float* __restrict__ b) {
    int row = blockIdx.x * 8 + (threadIdx.x >> 5);
    if (row >= NN) return;
    int lane = threadIdx.x & 31;
    float4 xi = *(const float4*)(g_xin + (size_t)row*DIM + lane*4);
    float4 ag = *(const float4*)(g_agg + (size_t)row*DIM + lane*4);
    float4 sk = *(const float4*)(g_qkvs + (size_t)row*512 + 384 + lane*4);
    float4 xa = make_float4(xi.x+ag.x+sk.x, xi.y+ag.y+sk.y, xi.z+ag.z+sk.z, xi.w+ag.w+sk.w);
    *(float4*)(g_xattn + (size_t)row*DIM + lane*4) = xa;
    float m = warp_sum(xa.x+xa.y+xa.z+xa.w) * (1.0f/128.0f);
    float4 dd = make_float4(xa.x-m, xa.y-m, xa.z-m, xa.w-m);
    float var = warp_sum(dd.x*dd.x+dd.y*dd.y+dd.z*dd.z+dd.w*dd.w) * (1.0f/128.0f);
    float inv = rsqrtf(var + 1e-5f);
    float4 gv = *(const float4*)(g + lane*4);
    float4 bv = *(const float4*)(b + lane*4);
    *(float4*)(g_h2 + (size_t)row*DIM + lane*4) =
        make_float4(dd.x*inv*gv.x+bv.x, dd.y*inv*gv.y+bv.y, dd.z*inv*gv.z+bv.z, dd.w*inv*gv.w+bv.w);
}

__global__ void k_xn(const float* __restrict__ xnew,
                     const float* __restrict__ g, const float* __restrict__ b) {
    int row = blockIdx.x * 8 + (threadIdx.x >> 5);
    if (row >= NN) return;
    int lane = threadIdx.x & 31;
    float4 xv = *(const float4*)(xnew + (size_t)row*DIM + lane*4);
    float m = warp_sum(xv.x+xv.y+xv.z+xv.w) * (1.0f/128.0f);
    float4 dd = make_float4(xv.x-m, xv.y-m, xv.z-m, xv.w-m);
    float var = warp_sum(dd.x*dd.x+dd.y*dd.y+dd.z*dd.z+dd.w*dd.w) * (1.0f/128.0f);
    float inv = rsqrtf(var + 1e-5f);
    float4 gv = *(const float4*)(g + lane*4);
    float4 bv = *(const float4*)(b + lane*4);
    *(float4*)(g_xn + (size_t)row*DIM + lane*4) =
        make_float4(dd.x*inv*gv.x+bv.x, dd.y*inv*gv.y+bv.y, dd.z*inv*gv.z+bv.z, dd.w*inv*gv.w+bv.w);
}

// ---------------- 128x128-tile GEMM, 8x8 micro-tile (round-3 proven form) ----------------
// MODE 0: +bias. MODE 1: +bias, exact GELU. MODE 2: +bias +res.
template<int MODE>
__global__ void __launch_bounds__(256, 2)
k_gemm128(const float* __restrict__ A, int lda,
          const float* __restrict__ B, int ldb,
          const float* __restrict__ bias,
          float* __restrict__ Co, int ldc,
          const float* __restrict__ res, int ldr,
          int M, int K) {
    __shared__ float Ash[16][132];
    __shared__ float Bsh[16][132];
    const int m0 = blockIdx.y * 128, n0 = blockIdx.x * 128;
    const int tid = threadIdx.x;
    const int tx = tid & 15, ty = tid >> 4;
    const int lr = tid >> 1, lh = (tid & 1) * 8;     // A loader
    const int br = tid >> 4, bc = (tid & 15) * 8;    // B loader
    float acc[8][8] = {};

    for (int k0 = 0; k0 < K; k0 += 16) {
        float4 a0, a1;
        if (m0 + lr < M) {
            const float* ap = A + (size_t)(m0 + lr)*lda + k0 + lh;
            a0 = *(const float4*)ap; a1 = *(const float4*)(ap + 4);
        } else { a0 = make_float4(0,0,0,0); a1 = a0; }
        Ash[lh+0][lr] = a0.x; Ash[lh+1][lr] = a0.y; Ash[lh+2][lr] = a0.z; Ash[lh+3][lr] = a0.w;
        Ash[lh+4][lr] = a1.x; Ash[lh+5][lr] = a1.y; Ash[lh+6][lr] = a1.z; Ash[lh+7][lr] = a1.w;
        const float* bp = B + (size_t)(k0 + br)*ldb + n0 + bc;
        *(float4*)&Bsh[br][bc]   = *(const float4*)bp;
        *(float4*)&Bsh[br][bc+4] = *(const float4*)(bp + 4);
        __syncthreads();
#pragma unroll
        for (int kk = 0; kk < 16; kk++) {
            float a[8], b[8];
            *(float4*)&a[0] = *(const float4*)&Ash[kk][ty*8];
            *(float4*)&a[4] = *(const float4*)&Ash[kk][ty*8+4];
            *(float4*)&b[0] = *(const float4*)&Bsh[kk][tx*8];
            *(float4*)&b[4] = *(const float4*)&Bsh[kk][tx*8+4];
#pragma unroll
            for (int i = 0; i < 8; i++)
#pragma unroll
                for (int j = 0; j < 8; j++) acc[i][j] += a[i] * b[j];
        }
        __syncthreads();
    }
#pragma unroll
    for (int i = 0; i < 8; i++) {
        int m = m0 + ty*8 + i;
        if (m >= M) continue;
#pragma unroll
        for (int j4 = 0; j4 < 8; j4 += 4) {
            int n = n0 + tx*8 + j4;
            float4 bb = *(const float4*)(bias + n);
            float4 c = make_float4(acc[i][j4]+bb.x, acc[i][j4+1]+bb.y,
                                   acc[i][j4+2]+bb.z, acc[i][j4+3]+bb.w);
            if (MODE == 1) {
                c.x = 0.5f*c.x*(1.0f+erff(c.x*0.70710678118654752f));
                c.y = 0.5f*c.y*(1.0f+erff(c.y*0.70710678118654752f));
                c.z = 0.5f*c.z*(1.0f+erff(c.z*0.70710678118654752f));
                c.w = 0.5f*c.w*(1.0f+erff(c.w*0.70710678118654752f));
            }
            if (MODE == 2) {
                float4 rr = *(const float4*)(res + (size_t)m*ldr + n);
                c.x += rr.x; c.y += rr.y; c.z += rr.z; c.w += rr.w;
            }
            *(float4*)(Co + (size_t)m*ldc + n) = c;
        }
    }
}

// no-bias variant for eproj
__global__ void __launch_bounds__(256, 2)
k_gemm128_nb(const float* __restrict__ A, int lda,
             const float* __restrict__ B, int ldb,
             float* __restrict__ Co, int ldc, int M, int K) {
    __shared__ float Ash[16][132];
    __shared__ float Bsh[16][132];
    const int m0 = blockIdx.y * 128, n0 = blockIdx.x * 128;
    const int tid = threadIdx.x;
    const int tx = tid & 15, ty = tid >> 4;
    const int lr = tid >> 1, lh = (tid & 1) * 8;
    const int br = tid >> 4, bc = (tid & 15) * 8;
    float acc[8][8] = {};
    for (int k0 = 0; k0 < K; k0 += 16) {
        const float* ap = A + (size_t)(m0 + lr)*lda + k0 + lh;
        float4 a0 = *(const float4*)ap, a1 = *(const float4*)(ap + 4);
        Ash[lh+0][lr] = a0.x; Ash[lh+1][lr] = a0.y; Ash[lh+2][lr] = a0.z; Ash[lh+3][lr] = a0.w;
        Ash[lh+4][lr] = a1.x; Ash[lh+5][lr] = a1.y; Ash[lh+6][lr] = a1.z; Ash[lh+7][lr] = a1.w;
        const float* bp = B + (size_t)(k0 + br)*ldb + n0 + bc;
        *(float4*)&Bsh[br][bc]   = *(const float4*)bp;
        *(float4*)&Bsh[br][bc+4] = *(const float4*)(bp + 4);
        __syncthreads();
#pragma unroll
        for (int kk = 0; kk < 16; kk++) {
            float a[8], b[8];
            *(float4*)&a[0] = *(const float4*)&Ash[kk][ty*8];
            *(float4*)&a[4] = *(const float4*)&Ash[kk][ty*8+4];
            *(float4*)&b[0] = *(const float4*)&Bsh[kk][tx*8];
            *(float4*)&b[4] = *(const float4*)&Bsh[kk][tx*8+4];
#pragma unroll
            for (int i = 0; i < 8; i++)
#pragma unroll
                for (int j = 0; j < 8; j++) acc[i][j] += a[i] * b[j];
        }
        __syncthreads();
    }
#pragma unroll
    for (int i = 0; i < 8; i++) {
        int m = m0 + ty*8 + i;
#pragma unroll
        for (int j4 = 0; j4 < 8; j4 += 4) {
            int n = n0 + tx*8 + j4;
            *(float4*)(Co + (size_t)m*ldc + n) =
                make_float4(acc[i][j4], acc[i][j4+1], acc[i][j4+2], acc[i][j4+3]);
        }
    }
}

// ---------------- attention ----------------
__global__ void k_alpha(const int* __restrict__ src, const int* __restrict__ dst) {
    int idx = blockIdx.x * blockDim.x + threadIdx.x;   // EE*NH
    int e = idx >> 3, hh = idx & 7;
    int s = src[e], d = dst[e];
    const float4* qp = (const float4*)(g_qkvs + (size_t)d*512 + hh*16);
    const float4* kp = (const float4*)(g_qkvs + (size_t)s*512 + 128 + hh*16);
    const float4* ep = (const float4*)(g_eproj + (size_t)e*128 + hh*16);
    float sum = 0.0f;
#pragma unroll
    for (int i = 0; i < 4; i++) {
        float4 q = qp[i], k = kp[i], ev = ep[i];
        sum += q.x*(k.x+ev.x) + q.y*(k.y+ev.y) + q.z*(k.z+ev.z) + q.w*(k.w+ev.w);
    }
    float a = sum * 0.25f;
    g_alpha[idx] = a;
    atomicMaxF(&g_amax[(size_t)d*NH + hh], a);
}

__global__ void k_pe(const int* __restrict__ dst) {
    int idx = blockIdx.x * blockDim.x + threadIdx.x;   // EE*NH
    int e = idx >> 3, hh = idx & 7;
    int d = dst[e];
    float p = expf(g_alpha[idx] - g_amax[(size_t)d*NH + hh]);
    g_alpha[idx] = p;
    atomicAdd(&g_denom[(size_t)d*NH + hh], p);
}

__global__ void k_agg(const int* __restrict__ src, const int* __restrict__ dst) {
    int idx = blockIdx.x * blockDim.x + threadIdx.x;   // EE*32
    int e = idx >> 5, t = idx & 31;
    int s = src[e], d = dst[e];
    int hh = t >> 2;
    float attn = g_alpha[(size_t)e*NH + hh] / g_denom[(size_t)d*NH + hh];
    float4 v = *(const float4*)(g_qkvs + (size_t)s*512 + 256 + t*4);
    float4 ev = *(const float4*)(g_eproj + (size_t)e*128 + t*4);
    float* o = g_agg + (size_t)d*128 + t*4;
    float m0 = attn*(v.x+ev.x), m1 = attn*(v.y+ev.y);
    float m2 = attn*(v.z+ev.z), m3 = attn*(v.w+ev.w);
    asm volatile("red.global.add.v4.f32 [%0], {%1,%2,%3,%4};"
                 :: "l"(o), "f"(m0), "f"(m1), "f"(m2), "f"(m3) : "memory");
}

// ---------------- edge update: tf32 mma.sync gather-GEMM + fused gate+LN ----------------
// Tile: 128 edges x 128 outputs, K=320 in 10 chunks of 32.
// 8 warps: wm = warp>>1 (4 along M, 32 rows each), wn = warp&1 (2 along N, 64 cols each).
// Per warp: 2 m16-tiles x 8 n8-tiles of mma.m16n8k8.tf32.
constexpr int ALD = 36;    // A smem ld (36 mod 32 = 4 -> conflict-free frag reads)
constexpr int BLD = 136;   // B smem ld (136 mod 32 = 8 -> conflict-free frag reads)
constexpr int EDGE_SMEM = 128*132*4;  // raw overlay dominates (67584 B)

__global__ void __launch_bounds__(256, 2)
k_edge_mma(const int* __restrict__ src, const int* __restrict__ dst,
           const float* __restrict__ ea,
           const float* __restrict__ W, const float* __restrict__ bvec,
           const float* __restrict__ eg, const float* __restrict__ ebias,
           float* __restrict__ out) {
    extern __shared__ float sm[];
    uint32_t (*Ash)[ALD] = (uint32_t(*)[ALD])sm;                 // 128 x 36  (18432 B)
    uint32_t (*Bsh)[BLD] = (uint32_t(*)[BLD])(sm + 128*ALD);     // 32 x 136  (17408 B)
    float    (*raw)[132] = (float(*)[132])sm;                    // overlay after mainloop
    __shared__ int sidx[128], didx[128];

    const int tid  = threadIdx.x;
    const int warp = tid >> 5, lane = tid & 31;
    const int e0 = blockIdx.x * 128;
    if (tid < 128) { sidx[tid] = src[e0+tid]; didx[tid] = dst[e0+tid]; }
    __syncthreads();

    const int wm = warp >> 1, wn = warp & 1;
    const int Mb = wm * 32, Nb = wn * 64;
    const int lg = lane >> 2, lt = lane & 3;   // groupID, threadID_in_group

    // loader indices
    const int lr = tid >> 1, lc = (tid & 1) * 16;        // A: row 0..127, col block 0/16
    const int kb = tid >> 3, cb = (tid & 7) * 16;        // B: row 0..31,  col block

    float acc[2][8][4] = {};

    for (int c = 0; c < 10; c++) {
        const int k0 = c * 32;
        // ---- load A chunk (gathered, cvt to tf32) ----
        {
            const float* base; int col;
            if (k0 < 128)      { base = g_xn + (size_t)sidx[lr]*128; col = k0 + lc; }
            else if (k0 < 256) { base = g_xn + (size_t)didx[lr]*128; col = k0 - 128 + lc; }
            else               { base = ea + (size_t)(e0+lr)*64;     col = k0 - 256 + lc; }
#pragma unroll
            for (int i = 0; i < 4; i++) {
                float4 v = *(const float4*)(base + col + i*4);
                Ash[lr][lc + i*4 + 0] = f2tf32(v.x);
                Ash[lr][lc + i*4 + 1] = f2tf32(v.y);
                Ash[lr][lc + i*4 + 2] = f2tf32(v.z);
                Ash[lr][lc + i*4 + 3] = f2tf32(v.w);
            }
        }
        // ---- load B chunk (W rows k0..k0+31, cvt to tf32) ----
        {
            const float* bp = W + (size_t)(k0 + kb)*128 + cb;
#pragma unroll
            for (int i = 0; i < 4; i++) {
                float4 v = *(const float4*)(bp + i*4);
                Bsh[kb][cb + i*4 + 0] = f2tf32(v.x);
                Bsh[kb][cb + i*4 + 1] = f2tf32(v.y);
                Bsh[kb][cb + i*4 + 2] = f2tf32(v.z);
                Bsh[kb][cb + i*4 + 3] = f2tf32(v.w);
            }
        }
        __syncthreads();

#pragma unroll
        for (int kq = 0; kq < 4; kq++) {
            const int kc = kq * 8;
            uint32_t b0[8], b1[8];
#pragma unroll
            for (int nt = 0; nt < 8; nt++) {
                int colB = Nb + nt*8 + lg;
                b0[nt] = Bsh[kc + lt][colB];
                b1[nt] = Bsh[kc + 4 + lt][colB];
            }
#pragma unroll
            for (int mt = 0; mt < 2; mt++) {
                int rb = Mb + mt*16;
                uint32_t a0 = Ash[rb + lg    ][kc + lt];
                uint32_t a1 = Ash[rb + 8 + lg][kc + lt];
                uint32_t a2 = Ash[rb + lg    ][kc + 4 + lt];
                uint32_t a3 = Ash[rb + 8 + lg][kc + 4 + lt];
#pragma unroll
                for (int nt = 0; nt < 8; nt++)
                    mma_tf32(acc[mt][nt], a0, a1, a2, a3, b0[nt], b1[nt]);
            }
        }
        __syncthreads();
    }

    // ---- bias + relu -> raw smem (overlays A/B tiles) ----
#pragma unroll
    for (int mt = 0; mt < 2; mt++) {
        int r0 = Mb + mt*16 + lg;
#pragma unroll
        for (int nt = 0; nt < 8; nt++) {
            int c0 = Nb + nt*8 + 2*lt;
            float2 bb = *(const float2*)(bvec + c0);
            *(float2*)&raw[r0][c0] =
                make_float2(fmaxf(acc[mt][nt][0] + bb.x, 0.0f),
                            fmaxf(acc[mt][nt][1] + bb.y, 0.0f));
            *(float2*)&raw[r0 + 8][c0] =
                make_float2(fmaxf(acc[mt][nt][2] + bb.x, 0.0f),
                            fmaxf(acc[mt][nt][3] + bb.y, 0.0f));
        }
    }
    __syncthreads();

    // ---- t = edge_attr + sigmoid(gate)*delta; LN over 64 ----
#pragma unroll
    for (int half = 0; half < 2; half++) {
        int r = (tid >> 2) + half * 64;
        int q = tid & 3;
        float t[16]; float s = 0.0f;
#pragma unroll
        for (int i4 = 0; i4 < 16; i4 += 4) {
            int cc = q*16 + i4;
            float4 e4 = *(const float4*)(ea + (size_t)(e0+r)*64 + cc);
            t[i4+0] = e4.x + raw[r][cc+0] / (1.0f + expf(-raw[r][64+cc+0]));
            t[i4+1] = e4.y + raw[r][cc+1] / (1.0f + expf(-raw[r][64+cc+1]));
            t[i4+2] = e4.z + raw[r][cc+2] / (1.0f + expf(-raw[r][64+cc+2]));
            t[i4+3] = e4.w + raw[r][cc+3] / (1.0f + expf(-raw[r][64+cc+3]));
            s += t[i4+0] + t[i4+1] + t[i4+2] + t[i4+3];
        }
        s += __shfl_xor_sync(0xffffffffu, s, 1);
        s += __shfl_xor_sync(0xffffffffu, s, 2);
        float m = s * (1.0f/64.0f);
        float vs = 0.0f;
#pragma unroll
        for (int i = 0; i < 16; i++) { float dd = t[i] - m; vs += dd*dd; }
        vs += __shfl_xor_sync(0xffffffffu, vs, 1);
        vs += __shfl_xor_sync(0xffffffffu, vs, 2);
        float inv = rsqrtf(vs * (1.0f/64.0f) + 1e-5f);
#pragma unroll
        for (int i4 = 0; i4 < 16; i4 += 4) {
            int cc = q*16 + i4;
            float4 gv = *(const float4*)(eg + cc);
            float4 bb = *(const float4*)(ebias + cc);
            *(float4*)(out + (size_t)(e0+r)*64 + cc) =
                make_float4((t[i4+0]-m)*inv*gv.x+bb.x, (t[i4+1]-m)*inv*gv.y+bb.y,
                            (t[i4+2]-m)*inv*gv.z+bb.z, (t[i4+3]-m)*inv*gv.w+bb.w);
        }
    }
}

// ---------------- launcher ----------------
extern "C" void kernel_launch(void* const* d_in, const int* in_sizes, int n_in,
                              void* d_out, int out_size) {
    const float* x     = (const float*)d_in[0];
    const int*   ei    = (const int*)  d_in[1];
    const float* ea    = (const float*)d_in[2];
    const float* demb  = (const float*)d_in[3];
    const float* ng    = (const float*)d_in[4];
    const float* nbv   = (const float*)d_in[5];
    const float* Wq    = (const float*)d_in[6];
    const float* bq    = (const float*)d_in[7];
    const float* Wk    = (const float*)d_in[8];
    const float* bk    = (const float*)d_in[9];
    const float* Wv    = (const float*)d_in[10];
    const float* bv    = (const float*)d_in[11];
    const float* We    = (const float*)d_in[12];
    const float* Wskip = (const float*)d_in[13];
    const float* bskip = (const float*)d_in[14];
    const float* W1    = (const float*)d_in[15];
    const float* b1    = (const float*)d_in[16];
    const float* W2    = (const float*)d_in[17];
    const float* b2    = (const float*)d_in[18];
    const float* eung  = (const float*)d_in[19];
    const float* eunb  = (const float*)d_in[20];
    const float* euW   = (const float*)d_in[21];
    const float* eub   = (const float*)d_in[22];
    const float* eueg  = (const float*)d_in[23];
    const float* eueb  = (const float*)d_in[24];
    float* out = (float*)d_out;

    const int* src = ei;
    const int* dst = ei + EE;

    static float *p_h = nullptr, *p_qkvs = nullptr, *p_eproj = nullptr,
                 *p_h2 = nullptr, *p_ffn1 = nullptr, *p_xattn = nullptr,
                 *p_W4 = nullptr, *p_b4 = nullptr;
    static bool inited = false;
    if (!inited) {
        cudaGetSymbolAddress((void**)&p_h,     g_h);
        cudaGetSymbolAddress((void**)&p_qkvs,  g_qkvs);
        cudaGetSymbolAddress((void**)&p_eproj, g_eproj);
        cudaGetSymbolAddress((void**)&p_h2,    g_h2);
        cudaGetSymbolAddress((void**)&p_ffn1,  g_ffn1);
        cudaGetSymbolAddress((void**)&p_xattn, g_xattn);
        cudaGetSymbolAddress((void**)&p_W4,    g_W4);
        cudaGetSymbolAddress((void**)&p_b4,    g_b4);
        cudaFuncSetAttribute(k_edge_mma, cudaFuncAttributeMaxDynamicSharedMemorySize, EDGE_SMEM);
        inited = true;
    }

    k_init<<<2048, 256>>>();
    k_deg<<<(EE + 255)/256, 256>>>(src);
    k_pack<<<64, 256>>>(Wq, Wk, Wv, Wskip, bq, bk, bv, bskip);
    k_node_prep<<<(NN + 7)/8, 256>>>(x, demb, ng, nbv);

    // fused QKV+skip: [50000x128] @ [128x512]
    k_gemm128<0><<<dim3(4, (NN+127)/128), 256>>>(p_h, 128, p_W4, 512, p_b4, p_qkvs, 512,
                                                 nullptr, 0, NN, 128);
    // edge proj: [800000x64] @ [64x128]
    k_gemm128_nb<<<dim3(1, EE/128), 256>>>(ea, 64, We, 128, p_eproj, 128, EE, 64);

    k_alpha<<<(EE*NH)/256, 256>>>(src, dst);
    k_pe   <<<(EE*NH)/256, 256>>>(dst);
    k_agg  <<<(EE*32)/256, 256>>>(src, dst);

    k_node_post<<<(NN + 7)/8, 256>>>(ng, nbv);

    // FFN
    k_gemm128<1><<<dim3(4, (NN+127)/128), 256>>>(p_h2, 128, W1, 512, b1, p_ffn1, 512,
                                                 nullptr, 0, NN, 128);
    k_gemm128<2><<<dim3(1, (NN+127)/128), 256>>>(p_ffn1, 512, W2, 128, b2, out, 128,
                                                 p_xattn, 128, NN, 512);

    k_xn<<<(NN + 7)/8, 256>>>(out, eung, eunb);
    k_edge_mma<<<EE/128, 256, EDGE_SMEM>>>(src, dst, ea, euW, eub, eueg, eueb,
                                           out + (size_t)NN*DIM);
}

// round 7
// speedup vs baseline: 1.9453x; 1.2635x over previous
#include <cuda_runtime.h>
#include <math.h>
#include <stdint.h>

// ---------------- problem constants ----------------
constexpr int NN   = 50000;
constexpr int EE   = 800000;
constexpr int DIM  = 128;
constexpr int NH   = 8;
constexpr int HID  = 512;
constexpr int KEU  = 320;

// ---------------- scratch ----------------
__device__ float g_xin  [(size_t)NN*DIM];
__device__ float g_h    [(size_t)NN*DIM];
__device__ float g_qkvs [(size_t)NN*4*DIM];   // q[0:128) k[128:256) v[256:384) skip[384:512)
__device__ float g_eproj[(size_t)EE*DIM];
__device__ float g_alpha[(size_t)EE*NH];
__device__ float g_amax [(size_t)NN*NH];
__device__ float g_denom[(size_t)NN*NH];
__device__ float g_agg  [(size_t)NN*DIM];
__device__ float g_xattn[(size_t)NN*DIM];
__device__ float g_h2   [(size_t)NN*DIM];
__device__ float g_ffn1 [(size_t)NN*HID];
__device__ float g_xn   [(size_t)NN*DIM];
__device__ float g_W4   [(size_t)DIM*512];
__device__ float g_b4   [512];
__device__ int   g_deg  [NN];

// ---------------- helpers ----------------
__device__ __forceinline__ float warp_sum(float v) {
#pragma unroll
    for (int o = 16; o > 0; o >>= 1) v += __shfl_xor_sync(0xffffffffu, v, o);
    return v;
}
__device__ __forceinline__ void atomicMaxF(float* addr, float v) {
    if (v >= 0.0f) atomicMax((int*)addr, __float_as_int(v));
    else           atomicMin((unsigned int*)addr, __float_as_uint(v));
}
__device__ __forceinline__ uint32_t f2tf32(float f) {
    uint32_t r;
    asm("cvt.rna.tf32.f32 %0, %1;" : "=r"(r) : "f"(f));
    return r;
}
__device__ __forceinline__ void mma_tf32(float* c,
                                         uint32_t a0, uint32_t a1, uint32_t a2, uint32_t a3,
                                         uint32_t b0, uint32_t b1) {
    asm volatile("mma.sync.aligned.m16n8k8.row.col.f32.tf32.tf32.f32 "
                 "{%0,%1,%2,%3}, {%4,%5,%6,%7}, {%8,%9}, {%0,%1,%2,%3};"
                 : "+f"(c[0]), "+f"(c[1]), "+f"(c[2]), "+f"(c[3])
                 : "r"(a0), "r"(a1), "r"(a2), "r"(a3), "r"(b0), "r"(b1));
}
__device__ __forceinline__ float gelu_erf(float v) {
    return 0.5f * v * (1.0f + erff(v * 0.70710678118654752f));
}

// ---------------- init / degree ----------------
__global__ void k_init() {
    int i  = blockIdx.x * blockDim.x + threadIdx.x;
    int st = gridDim.x * blockDim.x;
    for (int j = i; j < NN*DIM; j += st) g_agg[j] = 0.0f;
    for (int j = i; j < NN*NH;  j += st) { g_denom[j] = 0.0f; g_amax[j] = -INFINITY; }
    for (int j = i; j < NN;     j += st) g_deg[j] = 0;
}
__global__ void k_deg(const int* __restrict__ src) {
    int i = blockIdx.x * blockDim.x + threadIdx.x;
    if (i < EE) atomicAdd(&g_deg[src[i]], 1);
}
__global__ void k_pack(const float* __restrict__ Wq, const float* __restrict__ Wk,
                       const float* __restrict__ Wv, const float* __restrict__ Ws,
                       const float* __restrict__ bq, const float* __restrict__ bk,
                       const float* __restrict__ bv, const float* __restrict__ bs) {
    int i = blockIdx.x * blockDim.x + threadIdx.x;
    if (i < DIM*DIM) {
        int r = i >> 7, c = i & 127;
        g_W4[(size_t)r*512 +       c] = Wq[i];
        g_W4[(size_t)r*512 + 128 + c] = Wk[i];
        g_W4[(size_t)r*512 + 256 + c] = Wv[i];
        g_W4[(size_t)r*512 + 384 + c] = Ws[i];
    }
    if (i < 128) {
        g_b4[i] = bq[i]; g_b4[128+i] = bk[i]; g_b4[256+i] = bv[i]; g_b4[384+i] = bs[i];
    }
}

// ---------------- fused LN kernels ----------------
__global__ void k_node_prep(const float* __restrict__ x, const float* __restrict__ demb,
                            const float* __restrict__ g, const float* __restrict__ b) {
    int row = blockIdx.x * 8 + (threadIdx.x >> 5);
    if (row >= NN) return;
    int lane = threadIdx.x & 31;
    int d = g_deg[row]; if (d > 255) d = 255;
    float4 xv = *(const float4*)(x + (size_t)row*DIM + lane*4);
    float4 dv = *(const float4*)(demb + (size_t)d*DIM + lane*4);
    float4 xi = make_float4(xv.x+dv.x, xv.y+dv.y, xv.z+dv.z, xv.w+dv.w);
    *(float4*)(g_xin + (size_t)row*DIM + lane*4) = xi;
    float m = warp_sum(xi.x+xi.y+xi.z+xi.w) * (1.0f/128.0f);
    float4 dd = make_float4(xi.x-m, xi.y-m, xi.z-m, xi.w-m);
    float var = warp_sum(dd.x*dd.x+dd.y*dd.y+dd.z*dd.z+dd.w*dd.w) * (1.0f/128.0f);
    float inv = rsqrtf(var + 1e-5f);
    float4 gv = *(const float4*)(g + lane*4);
    float4 bv = *(const float4*)(b + lane*4);
    *(float4*)(g_h + (size_t)row*DIM + lane*4) =
        make_float4(dd.x*inv*gv.x+bv.x, dd.y*inv*gv.y+bv.y, dd.z*inv*gv.z+bv.z, dd.w*inv*gv.w+bv.w);
}

__global__ void k_node_post(const float* __restrict__ g, const float* __restrict__ b) {
    int row = blockIdx.x * 8 + (threadIdx.x >> 5);
    if (row >= NN) return;
    int lane = threadIdx.x & 31;
    float4 xi = *(const float4*)(g_xin + (size_t)row*DIM + lane*4);
    float4 ag = *(const float4*)(g_agg + (size_t)row*DIM + lane*4);
    float4 sk = *(const float4*)(g_qkvs + (size_t)row*512 + 384 + lane*4);
    float4 xa = make_float4(xi.x+ag.x+sk.x, xi.y+ag.y+sk.y, xi.z+ag.z+sk.z, xi.w+ag.w+sk.w);
    *(float4*)(g_xattn + (size_t)row*DIM + lane*4) = xa;
    float m = warp_sum(xa.x+xa.y+xa.z+xa.w) * (1.0f/128.0f);
    float4 dd = make_float4(xa.x-m, xa.y-m, xa.z-m, xa.w-m);
    float var = warp_sum(dd.x*dd.x+dd.y*dd.y+dd.z*dd.z+dd.w*dd.w) * (1.0f/128.0f);
    float inv = rsqrtf(var + 1e-5f);
    float4 gv = *(const float4*)(g + lane*4);
    float4 bv = *(const float4*)(b + lane*4);
    *(float4*)(g_h2 + (size_t)row*DIM + lane*4) =
        make_float4(dd.x*inv*gv.x+bv.x, dd.y*inv*gv.y+bv.y, dd.z*inv*gv.z+bv.z, dd.w*inv*gv.w+bv.w);
}

__global__ void k_xn(const float* __restrict__ xnew,
                     const float* __restrict__ g, const float* __restrict__ b) {
    int row = blockIdx.x * 8 + (threadIdx.x >> 5);
    if (row >= NN) return;
    int lane = threadIdx.x & 31;
    float4 xv = *(const float4*)(xnew + (size_t)row*DIM + lane*4);
    float m = warp_sum(xv.x+xv.y+xv.z+xv.w) * (1.0f/128.0f);
    float4 dd = make_float4(xv.x-m, xv.y-m, xv.z-m, xv.w-m);
    float var = warp_sum(dd.x*dd.x+dd.y*dd.y+dd.z*dd.z+dd.w*dd.w) * (1.0f/128.0f);
    float inv = rsqrtf(var + 1e-5f);
    float4 gv = *(const float4*)(g + lane*4);
    float4 bv = *(const float4*)(b + lane*4);
    *(float4*)(g_xn + (size_t)row*DIM + lane*4) =
        make_float4(dd.x*inv*gv.x+bv.x, dd.y*inv*gv.y+bv.y, dd.z*inv*gv.z+bv.z, dd.w*inv*gv.w+bv.w);
}

// ---------------- generic tf32 mma GEMM: 128x128 tile, K chunks of 32 ----------------
// MODE 0: +bias. MODE 1: +bias, GELU. MODE 2: +bias +res. MODE 3: plain.
constexpr int ALD = 36;    // A smem ld (mod 32 = 4 -> conflict-free frag reads)
constexpr int BLD = 136;   // B smem ld (mod 32 = 8)

template<int MODE>
__global__ void __launch_bounds__(256, 2)
k_gemm_mma(const float* __restrict__ A, int lda,
           const float* __restrict__ B, int ldb,
           const float* __restrict__ bias,
           float* __restrict__ Co, int ldc,
           const float* __restrict__ res, int ldr,
           int M, int K) {
    __shared__ uint32_t Ash[128][ALD];
    __shared__ uint32_t Bsh[32][BLD];
    const int m0 = blockIdx.y * 128, n0 = blockIdx.x * 128;
    const int tid = threadIdx.x;
    const int warp = tid >> 5, lane = tid & 31;
    const int wm = warp >> 1, wn = warp & 1;
    const int Mb = wm * 32, Nb = wn * 64;
    const int lg = lane >> 2, lt = lane & 3;
    const int lr = tid >> 1, lc = (tid & 1) * 16;   // A loader
    const int kb = tid >> 3, cb = (tid & 7) * 16;   // B loader
    float acc[2][8][4] = {};

    for (int k0 = 0; k0 < K; k0 += 32) {
        if (m0 + lr < M) {
            const float* ap = A + (size_t)(m0 + lr)*lda + k0 + lc;
#pragma unroll
            for (int i = 0; i < 4; i++) {
                float4 v = *(const float4*)(ap + i*4);
                Ash[lr][lc + i*4 + 0] = f2tf32(v.x);
                Ash[lr][lc + i*4 + 1] = f2tf32(v.y);
                Ash[lr][lc + i*4 + 2] = f2tf32(v.z);
                Ash[lr][lc + i*4 + 3] = f2tf32(v.w);
            }
        } else {
#pragma unroll
            for (int i = 0; i < 16; i++) Ash[lr][lc + i] = 0u;
        }
        {
            const float* bp = B + (size_t)(k0 + kb)*ldb + n0 + cb;
#pragma unroll
            for (int i = 0; i < 4; i++) {
                float4 v = *(const float4*)(bp + i*4);
                Bsh[kb][cb + i*4 + 0] = f2tf32(v.x);
                Bsh[kb][cb + i*4 + 1] = f2tf32(v.y);
                Bsh[kb][cb + i*4 + 2] = f2tf32(v.z);
                Bsh[kb][cb + i*4 + 3] = f2tf32(v.w);
            }
        }
        __syncthreads();
#pragma unroll
        for (int kq = 0; kq < 4; kq++) {
            const int kc = kq * 8;
            uint32_t b0[8], b1[8];
#pragma unroll
            for (int nt = 0; nt < 8; nt++) {
                int colB = Nb + nt*8 + lg;
                b0[nt] = Bsh[kc + lt][colB];
                b1[nt] = Bsh[kc + 4 + lt][colB];
            }
#pragma unroll
            for (int mt = 0; mt < 2; mt++) {
                int rb = Mb + mt*16;
                uint32_t a0 = Ash[rb + lg    ][kc + lt];
                uint32_t a1 = Ash[rb + 8 + lg][kc + lt];
                uint32_t a2 = Ash[rb + lg    ][kc + 4 + lt];
                uint32_t a3 = Ash[rb + 8 + lg][kc + 4 + lt];
#pragma unroll
                for (int nt = 0; nt < 8; nt++)
                    mma_tf32(acc[mt][nt], a0, a1, a2, a3, b0[nt], b1[nt]);
            }
        }
        __syncthreads();
    }

    // fragment epilogue -> global
#pragma unroll
    for (int mt = 0; mt < 2; mt++) {
        int r0 = m0 + Mb + mt*16 + lg;
#pragma unroll
        for (int nt = 0; nt < 8; nt++) {
            int cg = n0 + Nb + nt*8 + 2*lt;
            float2 bb = (MODE == 3) ? make_float2(0.0f, 0.0f)
                                    : *(const float2*)(bias + cg);
#pragma unroll
            for (int hrow = 0; hrow < 2; hrow++) {
                int m = r0 + hrow*8;
                if (m >= M) continue;
                float cx = acc[mt][nt][hrow*2 + 0] + bb.x;
                float cy = acc[mt][nt][hrow*2 + 1] + bb.y;
                if (MODE == 1) { cx = gelu_erf(cx); cy = gelu_erf(cy); }
                if (MODE == 2) {
                    float2 rr = *(const float2*)(res + (size_t)m*ldr + cg);
                    cx += rr.x; cy += rr.y;
                }
                *(float2*)(Co + (size_t)m*ldc + cg) = make_float2(cx, cy);
            }
        }
    }
}

// ---------------- attention ----------------
__global__ void k_alpha(const int* __restrict__ src, const int* __restrict__ dst) {
    int idx = blockIdx.x * blockDim.x + threadIdx.x;   // EE*NH
    int e = idx >> 3, hh = idx & 7;
    int s = src[e], d = dst[e];
    const float4* qp = (const float4*)(g_qkvs + (size_t)d*512 + hh*16);
    const float4* kp = (const float4*)(g_qkvs + (size_t)s*512 + 128 + hh*16);
    const float4* ep = (const float4*)(g_eproj + (size_t)e*128 + hh*16);
    float sum = 0.0f;
#pragma unroll
    for (int i = 0; i < 4; i++) {
        float4 q = qp[i], k = kp[i], ev = ep[i];
        sum += q.x*(k.x+ev.x) + q.y*(k.y+ev.y) + q.z*(k.z+ev.z) + q.w*(k.w+ev.w);
    }
    float a = sum * 0.25f;
    g_alpha[idx] = a;
    atomicMaxF(&g_amax[(size_t)d*NH + hh], a);
}

__global__ void k_pe(const int* __restrict__ dst) {
    int idx = blockIdx.x * blockDim.x + threadIdx.x;   // EE*NH
    int e = idx >> 3, hh = idx & 7;
    int d = dst[e];
    float p = expf(g_alpha[idx] - g_amax[(size_t)d*NH + hh]);
    g_alpha[idx] = p;
    atomicAdd(&g_denom[(size_t)d*NH + hh], p);
}

__global__ void k_agg(const int* __restrict__ src, const int* __restrict__ dst) {
    int idx = blockIdx.x * blockDim.x + threadIdx.x;   // EE*32
    int e = idx >> 5, t = idx & 31;
    int s = src[e], d = dst[e];
    int hh = t >> 2;
    float attn = g_alpha[(size_t)e*NH + hh] / g_denom[(size_t)d*NH + hh];
    float4 v = *(const float4*)(g_qkvs + (size_t)s*512 + 256 + t*4);
    float4 ev = *(const float4*)(g_eproj + (size_t)e*128 + t*4);
    float* o = g_agg + (size_t)d*128 + t*4;
    float m0 = attn*(v.x+ev.x), m1 = attn*(v.y+ev.y);
    float m2 = attn*(v.z+ev.z), m3 = attn*(v.w+ev.w);
    asm volatile("red.global.add.v4.f32 [%0], {%1,%2,%3,%4};"
                 :: "l"(o), "f"(m0), "f"(m1), "f"(m2), "f"(m3) : "memory");
}

// ---------------- edge update: tf32 mma.sync gather-GEMM + fused gate+LN ----------------
constexpr int EDGE_SMEM = 128*132*4;  // raw overlay dominates (67584 B)

__global__ void __launch_bounds__(256, 2)
k_edge_mma(const int* __restrict__ src, const int* __restrict__ dst,
           const float* __restrict__ ea,
           const float* __restrict__ W, const float* __restrict__ bvec,
           const float* __restrict__ eg, const float* __restrict__ ebias,
           float* __restrict__ out) {
    extern __shared__ float sm[];
    uint32_t (*Ash)[ALD] = (uint32_t(*)[ALD])sm;                 // 128 x 36
    uint32_t (*Bsh)[BLD] = (uint32_t(*)[BLD])(sm + 128*ALD);     // 32 x 136
    float    (*raw)[132] = (float(*)[132])sm;                    // overlay after mainloop
    __shared__ int sidx[128], didx[128];

    const int tid  = threadIdx.x;
    const int warp = tid >> 5, lane = tid & 31;
    const int e0 = blockIdx.x * 128;
    if (tid < 128) { sidx[tid] = src[e0+tid]; didx[tid] = dst[e0+tid]; }
    __syncthreads();

    const int wm = warp >> 1, wn = warp & 1;
    const int Mb = wm * 32, Nb = wn * 64;
    const int lg = lane >> 2, lt = lane & 3;
    const int lr = tid >> 1, lc = (tid & 1) * 16;
    const int kb = tid >> 3, cb = (tid & 7) * 16;

    float acc[2][8][4] = {};

    for (int c = 0; c < 10; c++) {
        const int k0 = c * 32;
        {
            const float* base; int col;
            if (k0 < 128)      { base = g_xn + (size_t)sidx[lr]*128; col = k0 + lc; }
            else if (k0 < 256) { base = g_xn + (size_t)didx[lr]*128; col = k0 - 128 + lc; }
            else               { base = ea + (size_t)(e0+lr)*64;     col = k0 - 256 + lc; }
#pragma unroll
            for (int i = 0; i < 4; i++) {
                float4 v = *(const float4*)(base + col + i*4);
                Ash[lr][lc + i*4 + 0] = f2tf32(v.x);
                Ash[lr][lc + i*4 + 1] = f2tf32(v.y);
                Ash[lr][lc + i*4 + 2] = f2tf32(v.z);
                Ash[lr][lc + i*4 + 3] = f2tf32(v.w);
            }
        }
        {
            const float* bp = W + (size_t)(k0 + kb)*128 + cb;
#pragma unroll
            for (int i = 0; i < 4; i++) {
                float4 v = *(const float4*)(bp + i*4);
                Bsh[kb][cb + i*4 + 0] = f2tf32(v.x);
                Bsh[kb][cb + i*4 + 1] = f2tf32(v.y);
                Bsh[kb][cb + i*4 + 2] = f2tf32(v.z);
                Bsh[kb][cb + i*4 + 3] = f2tf32(v.w);
            }
        }
        __syncthreads();

#pragma unroll
        for (int kq = 0; kq < 4; kq++) {
            const int kc = kq * 8;
            uint32_t b0[8], b1[8];
#pragma unroll
            for (int nt = 0; nt < 8; nt++) {
                int colB = Nb + nt*8 + lg;
                b0[nt] = Bsh[kc + lt][colB];
                b1[nt] = Bsh[kc + 4 + lt][colB];
            }
#pragma unroll
            for (int mt = 0; mt < 2; mt++) {
                int rb = Mb + mt*16;
                uint32_t a0 = Ash[rb + lg    ][kc + lt];
                uint32_t a1 = Ash[rb + 8 + lg][kc + lt];
                uint32_t a2 = Ash[rb + lg    ][kc + 4 + lt];
                uint32_t a3 = Ash[rb + 8 + lg][kc + 4 + lt];
#pragma unroll
                for (int nt = 0; nt < 8; nt++)
                    mma_tf32(acc[mt][nt], a0, a1, a2, a3, b0[nt], b1[nt]);
            }
        }
        __syncthreads();
    }

    // bias + relu -> raw smem (overlays A/B tiles)
#pragma unroll
    for (int mt = 0; mt < 2; mt++) {
        int r0 = Mb + mt*16 + lg;
#pragma unroll
        for (int nt = 0; nt < 8; nt++) {
            int c0 = Nb + nt*8 + 2*lt;
            float2 bb = *(const float2*)(bvec + c0);
            *(float2*)&raw[r0][c0] =
                make_float2(fmaxf(acc[mt][nt][0] + bb.x, 0.0f),
                            fmaxf(acc[mt][nt][1] + bb.y, 0.0f));
            *(float2*)&raw[r0 + 8][c0] =
                make_float2(fmaxf(acc[mt][nt][2] + bb.x, 0.0f),
                            fmaxf(acc[mt][nt][3] + bb.y, 0.0f));
        }
    }
    __syncthreads();

    // t = edge_attr + sigmoid(gate)*delta; LN over 64
#pragma unroll
    for (int half = 0; half < 2; half++) {
        int r = (tid >> 2) + half * 64;
        int q = tid & 3;
        float t[16]; float s = 0.0f;
#pragma unroll
        for (int i4 = 0; i4 < 16; i4 += 4) {
            int cc = q*16 + i4;
            float4 e4 = *(const float4*)(ea + (size_t)(e0+r)*64 + cc);
            t[i4+0] = e4.x + raw[r][cc+0] / (1.0f + expf(-raw[r][64+cc+0]));
            t[i4+1] = e4.y + raw[r][cc+1] / (1.0f + expf(-raw[r][64+cc+1]));
            t[i4+2] = e4.z + raw[r][cc+2] / (1.0f + expf(-raw[r][64+cc+2]));
            t[i4+3] = e4.w + raw[r][cc+3] / (1.0f + expf(-raw[r][64+cc+3]));
            s += t[i4+0] + t[i4+1] + t[i4+2] + t[i4+3];
        }
        s += __shfl_xor_sync(0xffffffffu, s, 1);
        s += __shfl_xor_sync(0xffffffffu, s, 2);
        float m = s * (1.0f/64.0f);
        float vs = 0.0f;
#pragma unroll
        for (int i = 0; i < 16; i++) { float dd = t[i] - m; vs += dd*dd; }
        vs += __shfl_xor_sync(0xffffffffu, vs, 1);
        vs += __shfl_xor_sync(0xffffffffu, vs, 2);
        float inv = rsqrtf(vs * (1.0f/64.0f) + 1e-5f);
#pragma unroll
        for (int i4 = 0; i4 < 16; i4 += 4) {
            int cc = q*16 + i4;
            float4 gv = *(const float4*)(eg + cc);
            float4 bb = *(const float4*)(ebias + cc);
            *(float4*)(out + (size_t)(e0+r)*64 + cc) =
                make_float4((t[i4+0]-m)*inv*gv.x+bb.x, (t[i4+1]-m)*inv*gv.y+bb.y,
                            (t[i4+2]-m)*inv*gv.z+bb.z, (t[i4+3]-m)*inv*gv.w+bb.w);
        }
    }
}

// ---------------- launcher ----------------
extern "C" void kernel_launch(void* const* d_in, const int* in_sizes, int n_in,
                              void* d_out, int out_size) {
    const float* x     = (const float*)d_in[0];
    const int*   ei    = (const int*)  d_in[1];
    const float* ea    = (const float*)d_in[2];
    const float* demb  = (const float*)d_in[3];
    const float* ng    = (const float*)d_in[4];
    const float* nbv   = (const float*)d_in[5];
    const float* Wq    = (const float*)d_in[6];
    const float* bq    = (const float*)d_in[7];
    const float* Wk    = (const float*)d_in[8];
    const float* bk    = (const float*)d_in[9];
    const float* Wv    = (const float*)d_in[10];
    const float* bv    = (const float*)d_in[11];
    const float* We    = (const float*)d_in[12];
    const float* Wskip = (const float*)d_in[13];
    const float* bskip = (const float*)d_in[14];
    const float* W1    = (const float*)d_in[15];
    const float* b1    = (const float*)d_in[16];
    const float* W2    = (const float*)d_in[17];
    const float* b2    = (const float*)d_in[18];
    const float* eung  = (const float*)d_in[19];
    const float* eunb  = (const float*)d_in[20];
    const float* euW   = (const float*)d_in[21];
    const float* eub   = (const float*)d_in[22];
    const float* eueg  = (const float*)d_in[23];
    const float* eueb  = (const float*)d_in[24];
    float* out = (float*)d_out;

    const int* src = ei;
    const int* dst = ei + EE;

    static float *p_h = nullptr, *p_qkvs = nullptr, *p_eproj = nullptr,
                 *p_h2 = nullptr, *p_ffn1 = nullptr, *p_xattn = nullptr,
                 *p_W4 = nullptr, *p_b4 = nullptr;
    static bool inited = false;
    if (!inited) {
        cudaGetSymbolAddress((void**)&p_h,     g_h);
        cudaGetSymbolAddress((void**)&p_qkvs,  g_qkvs);
        cudaGetSymbolAddress((void**)&p_eproj, g_eproj);
        cudaGetSymbolAddress((void**)&p_h2,    g_h2);
        cudaGetSymbolAddress((void**)&p_ffn1,  g_ffn1);
        cudaGetSymbolAddress((void**)&p_xattn, g_xattn);
        cudaGetSymbolAddress((void**)&p_W4,    g_W4);
        cudaGetSymbolAddress((void**)&p_b4,    g_b4);
        cudaFuncSetAttribute(k_edge_mma, cudaFuncAttributeMaxDynamicSharedMemorySize, EDGE_SMEM);
        inited = true;
    }

    const int MB = (NN + 127) / 128;   // 391

    k_init<<<2048, 256>>>();
    k_deg<<<(EE + 255)/256, 256>>>(src);
    k_pack<<<64, 256>>>(Wq, Wk, Wv, Wskip, bq, bk, bv, bskip);
    k_node_prep<<<(NN + 7)/8, 256>>>(x, demb, ng, nbv);

    // fused QKV+skip: [50000x128] @ [128x512]  (tf32 mma)
    k_gemm_mma<0><<<dim3(4, MB), 256>>>(p_h, 128, p_W4, 512, p_b4, p_qkvs, 512,
                                        nullptr, 0, NN, 128);
    // edge proj: [800000x64] @ [64x128]  (tf32 mma, no bias)
    k_gemm_mma<3><<<dim3(1, EE/128), 256>>>(ea, 64, We, 128, nullptr, p_eproj, 128,
                                            nullptr, 0, EE, 64);

    k_alpha<<<(EE*NH)/256, 256>>>(src, dst);
    k_pe   <<<(EE*NH)/256, 256>>>(dst);
    k_agg  <<<(EE*32)/256, 256>>>(src, dst);

    k_node_post<<<(NN + 7)/8, 256>>>(ng, nbv);

    // FFN (tf32 mma)
    k_gemm_mma<1><<<dim3(4, MB), 256>>>(p_h2, 128, W1, 512, b1, p_ffn1, 512,
                                        nullptr, 0, NN, 128);
    k_gemm_mma<2><<<dim3(1, MB), 256>>>(p_ffn1, 512, W2, 128, b2, out, 128,
                                        p_xattn, 128, NN, 512);

    k_xn<<<(NN + 7)/8, 256>>>(out, eung, eunb);
    k_edge_mma<<<EE/128, 256, EDGE_SMEM>>>(src, dst, ea, euW, eub, eueg, eueb,
                                           out + (size_t)NN*DIM);
}

// round 8
// speedup vs baseline: 2.1387x; 1.0994x over previous
#include <cuda_runtime.h>
#include <math.h>
#include <stdint.h>

// ---------------- problem constants ----------------
constexpr int NN   = 50000;
constexpr int EE   = 800000;
constexpr int DIM  = 128;
constexpr int NH   = 8;
constexpr int HID  = 512;
constexpr int KEU  = 320;

// ---------------- scratch ----------------
__device__ float g_xin  [(size_t)NN*DIM];
__device__ float g_h    [(size_t)NN*DIM];
__device__ float g_qkvs [(size_t)NN*4*DIM];   // q[0:128) k[128:256) v[256:384) skip[384:512)
__device__ float g_eproj[(size_t)EE*DIM];
__device__ float g_denom[(size_t)NN*NH];
__device__ float g_agg  [(size_t)NN*DIM];     // UNNORMALIZED sum of pe*(v+e)
__device__ float g_xattn[(size_t)NN*DIM];
__device__ float g_h2   [(size_t)NN*DIM];
__device__ float g_ffn1 [(size_t)NN*HID];
__device__ float g_xn   [(size_t)NN*DIM];
__device__ float g_W4   [(size_t)DIM*512];
__device__ float g_b4   [512];
__device__ int   g_deg  [NN];

// ---------------- helpers ----------------
__device__ __forceinline__ float warp_sum(float v) {
#pragma unroll
    for (int o = 16; o > 0; o >>= 1) v += __shfl_xor_sync(0xffffffffu, v, o);
    return v;
}
__device__ __forceinline__ uint32_t f2tf32(float f) {
    uint32_t r;
    asm("cvt.rna.tf32.f32 %0, %1;" : "=r"(r) : "f"(f));
    return r;
}
__device__ __forceinline__ void mma_tf32(float* c,
                                         uint32_t a0, uint32_t a1, uint32_t a2, uint32_t a3,
                                         uint32_t b0, uint32_t b1) {
    asm volatile("mma.sync.aligned.m16n8k8.row.col.f32.tf32.tf32.f32 "
                 "{%0,%1,%2,%3}, {%4,%5,%6,%7}, {%8,%9}, {%0,%1,%2,%3};"
                 : "+f"(c[0]), "+f"(c[1]), "+f"(c[2]), "+f"(c[3])
                 : "r"(a0), "r"(a1), "r"(a2), "r"(a3), "r"(b0), "r"(b1));
}
__device__ __forceinline__ float gelu_erf(float v) {
    return 0.5f * v * (1.0f + erff(v * 0.70710678118654752f));
}

// ---------------- init / degree ----------------
__global__ void k_init() {
    int i  = blockIdx.x * blockDim.x + threadIdx.x;
    int st = gridDim.x * blockDim.x;
    for (int j = i; j < NN*DIM; j += st) g_agg[j] = 0.0f;
    for (int j = i; j < NN*NH;  j += st) g_denom[j] = 0.0f;
    for (int j = i; j < NN;     j += st) g_deg[j] = 0;
}
__global__ void k_deg(const int* __restrict__ src) {
    int i = blockIdx.x * blockDim.x + threadIdx.x;
    if (i < EE) atomicAdd(&g_deg[src[i]], 1);
}
__global__ void k_pack(const float* __restrict__ Wq, const float* __restrict__ Wk,
                       const float* __restrict__ Wv, const float* __restrict__ Ws,
                       const float* __restrict__ bq, const float* __restrict__ bk,
                       const float* __restrict__ bv, const float* __restrict__ bs) {
    int i = blockIdx.x * blockDim.x + threadIdx.x;
    if (i < DIM*DIM) {
        int r = i >> 7, c = i & 127;
        g_W4[(size_t)r*512 +       c] = Wq[i];
        g_W4[(size_t)r*512 + 128 + c] = Wk[i];
        g_W4[(size_t)r*512 + 256 + c] = Wv[i];
        g_W4[(size_t)r*512 + 384 + c] = Ws[i];
    }
    if (i < 128) {
        g_b4[i] = bq[i]; g_b4[128+i] = bk[i]; g_b4[256+i] = bv[i]; g_b4[384+i] = bs[i];
    }
}

// ---------------- fused LN kernels ----------------
__global__ void k_node_prep(const float* __restrict__ x, const float* __restrict__ demb,
                            const float* __restrict__ g, const float* __restrict__ b) {
    int row = blockIdx.x * 8 + (threadIdx.x >> 5);
    if (row >= NN) return;
    int lane = threadIdx.x & 31;
    int d = g_deg[row]; if (d > 255) d = 255;
    float4 xv = *(const float4*)(x + (size_t)row*DIM + lane*4);
    float4 dv = *(const float4*)(demb + (size_t)d*DIM + lane*4);
    float4 xi = make_float4(xv.x+dv.x, xv.y+dv.y, xv.z+dv.z, xv.w+dv.w);
    *(float4*)(g_xin + (size_t)row*DIM + lane*4) = xi;
    float m = warp_sum(xi.x+xi.y+xi.z+xi.w) * (1.0f/128.0f);
    float4 dd = make_float4(xi.x-m, xi.y-m, xi.z-m, xi.w-m);
    float var = warp_sum(dd.x*dd.x+dd.y*dd.y+dd.z*dd.z+dd.w*dd.w) * (1.0f/128.0f);
    float inv = rsqrtf(var + 1e-5f);
    float4 gv = *(const float4*)(g + lane*4);
    float4 bv = *(const float4*)(b + lane*4);
    *(float4*)(g_h + (size_t)row*DIM + lane*4) =
        make_float4(dd.x*inv*gv.x+bv.x, dd.y*inv*gv.y+bv.y, dd.z*inv*gv.z+bv.z, dd.w*inv*gv.w+bv.w);
}

// x_attn = x_in + agg/denom + skip; h2 = LN(x_attn)
__global__ void k_node_post(const float* __restrict__ g, const float* __restrict__ b) {
    int row = blockIdx.x * 8 + (threadIdx.x >> 5);
    if (row >= NN) return;
    int lane = threadIdx.x & 31;
    float dn = g_denom[(size_t)row*NH + (lane >> 2)];
    float rd = (dn != 0.0f) ? (1.0f / dn) : 0.0f;
    float4 xi = *(const float4*)(g_xin + (size_t)row*DIM + lane*4);
    float4 ag = *(const float4*)(g_agg + (size_t)row*DIM + lane*4);
    float4 sk = *(const float4*)(g_qkvs + (size_t)row*512 + 384 + lane*4);
    float4 xa = make_float4(xi.x+ag.x*rd+sk.x, xi.y+ag.y*rd+sk.y,
                            xi.z+ag.z*rd+sk.z, xi.w+ag.w*rd+sk.w);
    *(float4*)(g_xattn + (size_t)row*DIM + lane*4) = xa;
    float m = warp_sum(xa.x+xa.y+xa.z+xa.w) * (1.0f/128.0f);
    float4 dd = make_float4(xa.x-m, xa.y-m, xa.z-m, xa.w-m);
    float var = warp_sum(dd.x*dd.x+dd.y*dd.y+dd.z*dd.z+dd.w*dd.w) * (1.0f/128.0f);
    float inv = rsqrtf(var + 1e-5f);
    float4 gv = *(const float4*)(g + lane*4);
    float4 bv = *(const float4*)(b + lane*4);
    *(float4*)(g_h2 + (size_t)row*DIM + lane*4) =
        make_float4(dd.x*inv*gv.x+bv.x, dd.y*inv*gv.y+bv.y, dd.z*inv*gv.z+bv.z, dd.w*inv*gv.w+bv.w);
}

__global__ void k_xn(const float* __restrict__ xnew,
                     const float* __restrict__ g, const float* __restrict__ b) {
    int row = blockIdx.x * 8 + (threadIdx.x >> 5);
    if (row >= NN) return;
    int lane = threadIdx.x & 31;
    float4 xv = *(const float4*)(xnew + (size_t)row*DIM + lane*4);
    float m = warp_sum(xv.x+xv.y+xv.z+xv.w) * (1.0f/128.0f);
    float4 dd = make_float4(xv.x-m, xv.y-m, xv.z-m, xv.w-m);
    float var = warp_sum(dd.x*dd.x+dd.y*dd.y+dd.z*dd.z+dd.w*dd.w) * (1.0f/128.0f);
    float inv = rsqrtf(var + 1e-5f);
    float4 gv = *(const float4*)(g + lane*4);
    float4 bv = *(const float4*)(b + lane*4);
    *(float4*)(g_xn + (size_t)row*DIM + lane*4) =
        make_float4(dd.x*inv*gv.x+bv.x, dd.y*inv*gv.y+bv.y, dd.z*inv*gv.z+bv.z, dd.w*inv*gv.w+bv.w);
}

// ---------------- generic tf32 mma GEMM: 128x128 tile, K chunks of 32 ----------------
// MODE 0: +bias. MODE 1: +bias, GELU. MODE 2: +bias +res. MODE 3: plain.
constexpr int ALD = 36;
constexpr int BLD = 136;

template<int MODE>
__global__ void __launch_bounds__(256, 2)
k_gemm_mma(const float* __restrict__ A, int lda,
           const float* __restrict__ B, int ldb,
           const float* __restrict__ bias,
           float* __restrict__ Co, int ldc,
           const float* __restrict__ res, int ldr,
           int M, int K) {
    __shared__ uint32_t Ash[128][ALD];
    __shared__ uint32_t Bsh[32][BLD];
    const int m0 = blockIdx.y * 128, n0 = blockIdx.x * 128;
    const int tid = threadIdx.x;
    const int warp = tid >> 5, lane = tid & 31;
    const int wm = warp >> 1, wn = warp & 1;
    const int Mb = wm * 32, Nb = wn * 64;
    const int lg = lane >> 2, lt = lane & 3;
    const int lr = tid >> 1, lc = (tid & 1) * 16;
    const int kb = tid >> 3, cb = (tid & 7) * 16;
    float acc[2][8][4] = {};

    for (int k0 = 0; k0 < K; k0 += 32) {
        if (m0 + lr < M) {
            const float* ap = A + (size_t)(m0 + lr)*lda + k0 + lc;
#pragma unroll
            for (int i = 0; i < 4; i++) {
                float4 v = *(const float4*)(ap + i*4);
                Ash[lr][lc + i*4 + 0] = f2tf32(v.x);
                Ash[lr][lc + i*4 + 1] = f2tf32(v.y);
                Ash[lr][lc + i*4 + 2] = f2tf32(v.z);
                Ash[lr][lc + i*4 + 3] = f2tf32(v.w);
            }
        } else {
#pragma unroll
            for (int i = 0; i < 16; i++) Ash[lr][lc + i] = 0u;
        }
        {
            const float* bp = B + (size_t)(k0 + kb)*ldb + n0 + cb;
#pragma unroll
            for (int i = 0; i < 4; i++) {
                float4 v = *(const float4*)(bp + i*4);
                Bsh[kb][cb + i*4 + 0] = f2tf32(v.x);
                Bsh[kb][cb + i*4 + 1] = f2tf32(v.y);
                Bsh[kb][cb + i*4 + 2] = f2tf32(v.z);
                Bsh[kb][cb + i*4 + 3] = f2tf32(v.w);
            }
        }
        __syncthreads();
#pragma unroll
        for (int kq = 0; kq < 4; kq++) {
            const int kc = kq * 8;
            uint32_t b0[8], b1[8];
#pragma unroll
            for (int nt = 0; nt < 8; nt++) {
                int colB = Nb + nt*8 + lg;
                b0[nt] = Bsh[kc + lt][colB];
                b1[nt] = Bsh[kc + 4 + lt][colB];
            }
#pragma unroll
            for (int mt = 0; mt < 2; mt++) {
                int rb = Mb + mt*16;
                uint32_t a0 = Ash[rb + lg    ][kc + lt];
                uint32_t a1 = Ash[rb + 8 + lg][kc + lt];
                uint32_t a2 = Ash[rb + lg    ][kc + 4 + lt];
                uint32_t a3 = Ash[rb + 8 + lg][kc + 4 + lt];
#pragma unroll
                for (int nt = 0; nt < 8; nt++)
                    mma_tf32(acc[mt][nt], a0, a1, a2, a3, b0[nt], b1[nt]);
            }
        }
        __syncthreads();
    }

#pragma unroll
    for (int mt = 0; mt < 2; mt++) {
        int r0 = m0 + Mb + mt*16 + lg;
#pragma unroll
        for (int nt = 0; nt < 8; nt++) {
            int cg = n0 + Nb + nt*8 + 2*lt;
            float2 bb = (MODE == 3) ? make_float2(0.0f, 0.0f)
                                    : *(const float2*)(bias + cg);
#pragma unroll
            for (int hrow = 0; hrow < 2; hrow++) {
                int m = r0 + hrow*8;
                if (m >= M) continue;
                float cx = acc[mt][nt][hrow*2 + 0] + bb.x;
                float cy = acc[mt][nt][hrow*2 + 1] + bb.y;
                if (MODE == 1) { cx = gelu_erf(cx); cy = gelu_erf(cy); }
                if (MODE == 2) {
                    float2 rr = *(const float2*)(res + (size_t)m*ldr + cg);
                    cx += rr.x; cy += rr.y;
                }
                *(float2*)(Co + (size_t)m*ldc + cg) = make_float2(cx, cy);
            }
        }
    }
}

// ---------------- fused attention: single edge pass ----------------
// warp per edge; lane t handles channels [t*4, t*4+4), head hh = t>>2.
// alpha_h = dot(q[dst], k[src]+e)/4 reduced over the 4 lanes of each head.
// pe = exp(alpha) (no max-shift: softmax is shift-invariant; |alpha| is O(1) here).
// Accumulate UNNORMALIZED agg += pe*(v+e) and denom += pe; normalization in k_node_post.
__global__ void k_attn(const int* __restrict__ src, const int* __restrict__ dst) {
    int idx = blockIdx.x * blockDim.x + threadIdx.x;   // EE*32
    int e = idx >> 5, t = idx & 31;
    int s = src[e], d = dst[e];
    int c = t * 4;
    float4 q  = *(const float4*)(g_qkvs + (size_t)d*512 + c);
    float4 k  = *(const float4*)(g_qkvs + (size_t)s*512 + 128 + c);
    float4 v  = *(const float4*)(g_qkvs + (size_t)s*512 + 256 + c);
    float4 ev = *(const float4*)(g_eproj + (size_t)e*128 + c);
    float part = q.x*(k.x+ev.x) + q.y*(k.y+ev.y) + q.z*(k.z+ev.z) + q.w*(k.w+ev.w);
    part += __shfl_xor_sync(0xffffffffu, part, 1);
    part += __shfl_xor_sync(0xffffffffu, part, 2);
    float pe = expf(part * 0.25f);
    float m0 = pe*(v.x+ev.x), m1 = pe*(v.y+ev.y);
    float m2 = pe*(v.z+ev.z), m3 = pe*(v.w+ev.w);
    float* o = g_agg + (size_t)d*128 + c;
    asm volatile("red.global.add.v4.f32 [%0], {%1,%2,%3,%4};"
                 :: "l"(o), "f"(m0), "f"(m1), "f"(m2), "f"(m3) : "memory");
    if ((t & 3) == 0) {
        float* dn = g_denom + (size_t)d*NH + (t >> 2);
        asm volatile("red.global.add.f32 [%0], %1;" :: "l"(dn), "f"(pe) : "memory");
    }
}

// ---------------- edge update: tf32 mma.sync gather-GEMM + fused gate+LN ----------------
constexpr int EDGE_SMEM = 128*132*4;

__global__ void __launch_bounds__(256, 2)
k_edge_mma(const int* __restrict__ src, const int* __restrict__ dst,
           const float* __restrict__ ea,
           const float* __restrict__ W, const float* __restrict__ bvec,
           const float* __restrict__ eg, const float* __restrict__ ebias,
           float* __restrict__ out) {
    extern __shared__ float sm[];
    uint32_t (*Ash)[ALD] = (uint32_t(*)[ALD])sm;
    uint32_t (*Bsh)[BLD] = (uint32_t(*)[BLD])(sm + 128*ALD);
    float    (*raw)[132] = (float(*)[132])sm;
    __shared__ int sidx[128], didx[128];

    const int tid  = threadIdx.x;
    const int warp = tid >> 5, lane = tid & 31;
    const int e0 = blockIdx.x * 128;
    if (tid < 128) { sidx[tid] = src[e0+tid]; didx[tid] = dst[e0+tid]; }
    __syncthreads();

    const int wm = warp >> 1, wn = warp & 1;
    const int Mb = wm * 32, Nb = wn * 64;
    const int lg = lane >> 2, lt = lane & 3;
    const int lr = tid >> 1, lc = (tid & 1) * 16;
    const int kb = tid >> 3, cb = (tid & 7) * 16;

    float acc[2][8][4] = {};

    for (int c = 0; c < 10; c++) {
        const int k0 = c * 32;
        {
            const float* base; int col;
            if (k0 < 128)      { base = g_xn + (size_t)sidx[lr]*128; col = k0 + lc; }
            else if (k0 < 256) { base = g_xn + (size_t)didx[lr]*128; col = k0 - 128 + lc; }
            else               { base = ea + (size_t)(e0+lr)*64;     col = k0 - 256 + lc; }
#pragma unroll
            for (int i = 0; i < 4; i++) {
                float4 v = *(const float4*)(base + col + i*4);
                Ash[lr][lc + i*4 + 0] = f2tf32(v.x);
                Ash[lr][lc + i*4 + 1] = f2tf32(v.y);
                Ash[lr][lc + i*4 + 2] = f2tf32(v.z);
                Ash[lr][lc + i*4 + 3] = f2tf32(v.w);
            }
        }
        {
            const float* bp = W + (size_t)(k0 + kb)*128 + cb;
#pragma unroll
            for (int i = 0; i < 4; i++) {
                float4 v = *(const float4*)(bp + i*4);
                Bsh[kb][cb + i*4 + 0] = f2tf32(v.x);
                Bsh[kb][cb + i*4 + 1] = f2tf32(v.y);
                Bsh[kb][cb + i*4 + 2] = f2tf32(v.z);
                Bsh[kb][cb + i*4 + 3] = f2tf32(v.w);
            }
        }
        __syncthreads();

#pragma unroll
        for (int kq = 0; kq < 4; kq++) {
            const int kc = kq * 8;
            uint32_t b0[8], b1[8];
#pragma unroll
            for (int nt = 0; nt < 8; nt++) {
                int colB = Nb + nt*8 + lg;
                b0[nt] = Bsh[kc + lt][colB];
                b1[nt] = Bsh[kc + 4 + lt][colB];
            }
#pragma unroll
            for (int mt = 0; mt < 2; mt++) {
                int rb = Mb + mt*16;
                uint32_t a0 = Ash[rb + lg    ][kc + lt];
                uint32_t a1 = Ash[rb + 8 + lg][kc + lt];
                uint32_t a2 = Ash[rb + lg    ][kc + 4 + lt];
                uint32_t a3 = Ash[rb + 8 + lg][kc + 4 + lt];
#pragma unroll
                for (int nt = 0; nt < 8; nt++)
                    mma_tf32(acc[mt][nt], a0, a1, a2, a3, b0[nt], b1[nt]);
            }
        }
        __syncthreads();
    }

#pragma unroll
    for (int mt = 0; mt < 2; mt++) {
        int r0 = Mb + mt*16 + lg;
#pragma unroll
        for (int nt = 0; nt < 8; nt++) {
            int c0 = Nb + nt*8 + 2*lt;
            float2 bb = *(const float2*)(bvec + c0);
            *(float2*)&raw[r0][c0] =
                make_float2(fmaxf(acc[mt][nt][0] + bb.x, 0.0f),
                            fmaxf(acc[mt][nt][1] + bb.y, 0.0f));
            *(float2*)&raw[r0 + 8][c0] =
                make_float2(fmaxf(acc[mt][nt][2] + bb.x, 0.0f),
                            fmaxf(acc[mt][nt][3] + bb.y, 0.0f));
        }
    }
    __syncthreads();

#pragma unroll
    for (int half = 0; half < 2; half++) {
        int r = (tid >> 2) + half * 64;
        int q = tid & 3;
        float t[16]; float s = 0.0f;
#pragma unroll
        for (int i4 = 0; i4 < 16; i4 += 4) {
            int cc = q*16 + i4;
            float4 e4 = *(const float4*)(ea + (size_t)(e0+r)*64 + cc);
            t[i4+0] = e4.x + raw[r][cc+0] / (1.0f + expf(-raw[r][64+cc+0]));
            t[i4+1] = e4.y + raw[r][cc+1] / (1.0f + expf(-raw[r][64+cc+1]));
            t[i4+2] = e4.z + raw[r][cc+2] / (1.0f + expf(-raw[r][64+cc+2]));
            t[i4+3] = e4.w + raw[r][cc+3] / (1.0f + expf(-raw[r][64+cc+3]));
            s += t[i4+0] + t[i4+1] + t[i4+2] + t[i4+3];
        }
        s += __shfl_xor_sync(0xffffffffu, s, 1);
        s += __shfl_xor_sync(0xffffffffu, s, 2);
        float m = s * (1.0f/64.0f);
        float vs = 0.0f;
#pragma unroll
        for (int i = 0; i < 16; i++) { float dd = t[i] - m; vs += dd*dd; }
        vs += __shfl_xor_sync(0xffffffffu, vs, 1);
        vs += __shfl_xor_sync(0xffffffffu, vs, 2);
        float inv = rsqrtf(vs * (1.0f/64.0f) + 1e-5f);
#pragma unroll
        for (int i4 = 0; i4 < 16; i4 += 4) {
            int cc = q*16 + i4;
            float4 gv = *(const float4*)(eg + cc);
            float4 bb = *(const float4*)(ebias + cc);
            *(float4*)(out + (size_t)(e0+r)*64 + cc) =
                make_float4((t[i4+0]-m)*inv*gv.x+bb.x, (t[i4+1]-m)*inv*gv.y+bb.y,
                            (t[i4+2]-m)*inv*gv.z+bb.z, (t[i4+3]-m)*inv*gv.w+bb.w);
        }
    }
}

// ---------------- launcher ----------------
extern "C" void kernel_launch(void* const* d_in, const int* in_sizes, int n_in,
                              void* d_out, int out_size) {
    const float* x     = (const float*)d_in[0];
    const int*   ei    = (const int*)  d_in[1];
    const float* ea    = (const float*)d_in[2];
    const float* demb  = (const float*)d_in[3];
    const float* ng    = (const float*)d_in[4];
    const float* nbv   = (const float*)d_in[5];
    const float* Wq    = (const float*)d_in[6];
    const float* bq    = (const float*)d_in[7];
    const float* Wk    = (const float*)d_in[8];
    const float* bk    = (const float*)d_in[9];
    const float* Wv    = (const float*)d_in[10];
    const float* bv    = (const float*)d_in[11];
    const float* We    = (const float*)d_in[12];
    const float* Wskip = (const float*)d_in[13];
    const float* bskip = (const float*)d_in[14];
    const float* W1    = (const float*)d_in[15];
    const float* b1    = (const float*)d_in[16];
    const float* W2    = (const float*)d_in[17];
    const float* b2    = (const float*)d_in[18];
    const float* eung  = (const float*)d_in[19];
    const float* eunb  = (const float*)d_in[20];
    const float* euW   = (const float*)d_in[21];
    const float* eub   = (const float*)d_in[22];
    const float* eueg  = (const float*)d_in[23];
    const float* eueb  = (const float*)d_in[24];
    float* out = (float*)d_out;

    const int* src = ei;
    const int* dst = ei + EE;

    static float *p_h = nullptr, *p_qkvs = nullptr, *p_eproj = nullptr,
                 *p_h2 = nullptr, *p_ffn1 = nullptr, *p_xattn = nullptr,
                 *p_W4 = nullptr, *p_b4 = nullptr;
    static bool inited = false;
    if (!inited) {
        cudaGetSymbolAddress((void**)&p_h,     g_h);
        cudaGetSymbolAddress((void**)&p_qkvs,  g_qkvs);
        cudaGetSymbolAddress((void**)&p_eproj, g_eproj);
        cudaGetSymbolAddress((void**)&p_h2,    g_h2);
        cudaGetSymbolAddress((void**)&p_ffn1,  g_ffn1);
        cudaGetSymbolAddress((void**)&p_xattn, g_xattn);
        cudaGetSymbolAddress((void**)&p_W4,    g_W4);
        cudaGetSymbolAddress((void**)&p_b4,    g_b4);
        cudaFuncSetAttribute(k_edge_mma, cudaFuncAttributeMaxDynamicSharedMemorySize, EDGE_SMEM);
        inited = true;
    }

    const int MB = (NN + 127) / 128;   // 391

    k_init<<<2048, 256>>>();
    k_deg<<<(EE + 255)/256, 256>>>(src);
    k_pack<<<64, 256>>>(Wq, Wk, Wv, Wskip, bq, bk, bv, bskip);
    k_node_prep<<<(NN + 7)/8, 256>>>(x, demb, ng, nbv);

    // fused QKV+skip: [50000x128] @ [128x512]  (tf32 mma)
    k_gemm_mma<0><<<dim3(4, MB), 256>>>(p_h, 128, p_W4, 512, p_b4, p_qkvs, 512,
                                        nullptr, 0, NN, 128);
    // edge proj: [800000x64] @ [64x128]  (tf32 mma, no bias)
    k_gemm_mma<3><<<dim3(1, EE/128), 256>>>(ea, 64, We, 128, nullptr, p_eproj, 128,
                                            nullptr, 0, EE, 64);

    // single fused attention pass (unnormalized agg + denom)
    k_attn<<<(EE*32)/256, 256>>>(src, dst);

    k_node_post<<<(NN + 7)/8, 256>>>(ng, nbv);

    // FFN (tf32 mma)
    k_gemm_mma<1><<<dim3(4, MB), 256>>>(p_h2, 128, W1, 512, b1, p_ffn1, 512,
                                        nullptr, 0, NN, 128);
    k_gemm_mma<2><<<dim3(1, MB), 256>>>(p_ffn1, 512, W2, 128, b2, out, 128,
                                        p_xattn, 128, NN, 512);

    k_xn<<<(NN + 7)/8, 256>>>(out, eung, eunb);
    k_edge_mma<<<EE/128, 256, EDGE_SMEM>>>(src, dst, ea, euW, eub, eueg, eueb,
                                           out + (size_t)NN*DIM);
}

// round 9
// speedup vs baseline: 2.2080x; 1.0324x over previous
#include <cuda_runtime.h>
#include <math.h>
#include <stdint.h>

// ---------------- problem constants ----------------
constexpr int NN   = 50000;
constexpr int EE   = 800000;
constexpr int DIM  = 128;
constexpr int NH   = 8;
constexpr int HID  = 512;
constexpr int KEU  = 320;

// ---------------- scratch ----------------
__device__ float g_xin  [(size_t)NN*DIM];
__device__ float g_h    [(size_t)NN*DIM];
__device__ float g_qkvs [(size_t)NN*4*DIM];   // q[0:128) k[128:256) v[256:384) skip[384:512)
__device__ float g_denom[(size_t)NN*NH];
__device__ float g_agg  [(size_t)NN*DIM];     // UNNORMALIZED sum of pe*(v+e)
__device__ float g_xattn[(size_t)NN*DIM];
__device__ float g_h2   [(size_t)NN*DIM];
__device__ float g_ffn1 [(size_t)NN*HID];
__device__ float g_xn   [(size_t)NN*DIM];
__device__ float g_W4   [(size_t)DIM*512];
__device__ float g_b4   [512];
__device__ int   g_deg  [NN];

// ---------------- helpers ----------------
__device__ __forceinline__ float warp_sum(float v) {
#pragma unroll
    for (int o = 16; o > 0; o >>= 1) v += __shfl_xor_sync(0xffffffffu, v, o);
    return v;
}
__device__ __forceinline__ uint32_t f2tf32(float f) {
    uint32_t r;
    asm("cvt.rna.tf32.f32 %0, %1;" : "=r"(r) : "f"(f));
    return r;
}
__device__ __forceinline__ void mma_tf32(float* c,
                                         uint32_t a0, uint32_t a1, uint32_t a2, uint32_t a3,
                                         uint32_t b0, uint32_t b1) {
    asm volatile("mma.sync.aligned.m16n8k8.row.col.f32.tf32.tf32.f32 "
                 "{%0,%1,%2,%3}, {%4,%5,%6,%7}, {%8,%9}, {%0,%1,%2,%3};"
                 : "+f"(c[0]), "+f"(c[1]), "+f"(c[2]), "+f"(c[3])
                 : "r"(a0), "r"(a1), "r"(a2), "r"(a3), "r"(b0), "r"(b1));
}
__device__ __forceinline__ float gelu_erf(float v) {
    return 0.5f * v * (1.0f + erff(v * 0.70710678118654752f));
}

// ---------------- init / degree ----------------
__global__ void k_init() {
    int i  = blockIdx.x * blockDim.x + threadIdx.x;
    int st = gridDim.x * blockDim.x;
    for (int j = i; j < NN*DIM; j += st) g_agg[j] = 0.0f;
    for (int j = i; j < NN*NH;  j += st) g_denom[j] = 0.0f;
    for (int j = i; j < NN;     j += st) g_deg[j] = 0;
}
__global__ void k_deg(const int* __restrict__ src) {
    int i = blockIdx.x * blockDim.x + threadIdx.x;
    if (i < EE) atomicAdd(&g_deg[src[i]], 1);
}
__global__ void k_pack(const float* __restrict__ Wq, const float* __restrict__ Wk,
                       const float* __restrict__ Wv, const float* __restrict__ Ws,
                       const float* __restrict__ bq, const float* __restrict__ bk,
                       const float* __restrict__ bv, const float* __restrict__ bs) {
    int i = blockIdx.x * blockDim.x + threadIdx.x;
    if (i < DIM*DIM) {
        int r = i >> 7, c = i & 127;
        g_W4[(size_t)r*512 +       c] = Wq[i];
        g_W4[(size_t)r*512 + 128 + c] = Wk[i];
        g_W4[(size_t)r*512 + 256 + c] = Wv[i];
        g_W4[(size_t)r*512 + 384 + c] = Ws[i];
    }
    if (i < 128) {
        g_b4[i] = bq[i]; g_b4[128+i] = bk[i]; g_b4[256+i] = bv[i]; g_b4[384+i] = bs[i];
    }
}

// ---------------- fused LN kernels ----------------
__global__ void k_node_prep(const float* __restrict__ x, const float* __restrict__ demb,
                            const float* __restrict__ g, const float* __restrict__ b) {
    int row = blockIdx.x * 8 + (threadIdx.x >> 5);
    if (row >= NN) return;
    int lane = threadIdx.x & 31;
    int d = g_deg[row]; if (d > 255) d = 255;
    float4 xv = *(const float4*)(x + (size_t)row*DIM + lane*4);
    float4 dv = *(const float4*)(demb + (size_t)d*DIM + lane*4);
    float4 xi = make_float4(xv.x+dv.x, xv.y+dv.y, xv.z+dv.z, xv.w+dv.w);
    *(float4*)(g_xin + (size_t)row*DIM + lane*4) = xi;
    float m = warp_sum(xi.x+xi.y+xi.z+xi.w) * (1.0f/128.0f);
    float4 dd = make_float4(xi.x-m, xi.y-m, xi.z-m, xi.w-m);
    float var = warp_sum(dd.x*dd.x+dd.y*dd.y+dd.z*dd.z+dd.w*dd.w) * (1.0f/128.0f);
    float inv = rsqrtf(var + 1e-5f);
    float4 gv = *(const float4*)(g + lane*4);
    float4 bv = *(const float4*)(b + lane*4);
    *(float4*)(g_h + (size_t)row*DIM + lane*4) =
        make_float4(dd.x*inv*gv.x+bv.x, dd.y*inv*gv.y+bv.y, dd.z*inv*gv.z+bv.z, dd.w*inv*gv.w+bv.w);
}

// x_attn = x_in + agg/denom + skip; h2 = LN(x_attn)
__global__ void k_node_post(const float* __restrict__ g, const float* __restrict__ b) {
    int row = blockIdx.x * 8 + (threadIdx.x >> 5);
    if (row >= NN) return;
    int lane = threadIdx.x & 31;
    float dn = g_denom[(size_t)row*NH + (lane >> 2)];
    float rd = (dn != 0.0f) ? (1.0f / dn) : 0.0f;
    float4 xi = *(const float4*)(g_xin + (size_t)row*DIM + lane*4);
    float4 ag = *(const float4*)(g_agg + (size_t)row*DIM + lane*4);
    float4 sk = *(const float4*)(g_qkvs + (size_t)row*512 + 384 + lane*4);
    float4 xa = make_float4(xi.x+ag.x*rd+sk.x, xi.y+ag.y*rd+sk.y,
                            xi.z+ag.z*rd+sk.z, xi.w+ag.w*rd+sk.w);
    *(float4*)(g_xattn + (size_t)row*DIM + lane*4) = xa;
    float m = warp_sum(xa.x+xa.y+xa.z+xa.w) * (1.0f/128.0f);
    float4 dd = make_float4(xa.x-m, xa.y-m, xa.z-m, xa.w-m);
    float var = warp_sum(dd.x*dd.x+dd.y*dd.y+dd.z*dd.z+dd.w*dd.w) * (1.0f/128.0f);
    float inv = rsqrtf(var + 1e-5f);
    float4 gv = *(const float4*)(g + lane*4);
    float4 bv = *(const float4*)(b + lane*4);
    *(float4*)(g_h2 + (size_t)row*DIM + lane*4) =
        make_float4(dd.x*inv*gv.x+bv.x, dd.y*inv*gv.y+bv.y, dd.z*inv*gv.z+bv.z, dd.w*inv*gv.w+bv.w);
}

__global__ void k_xn(const float* __restrict__ xnew,
                     const float* __restrict__ g, const float* __restrict__ b) {
    int row = blockIdx.x * 8 + (threadIdx.x >> 5);
    if (row >= NN) return;
    int lane = threadIdx.x & 31;
    float4 xv = *(const float4*)(xnew + (size_t)row*DIM + lane*4);
    float m = warp_sum(xv.x+xv.y+xv.z+xv.w) * (1.0f/128.0f);
    float4 dd = make_float4(xv.x-m, xv.y-m, xv.z-m, xv.w-m);
    float var = warp_sum(dd.x*dd.x+dd.y*dd.y+dd.z*dd.z+dd.w*dd.w) * (1.0f/128.0f);
    float inv = rsqrtf(var + 1e-5f);
    float4 gv = *(const float4*)(g + lane*4);
    float4 bv = *(const float4*)(b + lane*4);
    *(float4*)(g_xn + (size_t)row*DIM + lane*4) =
        make_float4(dd.x*inv*gv.x+bv.x, dd.y*inv*gv.y+bv.y, dd.z*inv*gv.z+bv.z, dd.w*inv*gv.w+bv.w);
}

// ---------------- generic tf32 mma GEMM: 128x128 tile, K chunks of 32 ----------------
// MODE 0: +bias. MODE 1: +bias, GELU. MODE 2: +bias +res. MODE 3: plain.
constexpr int ALD = 36;
constexpr int BLD = 136;

template<int MODE>
__global__ void __launch_bounds__(256, 2)
k_gemm_mma(const float* __restrict__ A, int lda,
           const float* __restrict__ B, int ldb,
           const float* __restrict__ bias,
           float* __restrict__ Co, int ldc,
           const float* __restrict__ res, int ldr,
           int M, int K) {
    __shared__ uint32_t Ash[128][ALD];
    __shared__ uint32_t Bsh[32][BLD];
    const int m0 = blockIdx.y * 128, n0 = blockIdx.x * 128;
    const int tid = threadIdx.x;
    const int warp = tid >> 5, lane = tid & 31;
    const int wm = warp >> 1, wn = warp & 1;
    const int Mb = wm * 32, Nb = wn * 64;
    const int lg = lane >> 2, lt = lane & 3;
    const int lr = tid >> 1, lc = (tid & 1) * 16;
    const int kb = tid >> 3, cb = (tid & 7) * 16;
    float acc[2][8][4] = {};

    for (int k0 = 0; k0 < K; k0 += 32) {
        if (m0 + lr < M) {
            const float* ap = A + (size_t)(m0 + lr)*lda + k0 + lc;
#pragma unroll
            for (int i = 0; i < 4; i++) {
                float4 v = *(const float4*)(ap + i*4);
                Ash[lr][lc + i*4 + 0] = f2tf32(v.x);
                Ash[lr][lc + i*4 + 1] = f2tf32(v.y);
                Ash[lr][lc + i*4 + 2] = f2tf32(v.z);
                Ash[lr][lc + i*4 + 3] = f2tf32(v.w);
            }
        } else {
#pragma unroll
            for (int i = 0; i < 16; i++) Ash[lr][lc + i] = 0u;
        }
        {
            const float* bp = B + (size_t)(k0 + kb)*ldb + n0 + cb;
#pragma unroll
            for (int i = 0; i < 4; i++) {
                float4 v = *(const float4*)(bp + i*4);
                Bsh[kb][cb + i*4 + 0] = f2tf32(v.x);
                Bsh[kb][cb + i*4 + 1] = f2tf32(v.y);
                Bsh[kb][cb + i*4 + 2] = f2tf32(v.z);
                Bsh[kb][cb + i*4 + 3] = f2tf32(v.w);
            }
        }
        __syncthreads();
#pragma unroll
        for (int kq = 0; kq < 4; kq++) {
            const int kc = kq * 8;
            uint32_t b0[8], b1[8];
#pragma unroll
            for (int nt = 0; nt < 8; nt++) {
                int colB = Nb + nt*8 + lg;
                b0[nt] = Bsh[kc + lt][colB];
                b1[nt] = Bsh[kc + 4 + lt][colB];
            }
#pragma unroll
            for (int mt = 0; mt < 2; mt++) {
                int rb = Mb + mt*16;
                uint32_t a0 = Ash[rb + lg    ][kc + lt];
                uint32_t a1 = Ash[rb + 8 + lg][kc + lt];
                uint32_t a2 = Ash[rb + lg    ][kc + 4 + lt];
                uint32_t a3 = Ash[rb + 8 + lg][kc + 4 + lt];
#pragma unroll
                for (int nt = 0; nt < 8; nt++)
                    mma_tf32(acc[mt][nt], a0, a1, a2, a3, b0[nt], b1[nt]);
            }
        }
        __syncthreads();
    }

#pragma unroll
    for (int mt = 0; mt < 2; mt++) {
        int r0 = m0 + Mb + mt*16 + lg;
#pragma unroll
        for (int nt = 0; nt < 8; nt++) {
            int cg = n0 + Nb + nt*8 + 2*lt;
            float2 bb = (MODE == 3) ? make_float2(0.0f, 0.0f)
                                    : *(const float2*)(bias + cg);
#pragma unroll
            for (int hrow = 0; hrow < 2; hrow++) {
                int m = r0 + hrow*8;
                if (m >= M) continue;
                float cx = acc[mt][nt][hrow*2 + 0] + bb.x;
                float cy = acc[mt][nt][hrow*2 + 1] + bb.y;
                if (MODE == 1) { cx = gelu_erf(cx); cy = gelu_erf(cy); }
                if (MODE == 2) {
                    float2 rr = *(const float2*)(res + (size_t)m*ldr + cg);
                    cx += rr.x; cy += rr.y;
                }
                *(float2*)(Co + (size_t)m*ldc + cg) = make_float2(cx, cy);
            }
        }
    }
}

// ---------------- fused edge-proj + attention ----------------
// Phase 1: e-tile [128 edges x 128] = ea[e0:e0+128, 0:64] @ We (tf32 mma, K=64).
// Phase 2: e-tile kept in smem; warp-per-edge attention (16 edges/warp):
//   pe = exp(dot(q[dst], k[src]+e)/4); red agg += pe*(v+e); red denom += pe.
constexpr int EATTN_SMEM = 128*132*4;  // e-tile overlay dominates (67584 B)

__global__ void __launch_bounds__(256, 2)
k_eattn(const int* __restrict__ src, const int* __restrict__ dst,
        const float* __restrict__ ea, const float* __restrict__ We) {
    extern __shared__ float sm[];
    uint32_t (*Ash)[ALD] = (uint32_t(*)[ALD])sm;               // 128 x 36
    uint32_t (*Bsh)[BLD] = (uint32_t(*)[BLD])(sm + 128*ALD);   // 32 x 136
    float    (*et)[132]  = (float(*)[132])sm;                  // overlay after mainloop
    __shared__ int sidx[128], didx[128];

    const int tid  = threadIdx.x;
    const int warp = tid >> 5, lane = tid & 31;
    const int e0 = blockIdx.x * 128;
    if (tid < 128) { sidx[tid] = src[e0+tid]; didx[tid] = dst[e0+tid]; }
    __syncthreads();

    const int wm = warp >> 1, wn = warp & 1;
    const int Mb = wm * 32, Nb = wn * 64;
    const int lg = lane >> 2, lt = lane & 3;
    const int lr = tid >> 1, lc = (tid & 1) * 16;
    const int kb = tid >> 3, cb = (tid & 7) * 16;

    float acc[2][8][4] = {};

    // e-tile GEMM: K=64, 2 chunks of 32
#pragma unroll
    for (int c = 0; c < 2; c++) {
        const int k0 = c * 32;
        {
            const float* ap = ea + (size_t)(e0 + lr)*64 + k0 + lc;
#pragma unroll
            for (int i = 0; i < 4; i++) {
                float4 v = *(const float4*)(ap + i*4);
                Ash[lr][lc + i*4 + 0] = f2tf32(v.x);
                Ash[lr][lc + i*4 + 1] = f2tf32(v.y);
                Ash[lr][lc + i*4 + 2] = f2tf32(v.z);
                Ash[lr][lc + i*4 + 3] = f2tf32(v.w);
            }
        }
        {
            const float* bp = We + (size_t)(k0 + kb)*128 + cb;
#pragma unroll
            for (int i = 0; i < 4; i++) {
                float4 v = *(const float4*)(bp + i*4);
                Bsh[kb][cb + i*4 + 0] = f2tf32(v.x);
                Bsh[kb][cb + i*4 + 1] = f2tf32(v.y);
                Bsh[kb][cb + i*4 + 2] = f2tf32(v.z);
                Bsh[kb][cb + i*4 + 3] = f2tf32(v.w);
            }
        }
        __syncthreads();
#pragma unroll
        for (int kq = 0; kq < 4; kq++) {
            const int kc = kq * 8;
            uint32_t b0[8], b1[8];
#pragma unroll
            for (int nt = 0; nt < 8; nt++) {
                int colB = Nb + nt*8 + lg;
                b0[nt] = Bsh[kc + lt][colB];
                b1[nt] = Bsh[kc + 4 + lt][colB];
            }
#pragma unroll
            for (int mt = 0; mt < 2; mt++) {
                int rb = Mb + mt*16;
                uint32_t a0 = Ash[rb + lg    ][kc + lt];
                uint32_t a1 = Ash[rb + 8 + lg][kc + lt];
                uint32_t a2 = Ash[rb + lg    ][kc + 4 + lt];
                uint32_t a3 = Ash[rb + 8 + lg][kc + 4 + lt];
#pragma unroll
                for (int nt = 0; nt < 8; nt++)
                    mma_tf32(acc[mt][nt], a0, a1, a2, a3, b0[nt], b1[nt]);
            }
        }
        __syncthreads();
    }

    // write e-tile to smem overlay
#pragma unroll
    for (int mt = 0; mt < 2; mt++) {
        int r0 = Mb + mt*16 + lg;
#pragma unroll
        for (int nt = 0; nt < 8; nt++) {
            int c0 = Nb + nt*8 + 2*lt;
            *(float2*)&et[r0][c0]     = make_float2(acc[mt][nt][0], acc[mt][nt][1]);
            *(float2*)&et[r0 + 8][c0] = make_float2(acc[mt][nt][2], acc[mt][nt][3]);
        }
    }
    __syncthreads();

    // attention: warp-per-edge, 16 edges per warp
    const int c4 = lane * 4;
#pragma unroll 4
    for (int it = 0; it < 16; it++) {
        int el = warp * 16 + it;
        int s = sidx[el], d = didx[el];
        float4 q  = *(const float4*)(g_qkvs + (size_t)d*512 + c4);
        float4 k  = *(const float4*)(g_qkvs + (size_t)s*512 + 128 + c4);
        float4 v  = *(const float4*)(g_qkvs + (size_t)s*512 + 256 + c4);
        float4 ev = *(const float4*)&et[el][c4];
        float part = q.x*(k.x+ev.x) + q.y*(k.y+ev.y) + q.z*(k.z+ev.z) + q.w*(k.w+ev.w);
        part += __shfl_xor_sync(0xffffffffu, part, 1);
        part += __shfl_xor_sync(0xffffffffu, part, 2);
        float pe = expf(part * 0.25f);
        float m0 = pe*(v.x+ev.x), m1 = pe*(v.y+ev.y);
        float m2 = pe*(v.z+ev.z), m3 = pe*(v.w+ev.w);
        float* o = g_agg + (size_t)d*128 + c4;
        asm volatile("red.global.add.v4.f32 [%0], {%1,%2,%3,%4};"
                     :: "l"(o), "f"(m0), "f"(m1), "f"(m2), "f"(m3) : "memory");
        if ((lane & 3) == 0) {
            float* dn = g_denom + (size_t)d*NH + (lane >> 2);
            asm volatile("red.global.add.f32 [%0], %1;" :: "l"(dn), "f"(pe) : "memory");
        }
    }
}

// ---------------- edge update: tf32 mma.sync gather-GEMM + fused gate+LN ----------------
constexpr int EDGE_SMEM = 128*132*4;

__global__ void __launch_bounds__(256, 2)
k_edge_mma(const int* __restrict__ src, const int* __restrict__ dst,
           const float* __restrict__ ea,
           const float* __restrict__ W, const float* __restrict__ bvec,
           const float* __restrict__ eg, const float* __restrict__ ebias,
           float* __restrict__ out) {
    extern __shared__ float sm[];
    uint32_t (*Ash)[ALD] = (uint32_t(*)[ALD])sm;
    uint32_t (*Bsh)[BLD] = (uint32_t(*)[BLD])(sm + 128*ALD);
    float    (*raw)[132] = (float(*)[132])sm;
    __shared__ int sidx[128], didx[128];

    const int tid  = threadIdx.x;
    const int warp = tid >> 5, lane = tid & 31;
    const int e0 = blockIdx.x * 128;
    if (tid < 128) { sidx[tid] = src[e0+tid]; didx[tid] = dst[e0+tid]; }
    __syncthreads();

    const int wm = warp >> 1, wn = warp & 1;
    const int Mb = wm * 32, Nb = wn * 64;
    const int lg = lane >> 2, lt = lane & 3;
    const int lr = tid >> 1, lc = (tid & 1) * 16;
    const int kb = tid >> 3, cb = (tid & 7) * 16;

    float acc[2][8][4] = {};

    for (int c = 0; c < 10; c++) {
        const int k0 = c * 32;
        {
            const float* base; int col;
            if (k0 < 128)      { base = g_xn + (size_t)sidx[lr]*128; col = k0 + lc; }
            else if (k0 < 256) { base = g_xn + (size_t)didx[lr]*128; col = k0 - 128 + lc; }
            else               { base = ea + (size_t)(e0+lr)*64;     col = k0 - 256 + lc; }
#pragma unroll
            for (int i = 0; i < 4; i++) {
                float4 v = *(const float4*)(base + col + i*4);
                Ash[lr][lc + i*4 + 0] = f2tf32(v.x);
                Ash[lr][lc + i*4 + 1] = f2tf32(v.y);
                Ash[lr][lc + i*4 + 2] = f2tf32(v.z);
                Ash[lr][lc + i*4 + 3] = f2tf32(v.w);
            }
        }
        {
            const float* bp = W + (size_t)(k0 + kb)*128 + cb;
#pragma unroll
            for (int i = 0; i < 4; i++) {
                float4 v = *(const float4*)(bp + i*4);
                Bsh[kb][cb + i*4 + 0] = f2tf32(v.x);
                Bsh[kb][cb + i*4 + 1] = f2tf32(v.y);
                Bsh[kb][cb + i*4 + 2] = f2tf32(v.z);
                Bsh[kb][cb + i*4 + 3] = f2tf32(v.w);
            }
        }
        __syncthreads();

#pragma unroll
        for (int kq = 0; kq < 4; kq++) {
            const int kc = kq * 8;
            uint32_t b0[8], b1[8];
#pragma unroll
            for (int nt = 0; nt < 8; nt++) {
                int colB = Nb + nt*8 + lg;
                b0[nt] = Bsh[kc + lt][colB];
                b1[nt] = Bsh[kc + 4 + lt][colB];
            }
#pragma unroll
            for (int mt = 0; mt < 2; mt++) {
                int rb = Mb + mt*16;
                uint32_t a0 = Ash[rb + lg    ][kc + lt];
                uint32_t a1 = Ash[rb + 8 + lg][kc + lt];
                uint32_t a2 = Ash[rb + lg    ][kc + 4 + lt];
                uint32_t a3 = Ash[rb + 8 + lg][kc + 4 + lt];
#pragma unroll
                for (int nt = 0; nt < 8; nt++)
                    mma_tf32(acc[mt][nt], a0, a1, a2, a3, b0[nt], b1[nt]);
            }
        }
        __syncthreads();
    }

#pragma unroll
    for (int mt = 0; mt < 2; mt++) {
        int r0 = Mb + mt*16 + lg;
#pragma unroll
        for (int nt = 0; nt < 8; nt++) {
            int c0 = Nb + nt*8 + 2*lt;
            float2 bb = *(const float2*)(bvec + c0);
            *(float2*)&raw[r0][c0] =
                make_float2(fmaxf(acc[mt][nt][0] + bb.x, 0.0f),
                            fmaxf(acc[mt][nt][1] + bb.y, 0.0f));
            *(float2*)&raw[r0 + 8][c0] =
                make_float2(fmaxf(acc[mt][nt][2] + bb.x, 0.0f),
                            fmaxf(acc[mt][nt][3] + bb.y, 0.0f));
        }
    }
    __syncthreads();

#pragma unroll
    for (int half = 0; half < 2; half++) {
        int r = (tid >> 2) + half * 64;
        int q = tid & 3;
        float t[16]; float s = 0.0f;
#pragma unroll
        for (int i4 = 0; i4 < 16; i4 += 4) {
            int cc = q*16 + i4;
            float4 e4 = *(const float4*)(ea + (size_t)(e0+r)*64 + cc);
            t[i4+0] = e4.x + raw[r][cc+0] / (1.0f + expf(-raw[r][64+cc+0]));
            t[i4+1] = e4.y + raw[r][cc+1] / (1.0f + expf(-raw[r][64+cc+1]));
            t[i4+2] = e4.z + raw[r][cc+2] / (1.0f + expf(-raw[r][64+cc+2]));
            t[i4+3] = e4.w + raw[r][cc+3] / (1.0f + expf(-raw[r][64+cc+3]));
            s += t[i4+0] + t[i4+1] + t[i4+2] + t[i4+3];
        }
        s += __shfl_xor_sync(0xffffffffu, s, 1);
        s += __shfl_xor_sync(0xffffffffu, s, 2);
        float m = s * (1.0f/64.0f);
        float vs = 0.0f;
#pragma unroll
        for (int i = 0; i < 16; i++) { float dd = t[i] - m; vs += dd*dd; }
        vs += __shfl_xor_sync(0xffffffffu, vs, 1);
        vs += __shfl_xor_sync(0xffffffffu, vs, 2);
        float inv = rsqrtf(vs * (1.0f/64.0f) + 1e-5f);
#pragma unroll
        for (int i4 = 0; i4 < 16; i4 += 4) {
            int cc = q*16 + i4;
            float4 gv = *(const float4*)(eg + cc);
            float4 bb = *(const float4*)(ebias + cc);
            *(float4*)(out + (size_t)(e0+r)*64 + cc) =
                make_float4((t[i4+0]-m)*inv*gv.x+bb.x, (t[i4+1]-m)*inv*gv.y+bb.y,
                            (t[i4+2]-m)*inv*gv.z+bb.z, (t[i4+3]-m)*inv*gv.w+bb.w);
        }
    }
}

// ---------------- launcher ----------------
extern "C" void kernel_launch(void* const* d_in, const int* in_sizes, int n_in,
                              void* d_out, int out_size) {
    const float* x     = (const float*)d_in[0];
    const int*   ei    = (const int*)  d_in[1];
    const float* ea    = (const float*)d_in[2];
    const float* demb  = (const float*)d_in[3];
    const float* ng    = (const float*)d_in[4];
    const float* nbv   = (const float*)d_in[5];
    const float* Wq    = (const float*)d_in[6];
    const float* bq    = (const float*)d_in[7];
    const float* Wk    = (const float*)d_in[8];
    const float* bk    = (const float*)d_in[9];
    const float* Wv    = (const float*)d_in[10];
    const float* bv    = (const float*)d_in[11];
    const float* We    = (const float*)d_in[12];
    const float* Wskip = (const float*)d_in[13];
    const float* bskip = (const float*)d_in[14];
    const float* W1    = (const float*)d_in[15];
    const float* b1    = (const float*)d_in[16];
    const float* W2    = (const float*)d_in[17];
    const float* b2    = (const float*)d_in[18];
    const float* eung  = (const float*)d_in[19];
    const float* eunb  = (const float*)d_in[20];
    const float* euW   = (const float*)d_in[21];
    const float* eub   = (const float*)d_in[22];
    const float* eueg  = (const float*)d_in[23];
    const float* eueb  = (const float*)d_in[24];
    float* out = (float*)d_out;

    const int* src = ei;
    const int* dst = ei + EE;

    static float *p_h = nullptr, *p_qkvs = nullptr,
                 *p_h2 = nullptr, *p_ffn1 = nullptr, *p_xattn = nullptr,
                 *p_W4 = nullptr, *p_b4 = nullptr;
    static bool inited = false;
    if (!inited) {
        cudaGetSymbolAddress((void**)&p_h,     g_h);
        cudaGetSymbolAddress((void**)&p_qkvs,  g_qkvs);
        cudaGetSymbolAddress((void**)&p_h2,    g_h2);
        cudaGetSymbolAddress((void**)&p_ffn1,  g_ffn1);
        cudaGetSymbolAddress((void**)&p_xattn, g_xattn);
        cudaGetSymbolAddress((void**)&p_W4,    g_W4);
        cudaGetSymbolAddress((void**)&p_b4,    g_b4);
        cudaFuncSetAttribute(k_edge_mma, cudaFuncAttributeMaxDynamicSharedMemorySize, EDGE_SMEM);
        cudaFuncSetAttribute(k_eattn,    cudaFuncAttributeMaxDynamicSharedMemorySize, EATTN_SMEM);
        inited = true;
    }

    const int MB = (NN + 127) / 128;   // 391

    k_init<<<2048, 256>>>();
    k_deg<<<(EE + 255)/256, 256>>>(src);
    k_pack<<<64, 256>>>(Wq, Wk, Wv, Wskip, bq, bk, bv, bskip);
    k_node_prep<<<(NN + 7)/8, 256>>>(x, demb, ng, nbv);

    // fused QKV+skip: [50000x128] @ [128x512]  (tf32 mma)
    k_gemm_mma<0><<<dim3(4, MB), 256>>>(p_h, 128, p_W4, 512, p_b4, p_qkvs, 512,
                                        nullptr, 0, NN, 128);

    // fused edge-proj + attention (single pass; unnormalized agg + denom)
    k_eattn<<<EE/128, 256, EATTN_SMEM>>>(src, dst, ea, We);

    k_node_post<<<(NN + 7)/8, 256>>>(ng, nbv);

    // FFN (tf32 mma)
    k_gemm_mma<1><<<dim3(4, MB), 256>>>(p_h2, 128, W1, 512, b1, p_ffn1, 512,
                                        nullptr, 0, NN, 128);
    k_gemm_mma<2><<<dim3(1, MB), 256>>>(p_ffn1, 512, W2, 128, b2, out, 128,
                                        p_xattn, 128, NN, 512);

    k_xn<<<(NN + 7)/8, 256>>>(out, eung, eunb);
    k_edge_mma<<<EE/128, 256, EDGE_SMEM>>>(src, dst, ea, euW, eub, eueg, eueb,
                                           out + (size_t)NN*DIM);
}

// round 10
// speedup vs baseline: 2.4612x; 1.1147x over previous
#include <cuda_runtime.h>
#include <math.h>
#include <stdint.h>

// ---------------- problem constants ----------------
constexpr int NN   = 50000;
constexpr int EE   = 800000;
constexpr int DIM  = 128;
constexpr int NH   = 8;
constexpr int HID  = 512;

// ---------------- scratch ----------------
__device__ float g_xin  [(size_t)NN*DIM];
__device__ float g_h    [(size_t)NN*DIM];
__device__ float g_qkvs [(size_t)NN*4*DIM];   // q[0:128) k[128:256) v[256:384) skip[384:512)
__device__ float g_denom[(size_t)NN*NH];
__device__ float g_agg  [(size_t)NN*DIM];     // UNNORMALIZED sum of pe*(v+e)
__device__ float g_xattn[(size_t)NN*DIM];
__device__ float g_h2   [(size_t)NN*DIM];
__device__ float g_ffn1 [(size_t)NN*HID];
__device__ float g_xn   [(size_t)NN*DIM];
__device__ float g_W4   [(size_t)DIM*512];
__device__ float g_b4   [512];
__device__ int   g_deg  [NN];

// ---------------- helpers ----------------
__device__ __forceinline__ float warp_sum(float v) {
#pragma unroll
    for (int o = 16; o > 0; o >>= 1) v += __shfl_xor_sync(0xffffffffu, v, o);
    return v;
}
__device__ __forceinline__ void mma_tf32(float* c,
                                         uint32_t a0, uint32_t a1, uint32_t a2, uint32_t a3,
                                         uint32_t b0, uint32_t b1) {
    asm volatile("mma.sync.aligned.m16n8k8.row.col.f32.tf32.tf32.f32 "
                 "{%0,%1,%2,%3}, {%4,%5,%6,%7}, {%8,%9}, {%0,%1,%2,%3};"
                 : "+f"(c[0]), "+f"(c[1]), "+f"(c[2]), "+f"(c[3])
                 : "r"(a0), "r"(a1), "r"(a2), "r"(a3), "r"(b0), "r"(b1));
}
__device__ __forceinline__ float gelu_erf(float v) {
    return 0.5f * v * (1.0f + erff(v * 0.70710678118654752f));
}
__device__ __forceinline__ void cp16(uint32_t d, const float* g) {
    asm volatile("cp.async.cg.shared.global [%0], [%1], 16;" :: "r"(d), "l"(g) : "memory");
}
__device__ __forceinline__ void cp_commit() {
    asm volatile("cp.async.commit_group;" ::: "memory");
}
template<int N> __device__ __forceinline__ void cp_wait() {
    asm volatile("cp.async.wait_group %0;" :: "n"(N) : "memory");
}

// smem tile geometry (shared by all mma kernels)
constexpr int ALD = 36;    // A smem ld (mod 32 = 4 -> conflict-free frag reads)
constexpr int BLD = 136;   // B smem ld (mod 32 = 8)
constexpr int AOFF = 128*ALD;          // u32 units per A buffer (4608)
constexpr int BOFF = 32*BLD;           // u32 units per B buffer (4352)
constexpr int TILE_SMEM_U32 = 2*AOFF + 2*BOFF;   // 17920 u32 = 71680 B
constexpr int MMA_SMEM = TILE_SMEM_U32 * 4;       // 71680 B (overlays fit inside)

// ---------------- init / degree ----------------
__global__ void k_init() {
    int i  = blockIdx.x * blockDim.x + threadIdx.x;
    int st = gridDim.x * blockDim.x;
    for (int j = i; j < NN*DIM; j += st) g_agg[j] = 0.0f;
    for (int j = i; j < NN*NH;  j += st) g_denom[j] = 0.0f;
    for (int j = i; j < NN;     j += st) g_deg[j] = 0;
}
__global__ void k_deg(const int* __restrict__ src) {
    int i = blockIdx.x * blockDim.x + threadIdx.x;
    if (i < EE) atomicAdd(&g_deg[src[i]], 1);
}
__global__ void k_pack(const float* __restrict__ Wq, const float* __restrict__ Wk,
                       const float* __restrict__ Wv, const float* __restrict__ Ws,
                       const float* __restrict__ bq, const float* __restrict__ bk,
                       const float* __restrict__ bv, const float* __restrict__ bs) {
    int i = blockIdx.x * blockDim.x + threadIdx.x;
    if (i < DIM*DIM) {
        int r = i >> 7, c = i & 127;
        g_W4[(size_t)r*512 +       c] = Wq[i];
        g_W4[(size_t)r*512 + 128 + c] = Wk[i];
        g_W4[(size_t)r*512 + 256 + c] = Wv[i];
        g_W4[(size_t)r*512 + 384 + c] = Ws[i];
    }
    if (i < 128) {
        g_b4[i] = bq[i]; g_b4[128+i] = bk[i]; g_b4[256+i] = bv[i]; g_b4[384+i] = bs[i];
    }
}

// ---------------- fused LN kernels ----------------
__global__ void k_node_prep(const float* __restrict__ x, const float* __restrict__ demb,
                            const float* __restrict__ g, const float* __restrict__ b) {
    int row = blockIdx.x * 8 + (threadIdx.x >> 5);
    if (row >= NN) return;
    int lane = threadIdx.x & 31;
    int d = g_deg[row]; if (d > 255) d = 255;
    float4 xv = *(const float4*)(x + (size_t)row*DIM + lane*4);
    float4 dv = *(const float4*)(demb + (size_t)d*DIM + lane*4);
    float4 xi = make_float4(xv.x+dv.x, xv.y+dv.y, xv.z+dv.z, xv.w+dv.w);
    *(float4*)(g_xin + (size_t)row*DIM + lane*4) = xi;
    float m = warp_sum(xi.x+xi.y+xi.z+xi.w) * (1.0f/128.0f);
    float4 dd = make_float4(xi.x-m, xi.y-m, xi.z-m, xi.w-m);
    float var = warp_sum(dd.x*dd.x+dd.y*dd.y+dd.z*dd.z+dd.w*dd.w) * (1.0f/128.0f);
    float inv = rsqrtf(var + 1e-5f);
    float4 gv = *(const float4*)(g + lane*4);
    float4 bv = *(const float4*)(b + lane*4);
    *(float4*)(g_h + (size_t)row*DIM + lane*4) =
        make_float4(dd.x*inv*gv.x+bv.x, dd.y*inv*gv.y+bv.y, dd.z*inv*gv.z+bv.z, dd.w*inv*gv.w+bv.w);
}

// x_attn = x_in + agg/denom + skip; h2 = LN(x_attn)
__global__ void k_node_post(const float* __restrict__ g, const float* __restrict__ b) {
    int row = blockIdx.x * 8 + (threadIdx.x >> 5);
    if (row >= NN) return;
    int lane = threadIdx.x & 31;
    float dn = g_denom[(size_t)row*NH + (lane >> 2)];
    float rd = (dn != 0.0f) ? (1.0f / dn) : 0.0f;
    float4 xi = *(const float4*)(g_xin + (size_t)row*DIM + lane*4);
    float4 ag = *(const float4*)(g_agg + (size_t)row*DIM + lane*4);
    float4 sk = *(const float4*)(g_qkvs + (size_t)row*512 + 384 + lane*4);
    float4 xa = make_float4(xi.x+ag.x*rd+sk.x, xi.y+ag.y*rd+sk.y,
                            xi.z+ag.z*rd+sk.z, xi.w+ag.w*rd+sk.w);
    *(float4*)(g_xattn + (size_t)row*DIM + lane*4) = xa;
    float m = warp_sum(xa.x+xa.y+xa.z+xa.w) * (1.0f/128.0f);
    float4 dd = make_float4(xa.x-m, xa.y-m, xa.z-m, xa.w-m);
    float var = warp_sum(dd.x*dd.x+dd.y*dd.y+dd.z*dd.z+dd.w*dd.w) * (1.0f/128.0f);
    float inv = rsqrtf(var + 1e-5f);
    float4 gv = *(const float4*)(g + lane*4);
    float4 bv = *(const float4*)(b + lane*4);
    *(float4*)(g_h2 + (size_t)row*DIM + lane*4) =
        make_float4(dd.x*inv*gv.x+bv.x, dd.y*inv*gv.y+bv.y, dd.z*inv*gv.z+bv.z, dd.w*inv*gv.w+bv.w);
}

__global__ void k_xn(const float* __restrict__ xnew,
                     const float* __restrict__ g, const float* __restrict__ b) {
    int row = blockIdx.x * 8 + (threadIdx.x >> 5);
    if (row >= NN) return;
    int lane = threadIdx.x & 31;
    float4 xv = *(const float4*)(xnew + (size_t)row*DIM + lane*4);
    float m = warp_sum(xv.x+xv.y+xv.z+xv.w) * (1.0f/128.0f);
    float4 dd = make_float4(xv.x-m, xv.y-m, xv.z-m, xv.w-m);
    float var = warp_sum(dd.x*dd.x+dd.y*dd.y+dd.z*dd.z+dd.w*dd.w) * (1.0f/128.0f);
    float inv = rsqrtf(var + 1e-5f);
    float4 gv = *(const float4*)(g + lane*4);
    float4 bv = *(const float4*)(b + lane*4);
    *(float4*)(g_xn + (size_t)row*DIM + lane*4) =
        make_float4(dd.x*inv*gv.x+bv.x, dd.y*inv*gv.y+bv.y, dd.z*inv*gv.z+bv.z, dd.w*inv*gv.w+bv.w);
}

// ---------------- generic tf32 mma GEMM: 128x128 tile, cp.async double-buffered ----------------
// fp32 bits loaded raw; tensor core truncates mantissa (tf32). MODE 0:+bias 1:+bias,GELU 2:+bias+res.
template<int MODE>
__global__ void __launch_bounds__(256, 2)
k_gemm_mma(const float* __restrict__ A, int lda,
           const float* __restrict__ B, int ldb,
           const float* __restrict__ bias,
           float* __restrict__ Co, int ldc,
           const float* __restrict__ res, int ldr,
           int M, int K) {
    extern __shared__ uint32_t smu[];
    uint32_t (*Ab0)[ALD] = (uint32_t(*)[ALD])smu;
    uint32_t (*Ab1)[ALD] = (uint32_t(*)[ALD])(smu + AOFF);
    uint32_t (*Bb0)[BLD] = (uint32_t(*)[BLD])(smu + 2*AOFF);
    uint32_t (*Bb1)[BLD] = (uint32_t(*)[BLD])(smu + 2*AOFF + BOFF);

    const int m0 = blockIdx.y * 128, n0 = blockIdx.x * 128;
    const int tid = threadIdx.x;
    const int warp = tid >> 5, lane = tid & 31;
    const int wm = warp >> 1, wn = warp & 1;
    const int Mb = wm * 32, Nb = wn * 64;
    const int lg = lane >> 2, lt = lane & 3;
    const int lr = tid >> 1, lc = (tid & 1) * 16;
    const int kb = tid >> 3, cb = (tid & 7) * 16;

    const uint32_t aD[2] = { (uint32_t)__cvta_generic_to_shared(&Ab0[lr][lc]),
                             (uint32_t)__cvta_generic_to_shared(&Ab1[lr][lc]) };
    const uint32_t bD[2] = { (uint32_t)__cvta_generic_to_shared(&Bb0[kb][cb]),
                             (uint32_t)__cvta_generic_to_shared(&Bb1[kb][cb]) };
    const bool aIn = (m0 + lr) < M;

    auto issue = [&](int c, int buf) {
        int k0 = c * 32;
        if (aIn) {
            const float* ap = A + (size_t)(m0 + lr)*lda + k0 + lc;
#pragma unroll
            for (int i = 0; i < 4; i++) cp16(aD[buf] + i*16, ap + i*4);
        } else {
            uint32_t (*Ax)[ALD] = buf ? Ab1 : Ab0;
#pragma unroll
            for (int i = 0; i < 4; i++)
                *(float4*)&Ax[lr][lc + i*4] = make_float4(0,0,0,0);
        }
        const float* bp = B + (size_t)(k0 + kb)*ldb + n0 + cb;
#pragma unroll
        for (int i = 0; i < 4; i++) cp16(bD[buf] + i*16, bp + i*4);
        cp_commit();
    };

    float acc[2][8][4] = {};
    const int NC = K >> 5;
    issue(0, 0);
    for (int c = 0; c < NC; c++) {
        int cur = c & 1;
        if (c + 1 < NC) { issue(c+1, cur ^ 1); cp_wait<1>(); }
        else cp_wait<0>();
        __syncthreads();
        uint32_t (*Ac)[ALD] = cur ? Ab1 : Ab0;
        uint32_t (*Bc)[BLD] = cur ? Bb1 : Bb0;
#pragma unroll
        for (int kq = 0; kq < 4; kq++) {
            const int kc = kq * 8;
            uint32_t b0[8], b1[8];
#pragma unroll
            for (int nt = 0; nt < 8; nt++) {
                int colB = Nb + nt*8 + lg;
                b0[nt] = Bc[kc + lt][colB];
                b1[nt] = Bc[kc + 4 + lt][colB];
            }
#pragma unroll
            for (int mt = 0; mt < 2; mt++) {
                int rb = Mb + mt*16;
                uint32_t a0 = Ac[rb + lg    ][kc + lt];
                uint32_t a1 = Ac[rb + 8 + lg][kc + lt];
                uint32_t a2 = Ac[rb + lg    ][kc + 4 + lt];
                uint32_t a3 = Ac[rb + 8 + lg][kc + 4 + lt];
#pragma unroll
                for (int nt = 0; nt < 8; nt++)
                    mma_tf32(acc[mt][nt], a0, a1, a2, a3, b0[nt], b1[nt]);
            }
        }
        __syncthreads();
    }

#pragma unroll
    for (int mt = 0; mt < 2; mt++) {
        int r0 = m0 + Mb + mt*16 + lg;
#pragma unroll
        for (int nt = 0; nt < 8; nt++) {
            int cg = n0 + Nb + nt*8 + 2*lt;
            float2 bb = *(const float2*)(bias + cg);
#pragma unroll
            for (int hrow = 0; hrow < 2; hrow++) {
                int m = r0 + hrow*8;
                if (m >= M) continue;
                float cx = acc[mt][nt][hrow*2 + 0] + bb.x;
                float cy = acc[mt][nt][hrow*2 + 1] + bb.y;
                if (MODE == 1) { cx = gelu_erf(cx); cy = gelu_erf(cy); }
                if (MODE == 2) {
                    float2 rr = *(const float2*)(res + (size_t)m*ldr + cg);
                    cx += rr.x; cy += rr.y;
                }
                *(float2*)(Co + (size_t)m*ldc + cg) = make_float2(cx, cy);
            }
        }
    }
}

// ---------------- fused edge-proj + attention (cp.async double-buffered) ----------------
__global__ void __launch_bounds__(256, 2)
k_eattn(const int* __restrict__ src, const int* __restrict__ dst,
        const float* __restrict__ ea, const float* __restrict__ We) {
    extern __shared__ uint32_t smu[];
    uint32_t (*Ab0)[ALD] = (uint32_t(*)[ALD])smu;
    uint32_t (*Ab1)[ALD] = (uint32_t(*)[ALD])(smu + AOFF);
    uint32_t (*Bb0)[BLD] = (uint32_t(*)[BLD])(smu + 2*AOFF);
    uint32_t (*Bb1)[BLD] = (uint32_t(*)[BLD])(smu + 2*AOFF + BOFF);
    float    (*et)[132]  = (float(*)[132])smu;     // overlay after mainloop
    __shared__ int sidx[128], didx[128];

    const int tid  = threadIdx.x;
    const int warp = tid >> 5, lane = tid & 31;
    const int e0 = blockIdx.x * 128;
    if (tid < 128) { sidx[tid] = src[e0+tid]; didx[tid] = dst[e0+tid]; }
    __syncthreads();

    const int wm = warp >> 1, wn = warp & 1;
    const int Mb = wm * 32, Nb = wn * 64;
    const int lg = lane >> 2, lt = lane & 3;
    const int lr = tid >> 1, lc = (tid & 1) * 16;
    const int kb = tid >> 3, cb = (tid & 7) * 16;

    const uint32_t aD[2] = { (uint32_t)__cvta_generic_to_shared(&Ab0[lr][lc]),
                             (uint32_t)__cvta_generic_to_shared(&Ab1[lr][lc]) };
    const uint32_t bD[2] = { (uint32_t)__cvta_generic_to_shared(&Bb0[kb][cb]),
                             (uint32_t)__cvta_generic_to_shared(&Bb1[kb][cb]) };

    auto issue = [&](int c, int buf) {
        int k0 = c * 32;
        const float* ap = ea + (size_t)(e0 + lr)*64 + k0 + lc;
#pragma unroll
        for (int i = 0; i < 4; i++) cp16(aD[buf] + i*16, ap + i*4);
        const float* bp = We + (size_t)(k0 + kb)*128 + cb;
#pragma unroll
        for (int i = 0; i < 4; i++) cp16(bD[buf] + i*16, bp + i*4);
        cp_commit();
    };

    float acc[2][8][4] = {};
    issue(0, 0);
#pragma unroll
    for (int c = 0; c < 2; c++) {
        int cur = c & 1;
        if (c == 0) { issue(1, 1); cp_wait<1>(); }
        else cp_wait<0>();
        __syncthreads();
        uint32_t (*Ac)[ALD] = cur ? Ab1 : Ab0;
        uint32_t (*Bc)[BLD] = cur ? Bb1 : Bb0;
#pragma unroll
        for (int kq = 0; kq < 4; kq++) {
            const int kc = kq * 8;
            uint32_t b0[8], b1[8];
#pragma unroll
            for (int nt = 0; nt < 8; nt++) {
                int colB = Nb + nt*8 + lg;
                b0[nt] = Bc[kc + lt][colB];
                b1[nt] = Bc[kc + 4 + lt][colB];
            }
#pragma unroll
            for (int mt = 0; mt < 2; mt++) {
                int rb = Mb + mt*16;
                uint32_t a0 = Ac[rb + lg    ][kc + lt];
                uint32_t a1 = Ac[rb + 8 + lg][kc + lt];
                uint32_t a2 = Ac[rb + lg    ][kc + 4 + lt];
                uint32_t a3 = Ac[rb + 8 + lg][kc + 4 + lt];
#pragma unroll
                for (int nt = 0; nt < 8; nt++)
                    mma_tf32(acc[mt][nt], a0, a1, a2, a3, b0[nt], b1[nt]);
            }
        }
        __syncthreads();
    }

    // write e-tile to smem overlay
#pragma unroll
    for (int mt = 0; mt < 2; mt++) {
        int r0 = Mb + mt*16 + lg;
#pragma unroll
        for (int nt = 0; nt < 8; nt++) {
            int c0 = Nb + nt*8 + 2*lt;
            *(float2*)&et[r0][c0]     = make_float2(acc[mt][nt][0], acc[mt][nt][1]);
            *(float2*)&et[r0 + 8][c0] = make_float2(acc[mt][nt][2], acc[mt][nt][3]);
        }
    }
    __syncthreads();

    // attention: warp-per-edge, 16 edges per warp
    const int c4 = lane * 4;
#pragma unroll 4
    for (int it = 0; it < 16; it++) {
        int el = warp * 16 + it;
        int s = sidx[el], d = didx[el];
        float4 q  = *(const float4*)(g_qkvs + (size_t)d*512 + c4);
        float4 k  = *(const float4*)(g_qkvs + (size_t)s*512 + 128 + c4);
        float4 v  = *(const float4*)(g_qkvs + (size_t)s*512 + 256 + c4);
        float4 ev = *(const float4*)&et[el][c4];
        float part = q.x*(k.x+ev.x) + q.y*(k.y+ev.y) + q.z*(k.z+ev.z) + q.w*(k.w+ev.w);
        part += __shfl_xor_sync(0xffffffffu, part, 1);
        part += __shfl_xor_sync(0xffffffffu, part, 2);
        float pe = expf(part * 0.25f);
        float m0 = pe*(v.x+ev.x), m1 = pe*(v.y+ev.y);
        float m2 = pe*(v.z+ev.z), m3 = pe*(v.w+ev.w);
        float* o = g_agg + (size_t)d*128 + c4;
        asm volatile("red.global.add.v4.f32 [%0], {%1,%2,%3,%4};"
                     :: "l"(o), "f"(m0), "f"(m1), "f"(m2), "f"(m3) : "memory");
        if ((lane & 3) == 0) {
            float* dn = g_denom + (size_t)d*NH + (lane >> 2);
            asm volatile("red.global.add.f32 [%0], %1;" :: "l"(dn), "f"(pe) : "memory");
        }
    }
}

// ---------------- edge update: gather-GEMM (cp.async dbl-buf) + fused gate+LN ----------------
__global__ void __launch_bounds__(256, 2)
k_edge_mma(const int* __restrict__ src, const int* __restrict__ dst,
           const float* __restrict__ ea,
           const float* __restrict__ W, const float* __restrict__ bvec,
           const float* __restrict__ eg, const float* __restrict__ ebias,
           float* __restrict__ out) {
    extern __shared__ uint32_t smu[];
    uint32_t (*Ab0)[ALD] = (uint32_t(*)[ALD])smu;
    uint32_t (*Ab1)[ALD] = (uint32_t(*)[ALD])(smu + AOFF);
    uint32_t (*Bb0)[BLD] = (uint32_t(*)[BLD])(smu + 2*AOFF);
    uint32_t (*Bb1)[BLD] = (uint32_t(*)[BLD])(smu + 2*AOFF + BOFF);
    float    (*raw)[132] = (float(*)[132])smu;     // overlay after mainloop
    __shared__ int sidx[128], didx[128];

    const int tid  = threadIdx.x;
    const int warp = tid >> 5, lane = tid & 31;
    const int e0 = blockIdx.x * 128;
    if (tid < 128) { sidx[tid] = src[e0+tid]; didx[tid] = dst[e0+tid]; }
    __syncthreads();

    const int wm = warp >> 1, wn = warp & 1;
    const int Mb = wm * 32, Nb = wn * 64;
    const int lg = lane >> 2, lt = lane & 3;
    const int lr = tid >> 1, lc = (tid & 1) * 16;
    const int kb = tid >> 3, cb = (tid & 7) * 16;

    const uint32_t aD[2] = { (uint32_t)__cvta_generic_to_shared(&Ab0[lr][lc]),
                             (uint32_t)__cvta_generic_to_shared(&Ab1[lr][lc]) };
    const uint32_t bD[2] = { (uint32_t)__cvta_generic_to_shared(&Bb0[kb][cb]),
                             (uint32_t)__cvta_generic_to_shared(&Bb1[kb][cb]) };

    auto issue = [&](int c, int buf) {
        int k0 = c * 32;
        const float* base; int col;
        if (k0 < 128)      { base = g_xn + (size_t)sidx[lr]*128; col = k0 + lc; }
        else if (k0 < 256) { base = g_xn + (size_t)didx[lr]*128; col = k0 - 128 + lc; }
        else               { base = ea + (size_t)(e0+lr)*64;     col = k0 - 256 + lc; }
#pragma unroll
        for (int i = 0; i < 4; i++) cp16(aD[buf] + i*16, base + col + i*4);
        const float* bp = W + (size_t)(k0 + kb)*128 + cb;
#pragma unroll
        for (int i = 0; i < 4; i++) cp16(bD[buf] + i*16, bp + i*4);
        cp_commit();
    };

    float acc[2][8][4] = {};
    issue(0, 0);
    for (int c = 0; c < 10; c++) {
        int cur = c & 1;
        if (c < 9) { issue(c+1, cur ^ 1); cp_wait<1>(); }
        else cp_wait<0>();
        __syncthreads();
        uint32_t (*Ac)[ALD] = cur ? Ab1 : Ab0;
        uint32_t (*Bc)[BLD] = cur ? Bb1 : Bb0;
#pragma unroll
        for (int kq = 0; kq < 4; kq++) {
            const int kc = kq * 8;
            uint32_t b0[8], b1[8];
#pragma unroll
            for (int nt = 0; nt < 8; nt++) {
                int colB = Nb + nt*8 + lg;
                b0[nt] = Bc[kc + lt][colB];
                b1[nt] = Bc[kc + 4 + lt][colB];
            }
#pragma unroll
            for (int mt = 0; mt < 2; mt++) {
                int rb = Mb + mt*16;
                uint32_t a0 = Ac[rb + lg    ][kc + lt];
                uint32_t a1 = Ac[rb + 8 + lg][kc + lt];
                uint32_t a2 = Ac[rb + lg    ][kc + 4 + lt];
                uint32_t a3 = Ac[rb + 8 + lg][kc + 4 + lt];
#pragma unroll
                for (int nt = 0; nt < 8; nt++)
                    mma_tf32(acc[mt][nt], a0, a1, a2, a3, b0[nt], b1[nt]);
            }
        }
        __syncthreads();
    }

    // bias + relu -> raw smem (overlays tile buffers)
#pragma unroll
    for (int mt = 0; mt < 2; mt++) {
        int r0 = Mb + mt*16 + lg;
#pragma unroll
        for (int nt = 0; nt < 8; nt++) {
            int c0 = Nb + nt*8 + 2*lt;
            float2 bb = *(const float2*)(bvec + c0);
            *(float2*)&raw[r0][c0] =
                make_float2(fmaxf(acc[mt][nt][0] + bb.x, 0.0f),
                            fmaxf(acc[mt][nt][1] + bb.y, 0.0f));
            *(float2*)&raw[r0 + 8][c0] =
                make_float2(fmaxf(acc[mt][nt][2] + bb.x, 0.0f),
                            fmaxf(acc[mt][nt][3] + bb.y, 0.0f));
        }
    }
    __syncthreads();

    // t = edge_attr + sigmoid(gate)*delta; LN over 64
#pragma unroll
    for (int half = 0; half < 2; half++) {
        int r = (tid >> 2) + half * 64;
        int q = tid & 3;
        float t[16]; float s = 0.0f;
#pragma unroll
        for (int i4 = 0; i4 < 16; i4 += 4) {
            int cc = q*16 + i4;
            float4 e4 = *(const float4*)(ea + (size_t)(e0+r)*64 + cc);
            t[i4+0] = e4.x + raw[r][cc+0] / (1.0f + expf(-raw[r][64+cc+0]));
            t[i4+1] = e4.y + raw[r][cc+1] / (1.0f + expf(-raw[r][64+cc+1]));
            t[i4+2] = e4.z + raw[r][cc+2] / (1.0f + expf(-raw[r][64+cc+2]));
            t[i4+3] = e4.w + raw[r][cc+3] / (1.0f + expf(-raw[r][64+cc+3]));
            s += t[i4+0] + t[i4+1] + t[i4+2] + t[i4+3];
        }
        s += __shfl_xor_sync(0xffffffffu, s, 1);
        s += __shfl_xor_sync(0xffffffffu, s, 2);
        float m = s * (1.0f/64.0f);
        float vs = 0.0f;
#pragma unroll
        for (int i = 0; i < 16; i++) { float dd = t[i] - m; vs += dd*dd; }
        vs += __shfl_xor_sync(0xffffffffu, vs, 1);
        vs += __shfl_xor_sync(0xffffffffu, vs, 2);
        float inv = rsqrtf(vs * (1.0f/64.0f) + 1e-5f);
#pragma unroll
        for (int i4 = 0; i4 < 16; i4 += 4) {
            int cc = q*16 + i4;
            float4 gv = *(const float4*)(eg + cc);
            float4 bb = *(const float4*)(ebias + cc);
            *(float4*)(out + (size_t)(e0+r)*64 + cc) =
                make_float4((t[i4+0]-m)*inv*gv.x+bb.x, (t[i4+1]-m)*inv*gv.y+bb.y,
                            (t[i4+2]-m)*inv*gv.z+bb.z, (t[i4+3]-m)*inv*gv.w+bb.w);
        }
    }
}

// ---------------- launcher ----------------
extern "C" void kernel_launch(void* const* d_in, const int* in_sizes, int n_in,
                              void* d_out, int out_size) {
    const float* x     = (const float*)d_in[0];
    const int*   ei    = (const int*)  d_in[1];
    const float* ea    = (const float*)d_in[2];
    const float* demb  = (const float*)d_in[3];
    const float* ng    = (const float*)d_in[4];
    const float* nbv   = (const float*)d_in[5];
    const float* Wq    = (const float*)d_in[6];
    const float* bq    = (const float*)d_in[7];
    const float* Wk    = (const float*)d_in[8];
    const float* bk    = (const float*)d_in[9];
    const float* Wv    = (const float*)d_in[10];
    const float* bv    = (const float*)d_in[11];
    const float* We    = (const float*)d_in[12];
    const float* Wskip = (const float*)d_in[13];
    const float* bskip = (const float*)d_in[14];
    const float* W1    = (const float*)d_in[15];
    const float* b1    = (const float*)d_in[16];
    const float* W2    = (const float*)d_in[17];
    const float* b2    = (const float*)d_in[18];
    const float* eung  = (const float*)d_in[19];
    const float* eunb  = (const float*)d_in[20];
    const float* euW   = (const float*)d_in[21];
    const float* eub   = (const float*)d_in[22];
    const float* eueg  = (const float*)d_in[23];
    const float* eueb  = (const float*)d_in[24];
    float* out = (float*)d_out;

    const int* src = ei;
    const int* dst = ei + EE;

    static float *p_h = nullptr, *p_qkvs = nullptr,
                 *p_h2 = nullptr, *p_ffn1 = nullptr, *p_xattn = nullptr,
                 *p_W4 = nullptr, *p_b4 = nullptr;
    static bool inited = false;
    if (!inited) {
        cudaGetSymbolAddress((void**)&p_h,     g_h);
        cudaGetSymbolAddress((void**)&p_qkvs,  g_qkvs);
        cudaGetSymbolAddress((void**)&p_h2,    g_h2);
        cudaGetSymbolAddress((void**)&p_ffn1,  g_ffn1);
        cudaGetSymbolAddress((void**)&p_xattn, g_xattn);
        cudaGetSymbolAddress((void**)&p_W4,    g_W4);
        cudaGetSymbolAddress((void**)&p_b4,    g_b4);
        cudaFuncSetAttribute(k_gemm_mma<0>, cudaFuncAttributeMaxDynamicSharedMemorySize, MMA_SMEM);
        cudaFuncSetAttribute(k_gemm_mma<1>, cudaFuncAttributeMaxDynamicSharedMemorySize, MMA_SMEM);
        cudaFuncSetAttribute(k_gemm_mma<2>, cudaFuncAttributeMaxDynamicSharedMemorySize, MMA_SMEM);
        cudaFuncSetAttribute(k_eattn,       cudaFuncAttributeMaxDynamicSharedMemorySize, MMA_SMEM);
        cudaFuncSetAttribute(k_edge_mma,    cudaFuncAttributeMaxDynamicSharedMemorySize, MMA_SMEM);
        inited = true;
    }

    const int MB = (NN + 127) / 128;   // 391

    k_init<<<2048, 256>>>();
    k_deg<<<(EE + 255)/256, 256>>>(src);
    k_pack<<<64, 256>>>(Wq, Wk, Wv, Wskip, bq, bk, bv, bskip);
    k_node_prep<<<(NN + 7)/8, 256>>>(x, demb, ng, nbv);

    // fused QKV+skip: [50000x128] @ [128x512]  (tf32 mma)
    k_gemm_mma<0><<<dim3(4, MB), 256, MMA_SMEM>>>(p_h, 128, p_W4, 512, p_b4, p_qkvs, 512,
                                                  nullptr, 0, NN, 128);

    // fused edge-proj + attention (single pass; unnormalized agg + denom)
    k_eattn<<<EE/128, 256, MMA_SMEM>>>(src, dst, ea, We);

    k_node_post<<<(NN + 7)/8, 256>>>(ng, nbv);

    // FFN (tf32 mma)
    k_gemm_mma<1><<<dim3(4, MB), 256, MMA_SMEM>>>(p_h2, 128, W1, 512, b1, p_ffn1, 512,
                                                  nullptr, 0, NN, 128);
    k_gemm_mma<2><<<dim3(1, MB), 256, MMA_SMEM>>>(p_ffn1, 512, W2, 128, b2, out, 128,
                                                  p_xattn, 128, NN, 512);

    k_xn<<<(NN + 7)/8, 256>>>(out, eung, eunb);
    k_edge_mma<<<EE/128, 256, MMA_SMEM>>>(src, dst, ea, euW, eub, eueg, eueb,
                                          out + (size_t)NN*DIM);
}

// round 11
// speedup vs baseline: 2.6227x; 1.0656x over previous
#include <cuda_runtime.h>
#include <math.h>
#include <stdint.h>

// ---------------- problem constants ----------------
constexpr int NN   = 50000;
constexpr int EE   = 800000;
constexpr int DIM  = 128;
constexpr int NH   = 8;
constexpr int HID  = 512;

// ---------------- scratch ----------------
__device__ float g_xin  [(size_t)NN*DIM];
__device__ float g_h    [(size_t)NN*DIM];
__device__ float g_qkvs [(size_t)NN*4*DIM];   // q[0:128) k[128:256) v[256:384) skip[384:512)
__device__ float g_denom[(size_t)NN*NH];
__device__ float g_agg  [(size_t)NN*DIM];     // UNNORMALIZED sum of pe*(v+e)
__device__ float g_xattn[(size_t)NN*DIM];
__device__ float g_h2   [(size_t)NN*DIM];
__device__ float g_ffn1 [(size_t)NN*HID];
__device__ float g_xn   [(size_t)NN*DIM];
__device__ float g_W4   [(size_t)DIM*512];
__device__ float g_b4   [512];
__device__ int   g_deg  [NN];

// ---------------- helpers ----------------
__device__ __forceinline__ float warp_sum(float v) {
#pragma unroll
    for (int o = 16; o > 0; o >>= 1) v += __shfl_xor_sync(0xffffffffu, v, o);
    return v;
}
__device__ __forceinline__ void mma_tf32(float* c,
                                         uint32_t a0, uint32_t a1, uint32_t a2, uint32_t a3,
                                         uint32_t b0, uint32_t b1) {
    asm volatile("mma.sync.aligned.m16n8k8.row.col.f32.tf32.tf32.f32 "
                 "{%0,%1,%2,%3}, {%4,%5,%6,%7}, {%8,%9}, {%0,%1,%2,%3};"
                 : "+f"(c[0]), "+f"(c[1]), "+f"(c[2]), "+f"(c[3])
                 : "r"(a0), "r"(a1), "r"(a2), "r"(a3), "r"(b0), "r"(b1));
}
__device__ __forceinline__ float gelu_erf(float v) {
    return 0.5f * v * (1.0f + erff(v * 0.70710678118654752f));
}
__device__ __forceinline__ void cp16(uint32_t d, const float* g) {
    asm volatile("cp.async.cg.shared.global [%0], [%1], 16;" :: "r"(d), "l"(g) : "memory");
}
__device__ __forceinline__ void cp_commit() {
    asm volatile("cp.async.commit_group;" ::: "memory");
}
template<int N> __device__ __forceinline__ void cp_wait() {
    asm volatile("cp.async.wait_group %0;" :: "n"(N) : "memory");
}

// smem tile geometry (shared by all mma kernels)
constexpr int ALD = 36;    // A smem ld (mod 32 = 4 -> conflict-free frag reads)
constexpr int BLD = 136;   // B smem ld (mod 32 = 8)
constexpr int AOFF = 128*ALD;
constexpr int BOFF = 32*BLD;
constexpr int TILE_SMEM_U32 = 2*AOFF + 2*BOFF;   // 17920 u32 = 71680 B
constexpr int MMA_SMEM = TILE_SMEM_U32 * 4;

// ---------------- init / degree ----------------
__global__ void k_init() {
    int i  = blockIdx.x * blockDim.x + threadIdx.x;
    int st = gridDim.x * blockDim.x;
    for (int j = i; j < NN*DIM; j += st) g_agg[j] = 0.0f;
    for (int j = i; j < NN*NH;  j += st) g_denom[j] = 0.0f;
    for (int j = i; j < NN;     j += st) g_deg[j] = 0;
}
__global__ void k_deg(const int* __restrict__ src) {
    int i = blockIdx.x * blockDim.x + threadIdx.x;
    if (i < EE) atomicAdd(&g_deg[src[i]], 1);
}
__global__ void k_pack(const float* __restrict__ Wq, const float* __restrict__ Wk,
                       const float* __restrict__ Wv, const float* __restrict__ Ws,
                       const float* __restrict__ bq, const float* __restrict__ bk,
                       const float* __restrict__ bv, const float* __restrict__ bs) {
    int i = blockIdx.x * blockDim.x + threadIdx.x;
    if (i < DIM*DIM) {
        int r = i >> 7, c = i & 127;
        g_W4[(size_t)r*512 +       c] = Wq[i];
        g_W4[(size_t)r*512 + 128 + c] = Wk[i];
        g_W4[(size_t)r*512 + 256 + c] = Wv[i];
        g_W4[(size_t)r*512 + 384 + c] = Ws[i];
    }
    if (i < 128) {
        g_b4[i] = bq[i]; g_b4[128+i] = bk[i]; g_b4[256+i] = bv[i]; g_b4[384+i] = bs[i];
    }
}

// ---------------- fused LN kernels ----------------
__global__ void k_node_prep(const float* __restrict__ x, const float* __restrict__ demb,
                            const float* __restrict__ g, const float* __restrict__ b) {
    int row = blockIdx.x * 8 + (threadIdx.x >> 5);
    if (row >= NN) return;
    int lane = threadIdx.x & 31;
    int d = g_deg[row]; if (d > 255) d = 255;
    float4 xv = *(const float4*)(x + (size_t)row*DIM + lane*4);
    float4 dv = *(const float4*)(demb + (size_t)d*DIM + lane*4);
    float4 xi = make_float4(xv.x+dv.x, xv.y+dv.y, xv.z+dv.z, xv.w+dv.w);
    *(float4*)(g_xin + (size_t)row*DIM + lane*4) = xi;
    float m = warp_sum(xi.x+xi.y+xi.z+xi.w) * (1.0f/128.0f);
    float4 dd = make_float4(xi.x-m, xi.y-m, xi.z-m, xi.w-m);
    float var = warp_sum(dd.x*dd.x+dd.y*dd.y+dd.z*dd.z+dd.w*dd.w) * (1.0f/128.0f);
    float inv = rsqrtf(var + 1e-5f);
    float4 gv = *(const float4*)(g + lane*4);
    float4 bv = *(const float4*)(b + lane*4);
    *(float4*)(g_h + (size_t)row*DIM + lane*4) =
        make_float4(dd.x*inv*gv.x+bv.x, dd.y*inv*gv.y+bv.y, dd.z*inv*gv.z+bv.z, dd.w*inv*gv.w+bv.w);
}

// x_attn = x_in + agg/denom + skip; h2 = LN(x_attn)
__global__ void k_node_post(const float* __restrict__ g, const float* __restrict__ b) {
    int row = blockIdx.x * 8 + (threadIdx.x >> 5);
    if (row >= NN) return;
    int lane = threadIdx.x & 31;
    float dn = g_denom[(size_t)row*NH + (lane >> 2)];
    float rd = (dn != 0.0f) ? (1.0f / dn) : 0.0f;
    float4 xi = *(const float4*)(g_xin + (size_t)row*DIM + lane*4);
    float4 ag = *(const float4*)(g_agg + (size_t)row*DIM + lane*4);
    float4 sk = *(const float4*)(g_qkvs + (size_t)row*512 + 384 + lane*4);
    float4 xa = make_float4(xi.x+ag.x*rd+sk.x, xi.y+ag.y*rd+sk.y,
                            xi.z+ag.z*rd+sk.z, xi.w+ag.w*rd+sk.w);
    *(float4*)(g_xattn + (size_t)row*DIM + lane*4) = xa;
    float m = warp_sum(xa.x+xa.y+xa.z+xa.w) * (1.0f/128.0f);
    float4 dd = make_float4(xa.x-m, xa.y-m, xa.z-m, xa.w-m);
    float var = warp_sum(dd.x*dd.x+dd.y*dd.y+dd.z*dd.z+dd.w*dd.w) * (1.0f/128.0f);
    float inv = rsqrtf(var + 1e-5f);
    float4 gv = *(const float4*)(g + lane*4);
    float4 bv = *(const float4*)(b + lane*4);
    *(float4*)(g_h2 + (size_t)row*DIM + lane*4) =
        make_float4(dd.x*inv*gv.x+bv.x, dd.y*inv*gv.y+bv.y, dd.z*inv*gv.z+bv.z, dd.w*inv*gv.w+bv.w);
}

// ---------------- generic tf32 mma GEMM: 128x128 tile, cp.async double-buffered ----------------
// MODE 0:+bias  1:+bias,GELU  2:+bias+res, then fused row-LN -> xn_out (also writes Co)
template<int MODE>
__global__ void __launch_bounds__(256, 2)
k_gemm_mma(const float* __restrict__ A, int lda,
           const float* __restrict__ B, int ldb,
           const float* __restrict__ bias,
           float* __restrict__ Co, int ldc,
           const float* __restrict__ res, int ldr,
           int M, int K,
           const float* __restrict__ lng, const float* __restrict__ lnb,
           float* __restrict__ xn_out) {
    extern __shared__ uint32_t smu[];
    uint32_t (*Ab0)[ALD] = (uint32_t(*)[ALD])smu;
    uint32_t (*Ab1)[ALD] = (uint32_t(*)[ALD])(smu + AOFF);
    uint32_t (*Bb0)[BLD] = (uint32_t(*)[BLD])(smu + 2*AOFF);
    uint32_t (*Bb1)[BLD] = (uint32_t(*)[BLD])(smu + 2*AOFF + BOFF);
    float    (*st)[132]  = (float(*)[132])smu;     // MODE 2 staging overlay

    const int m0 = blockIdx.y * 128, n0 = blockIdx.x * 128;
    const int tid = threadIdx.x;
    const int warp = tid >> 5, lane = tid & 31;
    const int wm = warp >> 1, wn = warp & 1;
    const int Mb = wm * 32, Nb = wn * 64;
    const int lg = lane >> 2, lt = lane & 3;
    const int lr = tid >> 1, lc = (tid & 1) * 16;
    const int kb = tid >> 3, cb = (tid & 7) * 16;

    const uint32_t aD[2] = { (uint32_t)__cvta_generic_to_shared(&Ab0[lr][lc]),
                             (uint32_t)__cvta_generic_to_shared(&Ab1[lr][lc]) };
    const uint32_t bD[2] = { (uint32_t)__cvta_generic_to_shared(&Bb0[kb][cb]),
                             (uint32_t)__cvta_generic_to_shared(&Bb1[kb][cb]) };
    const bool aIn = (m0 + lr) < M;

    auto issue = [&](int c, int buf) {
        int k0 = c * 32;
        if (aIn) {
            const float* ap = A + (size_t)(m0 + lr)*lda + k0 + lc;
#pragma unroll
            for (int i = 0; i < 4; i++) cp16(aD[buf] + i*16, ap + i*4);
        } else {
            uint32_t (*Ax)[ALD] = buf ? Ab1 : Ab0;
#pragma unroll
            for (int i = 0; i < 4; i++)
                *(float4*)&Ax[lr][lc + i*4] = make_float4(0,0,0,0);
        }
        const float* bp = B + (size_t)(k0 + kb)*ldb + n0 + cb;
#pragma unroll
        for (int i = 0; i < 4; i++) cp16(bD[buf] + i*16, bp + i*4);
        cp_commit();
    };

    float acc[2][8][4] = {};
    const int NC = K >> 5;
    issue(0, 0);
    for (int c = 0; c < NC; c++) {
        int cur = c & 1;
        if (c + 1 < NC) { issue(c+1, cur ^ 1); cp_wait<1>(); }
        else cp_wait<0>();
        __syncthreads();
        uint32_t (*Ac)[ALD] = cur ? Ab1 : Ab0;
        uint32_t (*Bc)[BLD] = cur ? Bb1 : Bb0;
#pragma unroll
        for (int kq = 0; kq < 4; kq++) {
            const int kc = kq * 8;
            uint32_t b0[8], b1[8];
#pragma unroll
            for (int nt = 0; nt < 8; nt++) {
                int colB = Nb + nt*8 + lg;
                b0[nt] = Bc[kc + lt][colB];
                b1[nt] = Bc[kc + 4 + lt][colB];
            }
#pragma unroll
            for (int mt = 0; mt < 2; mt++) {
                int rb = Mb + mt*16;
                uint32_t a0 = Ac[rb + lg    ][kc + lt];
                uint32_t a1 = Ac[rb + 8 + lg][kc + lt];
                uint32_t a2 = Ac[rb + lg    ][kc + 4 + lt];
                uint32_t a3 = Ac[rb + 8 + lg][kc + 4 + lt];
#pragma unroll
                for (int nt = 0; nt < 8; nt++)
                    mma_tf32(acc[mt][nt], a0, a1, a2, a3, b0[nt], b1[nt]);
            }
        }
        __syncthreads();
    }

    if (MODE != 2) {
        // direct fragment epilogue -> global
#pragma unroll
        for (int mt = 0; mt < 2; mt++) {
            int r0 = m0 + Mb + mt*16 + lg;
#pragma unroll
            for (int nt = 0; nt < 8; nt++) {
                int cg = n0 + Nb + nt*8 + 2*lt;
                float2 bb = *(const float2*)(bias + cg);
#pragma unroll
                for (int hrow = 0; hrow < 2; hrow++) {
                    int m = r0 + hrow*8;
                    if (m >= M) continue;
                    float cx = acc[mt][nt][hrow*2 + 0] + bb.x;
                    float cy = acc[mt][nt][hrow*2 + 1] + bb.y;
                    if (MODE == 1) { cx = gelu_erf(cx); cy = gelu_erf(cy); }
                    *(float2*)(Co + (size_t)m*ldc + cg) = make_float2(cx, cy);
                }
            }
        }
    } else {
        // MODE 2: bias + residual -> stage to smem, then per-row LN -> Co (x_new) and xn_out
#pragma unroll
        for (int mt = 0; mt < 2; mt++) {
            int rloc = Mb + mt*16 + lg;
#pragma unroll
            for (int nt = 0; nt < 8; nt++) {
                int cl = Nb + nt*8 + 2*lt;
                int cg = n0 + cl;
                float2 bb = *(const float2*)(bias + cg);
#pragma unroll
                for (int hrow = 0; hrow < 2; hrow++) {
                    int r = rloc + hrow*8;
                    int m = m0 + r;
                    float cx = acc[mt][nt][hrow*2 + 0] + bb.x;
                    float cy = acc[mt][nt][hrow*2 + 1] + bb.y;
                    if (m < M) {
                        float2 rr = *(const float2*)(res + (size_t)m*ldr + cg);
                        cx += rr.x; cy += rr.y;
                    }
                    *(float2*)&st[r][cl] = make_float2(cx, cy);
                }
            }
        }
        __syncthreads();
        // per-warp row LN: warp w handles rows w*16 .. w*16+15
#pragma unroll
        for (int rr = 0; rr < 16; rr++) {
            int r = warp * 16 + rr;
            int m = m0 + r;
            if (m >= M) continue;
            float4 xv = *(const float4*)&st[r][lane*4];
            float mn = warp_sum(xv.x+xv.y+xv.z+xv.w) * (1.0f/128.0f);
            float4 dd = make_float4(xv.x-mn, xv.y-mn, xv.z-mn, xv.w-mn);
            float var = warp_sum(dd.x*dd.x+dd.y*dd.y+dd.z*dd.z+dd.w*dd.w) * (1.0f/128.0f);
            float inv = rsqrtf(var + 1e-5f);
            float4 gv = *(const float4*)(lng + lane*4);
            float4 bv = *(const float4*)(lnb + lane*4);
            *(float4*)(Co + (size_t)m*ldc + lane*4) = xv;
            *(float4*)(xn_out + (size_t)m*DIM + lane*4) =
                make_float4(dd.x*inv*gv.x+bv.x, dd.y*inv*gv.y+bv.y,
                            dd.z*inv*gv.z+bv.z, dd.w*inv*gv.w+bv.w);
        }
    }
}

// ---------------- fused edge-proj + attention (cp.async double-buffered) ----------------
__global__ void __launch_bounds__(256, 2)
k_eattn(const int* __restrict__ src, const int* __restrict__ dst,
        const float* __restrict__ ea, const float* __restrict__ We) {
    extern __shared__ uint32_t smu[];
    uint32_t (*Ab0)[ALD] = (uint32_t(*)[ALD])smu;
    uint32_t (*Ab1)[ALD] = (uint32_t(*)[ALD])(smu + AOFF);
    uint32_t (*Bb0)[BLD] = (uint32_t(*)[BLD])(smu + 2*AOFF);
    uint32_t (*Bb1)[BLD] = (uint32_t(*)[BLD])(smu + 2*AOFF + BOFF);
    float    (*et)[132]  = (float(*)[132])smu;     // overlay after mainloop
    __shared__ int sidx[128], didx[128];

    const int tid  = threadIdx.x;
    const int warp = tid >> 5, lane = tid & 31;
    const int e0 = blockIdx.x * 128;
    if (tid < 128) { sidx[tid] = src[e0+tid]; didx[tid] = dst[e0+tid]; }
    __syncthreads();

    const int wm = warp >> 1, wn = warp & 1;
    const int Mb = wm * 32, Nb = wn * 64;
    const int lg = lane >> 2, lt = lane & 3;
    const int lr = tid >> 1, lc = (tid & 1) * 16;
    const int kb = tid >> 3, cb = (tid & 7) * 16;

    const uint32_t aD[2] = { (uint32_t)__cvta_generic_to_shared(&Ab0[lr][lc]),
                             (uint32_t)__cvta_generic_to_shared(&Ab1[lr][lc]) };
    const uint32_t bD[2] = { (uint32_t)__cvta_generic_to_shared(&Bb0[kb][cb]),
                             (uint32_t)__cvta_generic_to_shared(&Bb1[kb][cb]) };

    auto issue = [&](int c, int buf) {
        int k0 = c * 32;
        const float* ap = ea + (size_t)(e0 + lr)*64 + k0 + lc;
#pragma unroll
        for (int i = 0; i < 4; i++) cp16(aD[buf] + i*16, ap + i*4);
        const float* bp = We + (size_t)(k0 + kb)*128 + cb;
#pragma unroll
        for (int i = 0; i < 4; i++) cp16(bD[buf] + i*16, bp + i*4);
        cp_commit();
    };

    float acc[2][8][4] = {};
    issue(0, 0);
#pragma unroll
    for (int c = 0; c < 2; c++) {
        int cur = c & 1;
        if (c == 0) { issue(1, 1); cp_wait<1>(); }
        else cp_wait<0>();
        __syncthreads();
        uint32_t (*Ac)[ALD] = cur ? Ab1 : Ab0;
        uint32_t (*Bc)[BLD] = cur ? Bb1 : Bb0;
#pragma unroll
        for (int kq = 0; kq < 4; kq++) {
            const int kc = kq * 8;
            uint32_t b0[8], b1[8];
#pragma unroll
            for (int nt = 0; nt < 8; nt++) {
                int colB = Nb + nt*8 + lg;
                b0[nt] = Bc[kc + lt][colB];
                b1[nt] = Bc[kc + 4 + lt][colB];
            }
#pragma unroll
            for (int mt = 0; mt < 2; mt++) {
                int rb = Mb + mt*16;
                uint32_t a0 = Ac[rb + lg    ][kc + lt];
                uint32_t a1 = Ac[rb + 8 + lg][kc + lt];
                uint32_t a2 = Ac[rb + lg    ][kc + 4 + lt];
                uint32_t a3 = Ac[rb + 8 + lg][kc + 4 + lt];
#pragma unroll
                for (int nt = 0; nt < 8; nt++)
                    mma_tf32(acc[mt][nt], a0, a1, a2, a3, b0[nt], b1[nt]);
            }
        }
        __syncthreads();
    }

    // write e-tile to smem overlay
#pragma unroll
    for (int mt = 0; mt < 2; mt++) {
        int r0 = Mb + mt*16 + lg;
#pragma unroll
        for (int nt = 0; nt < 8; nt++) {
            int c0 = Nb + nt*8 + 2*lt;
            *(float2*)&et[r0][c0]     = make_float2(acc[mt][nt][0], acc[mt][nt][1]);
            *(float2*)&et[r0 + 8][c0] = make_float2(acc[mt][nt][2], acc[mt][nt][3]);
        }
    }
    __syncthreads();

    // attention: warp-per-edge, batched 4 edges per group for load MLP
    // (loads for all 4 edges issue before any red op's memory clobber)
    const int c4 = lane * 4;
#pragma unroll
    for (int grp = 0; grp < 4; grp++) {
        int base = warp * 16 + grp * 4;
        float4 q[4], k[4], v[4], ev[4];
        int dd[4];
        float pe[4];
#pragma unroll
        for (int j = 0; j < 4; j++) {
            int el = base + j;
            int s = sidx[el]; dd[j] = didx[el];
            q[j]  = *(const float4*)(g_qkvs + (size_t)dd[j]*512 + c4);
            k[j]  = *(const float4*)(g_qkvs + (size_t)s*512 + 128 + c4);
            v[j]  = *(const float4*)(g_qkvs + (size_t)s*512 + 256 + c4);
            ev[j] = *(const float4*)&et[el][c4];
        }
#pragma unroll
        for (int j = 0; j < 4; j++) {
            float part = q[j].x*(k[j].x+ev[j].x) + q[j].y*(k[j].y+ev[j].y)
                       + q[j].z*(k[j].z+ev[j].z) + q[j].w*(k[j].w+ev[j].w);
            part += __shfl_xor_sync(0xffffffffu, part, 1);
            part += __shfl_xor_sync(0xffffffffu, part, 2);
            pe[j] = expf(part * 0.25f);
        }
#pragma unroll
        for (int j = 0; j < 4; j++) {
            float m0 = pe[j]*(v[j].x+ev[j].x), m1 = pe[j]*(v[j].y+ev[j].y);
            float m2 = pe[j]*(v[j].z+ev[j].z), m3 = pe[j]*(v[j].w+ev[j].w);
            float* o = g_agg + (size_t)dd[j]*128 + c4;
            asm volatile("red.global.add.v4.f32 [%0], {%1,%2,%3,%4};"
                         :: "l"(o), "f"(m0), "f"(m1), "f"(m2), "f"(m3) : "memory");
            if ((lane & 3) == 0) {
                float* dn = g_denom + (size_t)dd[j]*NH + (lane >> 2);
                asm volatile("red.global.add.f32 [%0], %1;" :: "l"(dn), "f"(pe[j]) : "memory");
            }
        }
    }
}

// ---------------- edge update: gather-GEMM (cp.async dbl-buf) + fused gate+LN ----------------
__global__ void __launch_bounds__(256, 2)
k_edge_mma(const int* __restrict__ src, const int* __restrict__ dst,
           const float* __restrict__ ea,
           const float* __restrict__ W, const float* __restrict__ bvec,
           const float* __restrict__ eg, const float* __restrict__ ebias,
           float* __restrict__ out) {
    extern __shared__ uint32_t smu[];
    uint32_t (*Ab0)[ALD] = (uint32_t(*)[ALD])smu;
    uint32_t (*Ab1)[ALD] = (uint32_t(*)[ALD])(smu + AOFF);
    uint32_t (*Bb0)[BLD] = (uint32_t(*)[BLD])(smu + 2*AOFF);
    uint32_t (*Bb1)[BLD] = (uint32_t(*)[BLD])(smu + 2*AOFF + BOFF);
    float    (*raw)[132] = (float(*)[132])smu;
    __shared__ int sidx[128], didx[128];

    const int tid  = threadIdx.x;
    const int warp = tid >> 5, lane = tid & 31;
    const int e0 = blockIdx.x * 128;
    if (tid < 128) { sidx[tid] = src[e0+tid]; didx[tid] = dst[e0+tid]; }
    __syncthreads();

    const int wm = warp >> 1, wn = warp & 1;
    const int Mb = wm * 32, Nb = wn * 64;
    const int lg = lane >> 2, lt = lane & 3;
    const int lr = tid >> 1, lc = (tid & 1) * 16;
    const int kb = tid >> 3, cb = (tid & 7) * 16;

    const uint32_t aD[2] = { (uint32_t)__cvta_generic_to_shared(&Ab0[lr][lc]),
                             (uint32_t)__cvta_generic_to_shared(&Ab1[lr][lc]) };
    const uint32_t bD[2] = { (uint32_t)__cvta_generic_to_shared(&Bb0[kb][cb]),
                             (uint32_t)__cvta_generic_to_shared(&Bb1[kb][cb]) };

    auto issue = [&](int c, int buf) {
        int k0 = c * 32;
        const float* base; int col;
        if (k0 < 128)      { base = g_xn + (size_t)sidx[lr]*128; col = k0 + lc; }
        else if (k0 < 256) { base = g_xn + (size_t)didx[lr]*128; col = k0 - 128 + lc; }
        else               { base = ea + (size_t)(e0+lr)*64;     col = k0 - 256 + lc; }
#pragma unroll
        for (int i = 0; i < 4; i++) cp16(aD[buf] + i*16, base + col + i*4);
        const float* bp = W + (size_t)(k0 + kb)*128 + cb;
#pragma unroll
        for (int i = 0; i < 4; i++) cp16(bD[buf] + i*16, bp + i*4);
        cp_commit();
    };

    float acc[2][8][4] = {};
    issue(0, 0);
    for (int c = 0; c < 10; c++) {
        int cur = c & 1;
        if (c < 9) { issue(c+1, cur ^ 1); cp_wait<1>(); }
        else cp_wait<0>();
        __syncthreads();
        uint32_t (*Ac)[ALD] = cur ? Ab1 : Ab0;
        uint32_t (*Bc)[BLD] = cur ? Bb1 : Bb0;
#pragma unroll
        for (int kq = 0; kq < 4; kq++) {
            const int kc = kq * 8;
            uint32_t b0[8], b1[8];
#pragma unroll
            for (int nt = 0; nt < 8; nt++) {
                int colB = Nb + nt*8 + lg;
                b0[nt] = Bc[kc + lt][colB];
                b1[nt] = Bc[kc + 4 + lt][colB];
            }
#pragma unroll
            for (int mt = 0; mt < 2; mt++) {
                int rb = Mb + mt*16;
                uint32_t a0 = Ac[rb + lg    ][kc + lt];
                uint32_t a1 = Ac[rb + 8 + lg][kc + lt];
                uint32_t a2 = Ac[rb + lg    ][kc + 4 + lt];
                uint32_t a3 = Ac[rb + 8 + lg][kc + 4 + lt];
#pragma unroll
                for (int nt = 0; nt < 8; nt++)
                    mma_tf32(acc[mt][nt], a0, a1, a2, a3, b0[nt], b1[nt]);
            }
        }
        __syncthreads();
    }

    // bias + relu -> raw smem (overlays tile buffers)
#pragma unroll
    for (int mt = 0; mt < 2; mt++) {
        int r0 = Mb + mt*16 + lg;
#pragma unroll
        for (int nt = 0; nt < 8; nt++) {
            int c0 = Nb + nt*8 + 2*lt;
            float2 bb = *(const float2*)(bvec + c0);
            *(float2*)&raw[r0][c0] =
                make_float2(fmaxf(acc[mt][nt][0] + bb.x, 0.0f),
                            fmaxf(acc[mt][nt][1] + bb.y, 0.0f));
            *(float2*)&raw[r0 + 8][c0] =
                make_float2(fmaxf(acc[mt][nt][2] + bb.x, 0.0f),
                            fmaxf(acc[mt][nt][3] + bb.y, 0.0f));
        }
    }
    __syncthreads();

    // t = edge_attr + sigmoid(gate)*delta; LN over 64
#pragma unroll
    for (int half = 0; half < 2; half++) {
        int r = (tid >> 2) + half * 64;
        int q = tid & 3;
        float t[16]; float s = 0.0f;
#pragma unroll
        for (int i4 = 0; i4 < 16; i4 += 4) {
            int cc = q*16 + i4;
            float4 e4 = *(const float4*)(ea + (size_t)(e0+r)*64 + cc);
            t[i4+0] = e4.x + raw[r][cc+0] / (1.0f + expf(-raw[r][64+cc+0]));
            t[i4+1] = e4.y + raw[r][cc+1] / (1.0f + expf(-raw[r][64+cc+1]));
            t[i4+2] = e4.z + raw[r][cc+2] / (1.0f + expf(-raw[r][64+cc+2]));
            t[i4+3] = e4.w + raw[r][cc+3] / (1.0f + expf(-raw[r][64+cc+3]));
            s += t[i4+0] + t[i4+1] + t[i4+2] + t[i4+3];
        }
        s += __shfl_xor_sync(0xffffffffu, s, 1);
        s += __shfl_xor_sync(0xffffffffu, s, 2);
        float m = s * (1.0f/64.0f);
        float vs = 0.0f;
#pragma unroll
        for (int i = 0; i < 16; i++) { float dd = t[i] - m; vs += dd*dd; }
        vs += __shfl_xor_sync(0xffffffffu, vs, 1);
        vs += __shfl_xor_sync(0xffffffffu, vs, 2);
        float inv = rsqrtf(vs * (1.0f/64.0f) + 1e-5f);
#pragma unroll
        for (int i4 = 0; i4 < 16; i4 += 4) {
            int cc = q*16 + i4;
            float4 gv = *(const float4*)(eg + cc);
            float4 bb = *(const float4*)(ebias + cc);
            *(float4*)(out + (size_t)(e0+r)*64 + cc) =
                make_float4((t[i4+0]-m)*inv*gv.x+bb.x, (t[i4+1]-m)*inv*gv.y+bb.y,
                            (t[i4+2]-m)*inv*gv.z+bb.z, (t[i4+3]-m)*inv*gv.w+bb.w);
        }
    }
}

// ---------------- launcher ----------------
extern "C" void kernel_launch(void* const* d_in, const int* in_sizes, int n_in,
                              void* d_out, int out_size) {
    const float* x     = (const float*)d_in[0];
    const int*   ei    = (const int*)  d_in[1];
    const float* ea    = (const float*)d_in[2];
    const float* demb  = (const float*)d_in[3];
    const float* ng    = (const float*)d_in[4];
    const float* nbv   = (const float*)d_in[5];
    const float* Wq    = (const float*)d_in[6];
    const float* bq    = (const float*)d_in[7];
    const float* Wk    = (const float*)d_in[8];
    const float* bk    = (const float*)d_in[9];
    const float* Wv    = (const float*)d_in[10];
    const float* bv    = (const float*)d_in[11];
    const float* We    = (const float*)d_in[12];
    const float* Wskip = (const float*)d_in[13];
    const float* bskip = (const float*)d_in[14];
    const float* W1    = (const float*)d_in[15];
    const float* b1    = (const float*)d_in[16];
    const float* W2    = (const float*)d_in[17];
    const float* b2    = (const float*)d_in[18];
    const float* eung  = (const float*)d_in[19];
    const float* eunb  = (const float*)d_in[20];
    const float* euW   = (const float*)d_in[21];
    const float* eub   = (const float*)d_in[22];
    const float* eueg  = (const float*)d_in[23];
    const float* eueb  = (const float*)d_in[24];
    float* out = (float*)d_out;

    const int* src = ei;
    const int* dst = ei + EE;

    static float *p_h = nullptr, *p_qkvs = nullptr,
                 *p_h2 = nullptr, *p_ffn1 = nullptr, *p_xattn = nullptr,
                 *p_W4 = nullptr, *p_b4 = nullptr, *p_xn = nullptr;
    static bool inited = false;
    if (!inited) {
        cudaGetSymbolAddress((void**)&p_h,     g_h);
        cudaGetSymbolAddress((void**)&p_qkvs,  g_qkvs);
        cudaGetSymbolAddress((void**)&p_h2,    g_h2);
        cudaGetSymbolAddress((void**)&p_ffn1,  g_ffn1);
        cudaGetSymbolAddress((void**)&p_xattn, g_xattn);
        cudaGetSymbolAddress((void**)&p_W4,    g_W4);
        cudaGetSymbolAddress((void**)&p_b4,    g_b4);
        cudaGetSymbolAddress((void**)&p_xn,    g_xn);
        cudaFuncSetAttribute(k_gemm_mma<0>, cudaFuncAttributeMaxDynamicSharedMemorySize, MMA_SMEM);
        cudaFuncSetAttribute(k_gemm_mma<1>, cudaFuncAttributeMaxDynamicSharedMemorySize, MMA_SMEM);
        cudaFuncSetAttribute(k_gemm_mma<2>, cudaFuncAttributeMaxDynamicSharedMemorySize, MMA_SMEM);
        cudaFuncSetAttribute(k_eattn,       cudaFuncAttributeMaxDynamicSharedMemorySize, MMA_SMEM);
        cudaFuncSetAttribute(k_edge_mma,    cudaFuncAttributeMaxDynamicSharedMemorySize, MMA_SMEM);
        inited = true;
    }

    const int MB = (NN + 127) / 128;   // 391

    k_init<<<2048, 256>>>();
    k_deg<<<(EE + 255)/256, 256>>>(src);
    k_pack<<<64, 256>>>(Wq, Wk, Wv, Wskip, bq, bk, bv, bskip);
    k_node_prep<<<(NN + 7)/8, 256>>>(x, demb, ng, nbv);

    // fused QKV+skip: [50000x128] @ [128x512]  (tf32 mma)
    k_gemm_mma<0><<<dim3(4, MB), 256, MMA_SMEM>>>(p_h, 128, p_W4, 512, p_b4, p_qkvs, 512,
                                                  nullptr, 0, NN, 128, nullptr, nullptr, nullptr);

    // fused edge-proj + attention (single pass; unnormalized agg + denom)
    k_eattn<<<EE/128, 256, MMA_SMEM>>>(src, dst, ea, We);

    k_node_post<<<(NN + 7)/8, 256>>>(ng, nbv);

    // FFN (tf32 mma); FFN2 fuses the eu-LN producing g_xn
    k_gemm_mma<1><<<dim3(4, MB), 256, MMA_SMEM>>>(p_h2, 128, W1, 512, b1, p_ffn1, 512,
                                                  nullptr, 0, NN, 128, nullptr, nullptr, nullptr);
    k_gemm_mma<2><<<dim3(1, MB), 256, MMA_SMEM>>>(p_ffn1, 512, W2, 128, b2, out, 128,
                                                  p_xattn, 128, NN, 512, eung, eunb, p_xn);

    k_edge_mma<<<EE/128, 256, MMA_SMEM>>>(src, dst, ea, euW, eub, eueg, eueb,
                                          out + (size_t)NN*DIM);
}